// round 5
// baseline (speedup 1.0000x reference)
#include <cuda_runtime.h>
#include <cuda_fp16.h>
#include <math.h>
#include <stdint.h>

// ---------------- problem constants ----------------
#define BATCH   8
#define T       8192
#define IN_F    128
#define OUT_F   128
#define NSTATE  256
#define NC      64
#define CHUNK   128
#define MROWS   (BATCH * T)     // 65536
#define SCOLS   512             // 2*NSTATE interleaved: col 2n=re, 2n+1=im
#define KOUT    640             // 512 states + 128 x

// ---------------- scratch ----------------
__device__ __align__(256) __half g_x[(size_t)MROWS * IN_F];     // x fp16
__device__ __align__(256) __half g_Ssc[(size_t)MROWS * SCOLS];  // states fp16 interleaved
__device__ __align__(256) __half g_W1h[SCOLS * IN_F];
__device__ __align__(256) __half g_W1l[SCOLS * IN_F];
__device__ __align__(256) __half g_Woh[OUT_F * KOUT];
__device__ __align__(256) __half g_Wol[OUT_F * KOUT];
__device__ float2 g_carry[2048 * 64];   // per (m-tile, n-tile) 64 state carries
__device__ int    g_flag[2048];
__device__ float2 g_lam[NSTATE];
__device__ float2 g_lam16[NSTATE];
__device__ float2 g_lam128[NSTATE];

// ---------------- PTX helpers ----------------
__device__ __forceinline__ uint32_t smem_u32(const void* p) {
    uint32_t a;
    asm("{ .reg .u64 t; cvta.to.shared.u64 t, %1; cvt.u32.u64 %0, t; }" : "=r"(a) : "l"(p));
    return a;
}
__device__ __forceinline__ void cp16(uint32_t smem, const void* g) {
    asm volatile("cp.async.cg.shared.global [%0], [%1], 16;" :: "r"(smem), "l"(g));
}
#define CP_COMMIT() asm volatile("cp.async.commit_group;" ::: "memory")
template <int N>
__device__ __forceinline__ void cp_wait() {
    asm volatile("cp.async.wait_group %0;" :: "n"(N) : "memory");
}
__device__ __forceinline__ void ldsm4(uint32_t* r, uint32_t addr) {
    asm volatile("ldmatrix.sync.aligned.m8n8.x4.shared.b16 {%0,%1,%2,%3}, [%4];"
                 : "=r"(r[0]), "=r"(r[1]), "=r"(r[2]), "=r"(r[3]) : "r"(addr));
}
__device__ __forceinline__ void mma_f16(float* c, const uint32_t* a, const uint32_t* b) {
    asm volatile("mma.sync.aligned.m16n8k16.row.col.f32.f16.f16.f32 "
                 "{%0,%1,%2,%3}, {%4,%5,%6,%7}, {%8,%9}, {%0,%1,%2,%3};"
                 : "+f"(c[0]), "+f"(c[1]), "+f"(c[2]), "+f"(c[3])
                 : "r"(a[0]), "r"(a[1]), "r"(a[2]), "r"(a[3]), "r"(b[0]), "r"(b[1]));
}
__device__ __forceinline__ float2 cmul(float2 a, float2 b) {
    return make_float2(a.x * b.x - a.y * b.y, a.x * b.y + a.y * b.x);
}
__device__ __forceinline__ float2 cfma(float2 l, float2 s, float2 u) {  // l*s + u
    return make_float2(fmaf(l.x, s.x, fmaf(-l.y, s.y, u.x)),
                       fmaf(l.x, s.y, fmaf( l.y, s.x, u.y)));
}

// ---------------- prep ----------------
__device__ __forceinline__ void split_h(float v, __half& h, __half& l) {
    h = __float2half_rn(v);
    l = __float2half_rn(v - __half2float(h));
}

__global__ void prep_lambda_kernel(const float* __restrict__ nu_log,
                                   const float* __restrict__ theta_log) {
    int n = threadIdx.x;
    double nu  = exp((double)nu_log[n]);
    double th  = exp((double)theta_log[n]);
    double mod = exp(-nu);
    g_lam[n] = make_float2((float)(mod * cos(th)), (float)(mod * sin(th)));
    double m16 = exp(-16.0 * nu);
    g_lam16[n] = make_float2((float)(m16 * cos(16.0 * th)), (float)(m16 * sin(16.0 * th)));
    double m128 = exp(-128.0 * nu);
    g_lam128[n] = make_float2((float)(m128 * cos(128.0 * th)), (float)(m128 * sin(128.0 * th)));
}

__global__ void prep_w1_kernel(const float* __restrict__ gamma_log,
                               const float* __restrict__ B_re,
                               const float* __restrict__ B_im) {
    int idx = blockIdx.x * blockDim.x + threadIdx.x;
    if (idx >= SCOLS * IN_F) return;
    int r = idx / IN_F, i = idx % IN_F;
    int s = r >> 1;
    float gam = expf(gamma_log[s]);
    float v = gam * ((r & 1) ? B_im[s * IN_F + i] : B_re[s * IN_F + i]);
    split_h(v, g_W1h[idx], g_W1l[idx]);
}

__global__ void prep_wout_kernel(const float* __restrict__ C_re,
                                 const float* __restrict__ C_im,
                                 const float* __restrict__ D) {
    int idx = blockIdx.x * blockDim.x + threadIdx.x;
    if (idx >= OUT_F * KOUT) return;
    int o = idx / KOUT, k = idx % KOUT;
    float v;
    if (k < 512) {
        int s = k >> 1;
        v = (k & 1) ? -C_im[o * NSTATE + s] : C_re[o * NSTATE + s];
    } else {
        v = D[o * IN_F + (k - 512)];
    }
    split_h(v, g_Woh[idx], g_Wol[idx]);
}

__global__ void convert_x_kernel(const float* __restrict__ x) {
    size_t i = ((size_t)blockIdx.x * blockDim.x + threadIdx.x) * 4;
    float4 v = *(const float4*)(x + i);
    __half2* p = (__half2*)(g_x + i);
    p[0] = __half2(__float2half_rn(v.x), __float2half_rn(v.y));
    p[1] = __half2(__float2half_rn(v.z), __float2half_rn(v.w));
}

__global__ void zero_flags_kernel() {
    int i = threadIdx.x;
    #pragma unroll
    for (int k = 0; k < 4; k++) g_flag[i + k * 512] = 0;
}

// ---------------- unified MMA GEMM ----------------
// Block 128x128, 16 warps of 32x32, K-chunk 32, 2-stage cp.async.
// smem tile: 128 rows x 32 fp16, row stride 80B. Stage = A, Bh, Bl.
#define ROW_B   80
#define TILE_B  (128 * ROW_B)          // 10240
#define STAGE_B (3 * TILE_B)           // 30720
#define EPI_B   (128 * 128 * 4 + 8 * 64 * 8 * 2 + 64 * 8)   // smf + segc + Pseg + cin
#define GSMEM   ((2 * STAGE_B) > EPI_B ? (2 * STAGE_B) : EPI_B)

__device__ __forceinline__ void load_tile(uint32_t sm, const __half* __restrict__ g,
                                          size_t row0, int ld, int kb, int tid) {
    int r = tid >> 2, c = tid & 3;     // 512 threads x 16B
    cp16(sm + r * ROW_B + c * 16, g + (row0 + r) * (size_t)ld + kb + c * 8);
}

__global__ void __launch_bounds__(512, 1) gemm_kernel(
    const __half* __restrict__ A0, int lda0, int nk0,
    const __half* __restrict__ A1, int lda1,
    const __half* __restrict__ Bh, const __half* __restrict__ Bl, int ldb,
    float* __restrict__ out, int ldo, int nk, int do_scan)
{
    extern __shared__ char smem[];
    uint32_t sb = smem_u32(smem);
    int tid = threadIdx.x, lane = tid & 31, wid = tid >> 5;
    int wm = wid & 3, wn = wid >> 2;
    int bid = blockIdx.x;
    int m, nt;
    if (do_scan) { m = bid >> 2; nt = bid & 3; }
    else         { m = bid;      nt = 0;       }
    size_t m0 = (size_t)m * 128;
    int n0 = nt * 128;

    float acc[2][4][4];
    #pragma unroll
    for (int a = 0; a < 2; a++)
        #pragma unroll
        for (int b = 0; b < 4; b++)
            #pragma unroll
            for (int c = 0; c < 4; c++) acc[a][b][c] = 0.f;

    auto load_chunk = [&](int i, int s) {
        uint32_t st = sb + s * STAGE_B;
        const __half* a;
        int lda, kb;
        if (i < nk0) { a = A0; lda = lda0; kb = i * 32; }
        else         { a = A1; lda = lda1; kb = (i - nk0) * 32; }
        load_tile(st,              a,  m0, lda, kb, tid);
        load_tile(st + TILE_B,     Bh, (size_t)n0, ldb, i * 32, tid);
        load_tile(st + 2 * TILE_B, Bl, (size_t)n0, ldb, i * 32, tid);
    };

    load_chunk(0, 0);
    CP_COMMIT();

    for (int i = 0; i < nk; i++) {
        if (i + 1 < nk) { load_chunk(i + 1, (i + 1) & 1); CP_COMMIT(); cp_wait<1>(); }
        else            { cp_wait<0>(); }
        __syncthreads();

        uint32_t st = sb + (i & 1) * STAGE_B;
        #pragma unroll
        for (int kk = 0; kk < 32; kk += 16) {
            uint32_t af[2][4], bh[2][4], bl[2][4];
            int arow = wm * 32 + (lane & 15);
            int acol = kk + ((lane >> 4) << 3);
            #pragma unroll
            for (int mi = 0; mi < 2; mi++)
                ldsm4(af[mi], st + (arow + mi * 16) * ROW_B + acol * 2);
            int brow = wn * 32 + ((lane >> 4) << 3) + (lane & 7);
            int bcol = kk + (((lane >> 3) & 1) << 3);
            #pragma unroll
            for (int g = 0; g < 2; g++) {
                uint32_t bd = st + TILE_B + (brow + g * 16) * ROW_B + bcol * 2;
                ldsm4(bh[g], bd);
                ldsm4(bl[g], bd + TILE_B);
            }
            #pragma unroll
            for (int mi = 0; mi < 2; mi++)
                #pragma unroll
                for (int ni = 0; ni < 4; ni++) {
                    mma_f16(acc[mi][ni], af[mi], &bh[ni >> 1][(ni & 1) * 2]);
                    mma_f16(acc[mi][ni], af[mi], &bl[ni >> 1][(ni & 1) * 2]);
                }
        }
        __syncthreads();
    }

    int r0 = wm * 32 + (lane >> 2);
    int c0 = wn * 32 + (lane & 3) * 2;

    if (!do_scan) {
        // plain epilogue: fp32 stores
        #pragma unroll
        for (int mi = 0; mi < 2; mi++)
            #pragma unroll
            for (int ni = 0; ni < 4; ni++) {
                int rl = r0 + mi * 16, cl = c0 + ni * 8;
                *(float2*)(out + (m0 + rl) * (size_t)ldo + cl) =
                    make_float2(acc[mi][ni][0], acc[mi][ni][1]);
                *(float2*)(out + (m0 + rl + 8) * (size_t)ldo + cl) =
                    make_float2(acc[mi][ni][2], acc[mi][ni][3]);
            }
        return;
    }

    // ---- fused scan epilogue (GEMM1) ----
    float2* smf  = (float2*)smem;                       // [128 rows][64 states]
    float2* segc = (float2*)(smem + 65536);             // [8][64]
    float2* Pseg = (float2*)(smem + 65536 + 4096);      // [8][64]
    float2* cin  = (float2*)(smem + 65536 + 8192);      // [64]
    int sbase = nt * 64;

    #pragma unroll
    for (int mi = 0; mi < 2; mi++)
        #pragma unroll
        for (int ni = 0; ni < 4; ni++) {
            int rl = r0 + mi * 16, cl = c0 + ni * 8;
            smf[rl * 64 + (cl >> 1)]       = make_float2(acc[mi][ni][0], acc[mi][ni][1]);
            smf[(rl + 8) * 64 + (cl >> 1)] = make_float2(acc[mi][ni][2], acc[mi][ni][3]);
        }
    __syncthreads();

    // step1: segment-local scans (in place), 8 segs x 64 states
    int seg = tid >> 6, s = tid & 63;
    {
        float2 lam = g_lam[sbase + s];
        float2 p = make_float2(0.f, 0.f);
        #pragma unroll 4
        for (int t = 0; t < 16; t++) {
            int row = seg * 16 + t;
            p = cfma(lam, p, smf[row * 64 + s]);
            smf[row * 64 + s] = p;
        }
        segc[seg * 64 + s] = p;
    }
    __syncthreads();

    // step2: combine segments (zero-init prefixes + tile-local carry)
    float2 local_carry;
    if (tid < 64) {
        float2 l16 = g_lam16[sbase + s];
        float2 e = make_float2(0.f, 0.f);
        #pragma unroll
        for (int g = 0; g < 8; g++) {
            Pseg[g * 64 + s] = e;
            e = cfma(l16, e, segc[g * 64 + s]);
        }
        local_carry = e;
    }
    __syncthreads();

    // step3: decoupled look-back
    int ch = m & 63;
    if (ch > 0 && tid == 0) {
        volatile int* f = &g_flag[(m - 1) * 4 + nt];
        while (*f == 0) { }
    }
    __syncthreads();
    if (tid < 64) {
        float2 ci = make_float2(0.f, 0.f);
        if (ch > 0) {
            volatile float* p = (volatile float*)&g_carry[(size_t)((m - 1) * 4 + nt) * 64 + s];
            ci.x = p[0]; ci.y = p[1];
        }
        cin[s] = ci;
        float2 co = cfma(g_lam128[sbase + s], ci, local_carry);
        g_carry[(size_t)(m * 4 + nt) * 64 + s] = co;
        __threadfence();
    }
    __syncthreads();
    if (tid == 0) atomicExch(&g_flag[m * 4 + nt], 1);

    // step4: fixup + fp16 writeout
    {
        float2 lam = g_lam[sbase + s];
        float2 l16 = g_lam16[sbase + s];
        float2 lp = make_float2(1.f, 0.f);
        for (int q = 0; q < seg; q++) lp = cmul(lp, l16);
        float2 e = Pseg[seg * 64 + s];
        float2 c = cin[s];
        e.x += lp.x * c.x - lp.y * c.y;
        e.y += lp.x * c.y + lp.y * c.x;
        float2 mm = cmul(lam, e);
        #pragma unroll 4
        for (int t = 0; t < 16; t++) {
            int row = seg * 16 + t;
            float2 p = smf[row * 64 + s];
            float2 v = make_float2(p.x + mm.x, p.y + mm.y);
            mm = cmul(lam, mm);
            ((__half2*)(g_Ssc + (m0 + row) * SCOLS))[sbase + s] =
                __half2(__float2half_rn(v.x), __float2half_rn(v.y));
        }
    }
}

// ---------------- launch ----------------
extern "C" void kernel_launch(void* const* d_in, const int* in_sizes, int n_in,
                              void* d_out, int out_size) {
    const float* x         = (const float*)d_in[0];
    const float* nu_log    = (const float*)d_in[1];
    const float* theta_log = (const float*)d_in[2];
    const float* gamma_log = (const float*)d_in[3];
    const float* B_re      = (const float*)d_in[4];
    const float* B_im      = (const float*)d_in[5];
    const float* C_re      = (const float*)d_in[6];
    const float* C_im      = (const float*)d_in[7];
    const float* D         = (const float*)d_in[8];
    float* out = (float*)d_out;

    __half *xp, *sp, *w1h, *w1l, *woh, *wol;
    cudaGetSymbolAddress((void**)&xp,  g_x);
    cudaGetSymbolAddress((void**)&sp,  g_Ssc);
    cudaGetSymbolAddress((void**)&w1h, g_W1h);
    cudaGetSymbolAddress((void**)&w1l, g_W1l);
    cudaGetSymbolAddress((void**)&woh, g_Woh);
    cudaGetSymbolAddress((void**)&wol, g_Wol);

    cudaFuncSetAttribute(gemm_kernel, cudaFuncAttributeMaxDynamicSharedMemorySize, GSMEM);

    prep_lambda_kernel<<<1, 256>>>(nu_log, theta_log);
    prep_w1_kernel<<<(SCOLS * IN_F + 255) / 256, 256>>>(gamma_log, B_re, B_im);
    prep_wout_kernel<<<(OUT_F * KOUT + 255) / 256, 256>>>(C_re, C_im, D);
    convert_x_kernel<<<(MROWS * IN_F / 4) / 256, 256>>>(x);
    zero_flags_kernel<<<1, 512>>>();

    // GEMM1 + fused scan: states = scan(x @ W1^T), K=128
    gemm_kernel<<<2048, 512, GSMEM>>>(
        xp, IN_F, 4, xp, IN_F, w1h, w1l, IN_F, nullptr, 0, 4, 1);

    // GEMM2: out = S @ Wout^T (K 0..511 states, 512..639 x)
    gemm_kernel<<<MROWS / 128, 512, GSMEM>>>(
        sp, SCOLS, 16, xp, IN_F, woh, wol, KOUT, out, OUT_F, 20, 0);
}

// round 6
// speedup vs baseline: 1.6308x; 1.6308x over previous
#include <cuda_runtime.h>
#include <cuda_fp16.h>
#include <math.h>
#include <stdint.h>

// ---------------- problem constants ----------------
#define BATCH   8
#define T       8192
#define IN_F    128
#define OUT_F   128
#define NSTATE  256
#define NC      64
#define CHUNK   128
#define MROWS   (BATCH * T)     // 65536
#define SCOLS   512             // 2*NSTATE interleaved: col 2n=re, 2n+1=im
#define KOUT    640             // 512 states + 128 x

// ---------------- scratch ----------------
__device__ __align__(256) float  g_S[(size_t)MROWS * SCOLS];    // chunk-scanned states fp32
__device__ __align__(256) __half g_x[(size_t)MROWS * IN_F];     // x fp16
__device__ __align__(256) __half g_Ssc[(size_t)MROWS * SCOLS];  // final states fp16
__device__ __align__(256) __half g_W1h[SCOLS * IN_F];
__device__ __align__(256) __half g_W1l[SCOLS * IN_F];
__device__ __align__(256) __half g_Woh[OUT_F * KOUT];
__device__ __align__(256) __half g_Wol[OUT_F * KOUT];
__device__ float2  g_carry[BATCH * NC * NSTATE];   // per (b,chunk) state carries
__device__ float2  g_lam[NSTATE];
__device__ float2  g_lam32[NSTATE];
__device__ double2 g_lam128[NSTATE];

// ---------------- PTX helpers ----------------
__device__ __forceinline__ uint32_t smem_u32(const void* p) {
    uint32_t a;
    asm("{ .reg .u64 t; cvta.to.shared.u64 t, %1; cvt.u32.u64 %0, t; }" : "=r"(a) : "l"(p));
    return a;
}
__device__ __forceinline__ void cp16(uint32_t smem, const void* g) {
    asm volatile("cp.async.cg.shared.global [%0], [%1], 16;" :: "r"(smem), "l"(g));
}
#define CP_COMMIT() asm volatile("cp.async.commit_group;" ::: "memory")
template <int N>
__device__ __forceinline__ void cp_wait() {
    asm volatile("cp.async.wait_group %0;" :: "n"(N) : "memory");
}
__device__ __forceinline__ void ldsm4(uint32_t* r, uint32_t addr) {
    asm volatile("ldmatrix.sync.aligned.m8n8.x4.shared.b16 {%0,%1,%2,%3}, [%4];"
                 : "=r"(r[0]), "=r"(r[1]), "=r"(r[2]), "=r"(r[3]) : "r"(addr));
}
__device__ __forceinline__ void mma_f16(float* c, const uint32_t* a, const uint32_t* b) {
    asm volatile("mma.sync.aligned.m16n8k16.row.col.f32.f16.f16.f32 "
                 "{%0,%1,%2,%3}, {%4,%5,%6,%7}, {%8,%9}, {%0,%1,%2,%3};"
                 : "+f"(c[0]), "+f"(c[1]), "+f"(c[2]), "+f"(c[3])
                 : "r"(a[0]), "r"(a[1]), "r"(a[2]), "r"(a[3]), "r"(b[0]), "r"(b[1]));
}
__device__ __forceinline__ float2 cmul(float2 a, float2 b) {
    return make_float2(a.x * b.x - a.y * b.y, a.x * b.y + a.y * b.x);
}
__device__ __forceinline__ float2 cfma(float2 l, float2 s, float2 u) {  // l*s + u
    return make_float2(fmaf(l.x, s.x, fmaf(-l.y, s.y, u.x)),
                       fmaf(l.x, s.y, fmaf( l.y, s.x, u.y)));
}

// ---------------- prep ----------------
__device__ __forceinline__ void split_h(float v, __half& h, __half& l) {
    h = __float2half_rn(v);
    l = __float2half_rn(v - __half2float(h));
}

__global__ void prep_lambda_kernel(const float* __restrict__ nu_log,
                                   const float* __restrict__ theta_log) {
    int n = threadIdx.x;
    double nu  = exp((double)nu_log[n]);
    double th  = exp((double)theta_log[n]);
    double mod = exp(-nu);
    g_lam[n] = make_float2((float)(mod * cos(th)), (float)(mod * sin(th)));
    double m32 = exp(-32.0 * nu);
    g_lam32[n] = make_float2((float)(m32 * cos(32.0 * th)), (float)(m32 * sin(32.0 * th)));
    double m128 = exp(-128.0 * nu);
    g_lam128[n] = make_double2(m128 * cos(128.0 * th), m128 * sin(128.0 * th));
}

__global__ void prep_w1_kernel(const float* __restrict__ gamma_log,
                               const float* __restrict__ B_re,
                               const float* __restrict__ B_im) {
    int idx = blockIdx.x * blockDim.x + threadIdx.x;
    if (idx >= SCOLS * IN_F) return;
    int r = idx / IN_F, i = idx % IN_F;
    int s = r >> 1;
    float gam = expf(gamma_log[s]);
    float v = gam * ((r & 1) ? B_im[s * IN_F + i] : B_re[s * IN_F + i]);
    split_h(v, g_W1h[idx], g_W1l[idx]);
}

__global__ void prep_wout_kernel(const float* __restrict__ C_re,
                                 const float* __restrict__ C_im,
                                 const float* __restrict__ D) {
    int idx = blockIdx.x * blockDim.x + threadIdx.x;
    if (idx >= OUT_F * KOUT) return;
    int o = idx / KOUT, k = idx % KOUT;
    float v;
    if (k < 512) {
        int s = k >> 1;
        v = (k & 1) ? -C_im[o * NSTATE + s] : C_re[o * NSTATE + s];
    } else {
        v = D[o * IN_F + (k - 512)];
    }
    split_h(v, g_Woh[idx], g_Wol[idx]);
}

__global__ void convert_x_kernel(const float* __restrict__ x) {
    size_t i = ((size_t)blockIdx.x * blockDim.x + threadIdx.x) * 4;
    float4 v = *(const float4*)(x + i);
    __half2* p = (__half2*)(g_x + i);
    p[0] = __half2(__float2half_rn(v.x), __float2half_rn(v.y));
    p[1] = __half2(__float2half_rn(v.z), __float2half_rn(v.w));
}

// ---------------- MMA GEMM ----------------
// Block 128x128, 8 warps of 64x32, K-chunk 32, 2-stage cp.async.
// smem tile: 128 rows x 32 fp16, row stride 80B (conflict-free ldmatrix).
#define ROW_B   80
#define TILE_B  (128 * ROW_B)          // 10240
#define STAGE_B (3 * TILE_B)           // A, Bh, Bl = 30720
#define MAIN_B  (2 * STAGE_B)          // 61440
#define EPI_B   (65536 + 2 * 2048)     // smf + segc + Pseg
#define GSMEM   (MAIN_B > EPI_B ? MAIN_B : EPI_B)

__device__ __forceinline__ void load_tile(uint32_t sm, const __half* __restrict__ g,
                                          size_t row0, int ld, int kb, int tid) {
    #pragma unroll
    for (int t = 0; t < 2; t++) {
        int idx = tid + t * 256;       // 512 x 16B
        int r = idx >> 2, c = idx & 3;
        cp16(sm + r * ROW_B + c * 16, g + (row0 + r) * (size_t)ld + kb + c * 8);
    }
}

__global__ void __launch_bounds__(256, 1) gemm_kernel(
    const __half* __restrict__ A0, int lda0, int nk0,
    const __half* __restrict__ A1, int lda1,
    const __half* __restrict__ Bh, const __half* __restrict__ Bl, int ldb,
    float* __restrict__ out, int ldo, int nk, int do_scan)
{
    extern __shared__ char smem[];
    uint32_t sb = smem_u32(smem);
    int tid = threadIdx.x, lane = tid & 31, wid = tid >> 5;
    int wm = wid & 1, wn = wid >> 1;
    int m = blockIdx.x, nt = blockIdx.y;
    size_t m0 = (size_t)m * 128;
    int n0 = nt * 128;

    float acc[4][4][4];
    #pragma unroll
    for (int a = 0; a < 4; a++)
        #pragma unroll
        for (int b = 0; b < 4; b++)
            #pragma unroll
            for (int c = 0; c < 4; c++) acc[a][b][c] = 0.f;

    auto load_chunk = [&](int i, int s) {
        uint32_t st = sb + s * STAGE_B;
        const __half* a;
        int lda, kb;
        if (i < nk0) { a = A0; lda = lda0; kb = i * 32; }
        else         { a = A1; lda = lda1; kb = (i - nk0) * 32; }
        load_tile(st,              a,  m0, lda, kb, tid);
        load_tile(st + TILE_B,     Bh, (size_t)n0, ldb, i * 32, tid);
        load_tile(st + 2 * TILE_B, Bl, (size_t)n0, ldb, i * 32, tid);
    };

    load_chunk(0, 0);
    CP_COMMIT();

    for (int i = 0; i < nk; i++) {
        if (i + 1 < nk) { load_chunk(i + 1, (i + 1) & 1); CP_COMMIT(); cp_wait<1>(); }
        else            { cp_wait<0>(); }
        __syncthreads();

        uint32_t st = sb + (i & 1) * STAGE_B;
        #pragma unroll
        for (int kk = 0; kk < 32; kk += 16) {
            uint32_t af[4][4], bh[2][4], bl[2][4];
            int arow = wm * 64 + (lane & 15);
            int acol = kk + ((lane >> 4) << 3);
            #pragma unroll
            for (int mi = 0; mi < 4; mi++)
                ldsm4(af[mi], st + (arow + mi * 16) * ROW_B + acol * 2);
            int brow = wn * 32 + ((lane >> 4) << 3) + (lane & 7);
            int bcol = kk + (((lane >> 3) & 1) << 3);
            #pragma unroll
            for (int g = 0; g < 2; g++) {
                uint32_t bd = st + TILE_B + (brow + g * 16) * ROW_B + bcol * 2;
                ldsm4(bh[g], bd);
                ldsm4(bl[g], bd + TILE_B);
            }
            #pragma unroll
            for (int mi = 0; mi < 4; mi++)
                #pragma unroll
                for (int ni = 0; ni < 4; ni++) {
                    mma_f16(acc[mi][ni], af[mi], &bh[ni >> 1][(ni & 1) * 2]);
                    mma_f16(acc[mi][ni], af[mi], &bl[ni >> 1][(ni & 1) * 2]);
                }
        }
        __syncthreads();
    }

    int r0 = wm * 64 + (lane >> 2);
    int c0 = wn * 32 + (lane & 3) * 2;

    if (!do_scan) {
        #pragma unroll
        for (int mi = 0; mi < 4; mi++)
            #pragma unroll
            for (int ni = 0; ni < 4; ni++) {
                int rl = r0 + mi * 16, cl = c0 + ni * 8;
                *(float2*)(out + (m0 + rl) * (size_t)ldo + n0 + cl) =
                    make_float2(acc[mi][ni][0], acc[mi][ni][1]);
                *(float2*)(out + (m0 + rl + 8) * (size_t)ldo + n0 + cl) =
                    make_float2(acc[mi][ni][2], acc[mi][ni][3]);
            }
        return;
    }

    // ---- fused tile-local scan epilogue (GEMM1) ----
    float2* smf  = (float2*)smem;                  // [128 rows][64 states]
    float2* segc = (float2*)(smem + 65536);        // [4][64]
    float2* Pseg = (float2*)(smem + 65536 + 2048); // [4][64]
    int sbase = nt * 64;

    #pragma unroll
    for (int mi = 0; mi < 4; mi++)
        #pragma unroll
        for (int ni = 0; ni < 4; ni++) {
            int rl = r0 + mi * 16, cl = c0 + ni * 8;
            smf[rl * 64 + (cl >> 1)]       = make_float2(acc[mi][ni][0], acc[mi][ni][1]);
            smf[(rl + 8) * 64 + (cl >> 1)] = make_float2(acc[mi][ni][2], acc[mi][ni][3]);
        }
    __syncthreads();

    // step1: 4 segments x 32 rows, local scans in place
    int seg = tid >> 6, s = tid & 63;
    {
        float2 lam = g_lam[sbase + s];
        float2 p = make_float2(0.f, 0.f);
        #pragma unroll 4
        for (int t = 0; t < 32; t++) {
            int row = seg * 32 + t;
            p = cfma(lam, p, smf[row * 64 + s]);
            smf[row * 64 + s] = p;
        }
        segc[seg * 64 + s] = p;
    }
    __syncthreads();

    // step2: exclusive prefix of segment carries (Lambda^32 steps) + tile carry out
    if (tid < 64) {
        float2 l32 = g_lam32[sbase + s];
        float2 e = make_float2(0.f, 0.f);
        #pragma unroll
        for (int g = 0; g < 4; g++) {
            Pseg[g * 64 + s] = e;
            e = cfma(l32, e, segc[g * 64 + s]);
        }
        g_carry[(size_t)m * NSTATE + sbase + s] = e;   // m == b*NC + chunk
    }
    __syncthreads();

    // step3: apply segment prefix, write chunk-scanned fp32 values
    {
        float2 lam = g_lam[sbase + s];
        float2 mm = cmul(lam, Pseg[seg * 64 + s]);
        #pragma unroll 4
        for (int t = 0; t < 32; t++) {
            int row = seg * 32 + t;
            float2 p = smf[row * 64 + s];
            float2 v = make_float2(p.x + mm.x, p.y + mm.y);
            mm = cmul(lam, mm);
            ((float2*)(g_S + (m0 + row) * SCOLS))[sbase + s] = v;
        }
    }
}

// ---------------- cross-chunk combine (fp64) ----------------
__global__ void combine_kernel() {
    int b = blockIdx.x;
    int n = threadIdx.x;
    double2 lL = g_lam128[n];
    double pre = 0.0, pim = 0.0;
    for (int c = 0; c < NC; c++) {
        float2* p = &g_carry[((size_t)b * NC + c) * NSTATE + n];
        double cre = (double)p->x, cim = (double)p->y;
        double nre = lL.x * pre - lL.y * pim + cre;
        double nim = lL.x * pim + lL.y * pre + cim;
        pre = nre; pim = nim;
        *p = make_float2((float)pre, (float)pim);
    }
}

// ---------------- fixup: add Lambda^(j+1)*carry_in, emit fp16 states ----------------
__global__ void fixup_kernel() {
    int b = blockIdx.x >> 6;
    int c = blockIdx.x & 63;
    int s = threadIdx.x;       // state 0..255
    float2 ci = make_float2(0.f, 0.f);
    if (c > 0) ci = g_carry[((size_t)b * NC + c - 1) * NSTATE + s];
    float2 lam = g_lam[s];
    float2 mm = cmul(lam, ci);
    size_t rbase = (size_t)(b * T + c * CHUNK);
    const float2* in = (const float2*)(g_S + rbase * SCOLS) + s;
    __half2* outp = (__half2*)(g_Ssc + rbase * SCOLS) + s;
    #pragma unroll 2
    for (int j = 0; j < CHUNK; j++) {
        float2 v = in[(size_t)j * (SCOLS / 2)];
        v.x += mm.x; v.y += mm.y;
        mm = cmul(lam, mm);
        outp[(size_t)j * (SCOLS / 2)] = __half2(__float2half_rn(v.x), __float2half_rn(v.y));
    }
}

// ---------------- launch ----------------
extern "C" void kernel_launch(void* const* d_in, const int* in_sizes, int n_in,
                              void* d_out, int out_size) {
    const float* x         = (const float*)d_in[0];
    const float* nu_log    = (const float*)d_in[1];
    const float* theta_log = (const float*)d_in[2];
    const float* gamma_log = (const float*)d_in[3];
    const float* B_re      = (const float*)d_in[4];
    const float* B_im      = (const float*)d_in[5];
    const float* C_re      = (const float*)d_in[6];
    const float* C_im      = (const float*)d_in[7];
    const float* D         = (const float*)d_in[8];
    float* out = (float*)d_out;

    __half *xp, *sp, *w1h, *w1l, *woh, *wol;
    float* S;
    cudaGetSymbolAddress((void**)&xp,  g_x);
    cudaGetSymbolAddress((void**)&sp,  g_Ssc);
    cudaGetSymbolAddress((void**)&w1h, g_W1h);
    cudaGetSymbolAddress((void**)&w1l, g_W1l);
    cudaGetSymbolAddress((void**)&woh, g_Woh);
    cudaGetSymbolAddress((void**)&wol, g_Wol);
    cudaGetSymbolAddress((void**)&S,   g_S);

    cudaFuncSetAttribute(gemm_kernel, cudaFuncAttributeMaxDynamicSharedMemorySize, GSMEM);

    prep_lambda_kernel<<<1, 256>>>(nu_log, theta_log);
    prep_w1_kernel<<<(SCOLS * IN_F + 255) / 256, 256>>>(gamma_log, B_re, B_im);
    prep_wout_kernel<<<(OUT_F * KOUT + 255) / 256, 256>>>(C_re, C_im, D);
    convert_x_kernel<<<(MROWS * IN_F / 4) / 256, 256>>>(x);

    // GEMM1 + fused tile-local scan: g_S = chunkscan(x @ W1^T), K=128
    gemm_kernel<<<dim3(MROWS / 128, 4), 256, GSMEM>>>(
        xp, IN_F, 4, xp, IN_F, w1h, w1l, IN_F, nullptr, 0, 4, 1);

    combine_kernel<<<BATCH, NSTATE>>>();
    fixup_kernel<<<BATCH * NC, NSTATE>>>();

    // GEMM2: out = S @ Wout^T (K 0..511 states fp16, 512..639 x)
    gemm_kernel<<<dim3(MROWS / 128, 1), 256, GSMEM>>>(
        sp, SCOLS, 16, xp, IN_F, woh, wol, KOUT, out, OUT_F, 20, 0);
}

// round 8
// speedup vs baseline: 2.3475x; 1.4395x over previous
#include <cuda_runtime.h>
#include <cuda_fp16.h>
#include <math.h>
#include <stdint.h>

// ---------------- problem constants ----------------
#define BATCH   8
#define T       8192
#define IN_F    128
#define OUT_F   128
#define NSTATE  256
#define NC      64
#define CHUNK   128
#define MROWS   (BATCH * T)     // 65536
#define SCOLS   512             // 2*NSTATE interleaved: col 2n=re, 2n+1=im
#define KOUT    640             // 512 states + 128 x

// ---------------- scratch ----------------
__device__ __align__(256) __half g_x[(size_t)MROWS * IN_F];     // x fp16
__device__ __align__(256) __half g_Ssc[(size_t)MROWS * SCOLS];  // prescan -> final states fp16
__device__ __align__(256) __half g_W1[SCOLS * IN_F];
__device__ __align__(256) __half g_Wo[OUT_F * KOUT];
__device__ float2  g_carry[BATCH * NC * NSTATE];
__device__ float2  g_lam[NSTATE];
__device__ float2  g_lam32[NSTATE];
__device__ double2 g_lam128[NSTATE];

// ---------------- PTX helpers ----------------
__device__ __forceinline__ uint32_t smem_u32(const void* p) {
    uint32_t a;
    asm("{ .reg .u64 t; cvta.to.shared.u64 t, %1; cvt.u32.u64 %0, t; }" : "=r"(a) : "l"(p));
    return a;
}
__device__ __forceinline__ void cp16(uint32_t smem, const void* g) {
    asm volatile("cp.async.cg.shared.global [%0], [%1], 16;" :: "r"(smem), "l"(g));
}
#define CP_COMMIT() asm volatile("cp.async.commit_group;" ::: "memory")
template <int N>
__device__ __forceinline__ void cp_wait() {
    asm volatile("cp.async.wait_group %0;" :: "n"(N) : "memory");
}
__device__ __forceinline__ void ldsm4(uint32_t* r, uint32_t addr) {
    asm volatile("ldmatrix.sync.aligned.m8n8.x4.shared.b16 {%0,%1,%2,%3}, [%4];"
                 : "=r"(r[0]), "=r"(r[1]), "=r"(r[2]), "=r"(r[3]) : "r"(addr));
}
__device__ __forceinline__ void mma_f16(float* c, const uint32_t* a, const uint32_t* b) {
    asm volatile("mma.sync.aligned.m16n8k16.row.col.f32.f16.f16.f32 "
                 "{%0,%1,%2,%3}, {%4,%5,%6,%7}, {%8,%9}, {%0,%1,%2,%3};"
                 : "+f"(c[0]), "+f"(c[1]), "+f"(c[2]), "+f"(c[3])
                 : "r"(a[0]), "r"(a[1]), "r"(a[2]), "r"(a[3]), "r"(b[0]), "r"(b[1]));
}
__device__ __forceinline__ float2 cmul(float2 a, float2 b) {
    return make_float2(a.x * b.x - a.y * b.y, a.x * b.y + a.y * b.x);
}
__device__ __forceinline__ float2 cfma(float2 l, float2 s, float2 u) {  // l*s + u
    return make_float2(fmaf(l.x, s.x, fmaf(-l.y, s.y, u.x)),
                       fmaf(l.x, s.y, fmaf( l.y, s.x, u.y)));
}

// ---------------- prep ----------------
__global__ void prep_lambda_kernel(const float* __restrict__ nu_log,
                                   const float* __restrict__ theta_log) {
    int n = threadIdx.x;
    double nu  = exp((double)nu_log[n]);
    double th  = exp((double)theta_log[n]);
    double mod = exp(-nu);
    g_lam[n] = make_float2((float)(mod * cos(th)), (float)(mod * sin(th)));
    double m32 = exp(-32.0 * nu);
    g_lam32[n] = make_float2((float)(m32 * cos(32.0 * th)), (float)(m32 * sin(32.0 * th)));
    double m128 = exp(-128.0 * nu);
    g_lam128[n] = make_double2(m128 * cos(128.0 * th), m128 * sin(128.0 * th));
}

__global__ void prep_w1_kernel(const float* __restrict__ gamma_log,
                               const float* __restrict__ B_re,
                               const float* __restrict__ B_im) {
    int idx = blockIdx.x * blockDim.x + threadIdx.x;
    if (idx >= SCOLS * IN_F) return;
    int r = idx / IN_F, i = idx % IN_F;
    int s = r >> 1;
    float gam = expf(gamma_log[s]);
    float v = gam * ((r & 1) ? B_im[s * IN_F + i] : B_re[s * IN_F + i]);
    g_W1[idx] = __float2half_rn(v);
}

__global__ void prep_wout_kernel(const float* __restrict__ C_re,
                                 const float* __restrict__ C_im,
                                 const float* __restrict__ D) {
    int idx = blockIdx.x * blockDim.x + threadIdx.x;
    if (idx >= OUT_F * KOUT) return;
    int o = idx / KOUT, k = idx % KOUT;
    float v;
    if (k < 512) {
        int s = k >> 1;
        v = (k & 1) ? -C_im[o * NSTATE + s] : C_re[o * NSTATE + s];
    } else {
        v = D[o * IN_F + (k - 512)];
    }
    g_Wo[idx] = __float2half_rn(v);
}

__global__ void convert_x_kernel(const float* __restrict__ x) {
    size_t i = ((size_t)blockIdx.x * blockDim.x + threadIdx.x) * 4;
    float4 v = *(const float4*)(x + i);
    __half2* p = (__half2*)(g_x + i);
    p[0] = __half2(__float2half_rn(v.x), __float2half_rn(v.y));
    p[1] = __half2(__float2half_rn(v.z), __float2half_rn(v.w));
}

// ---------------- MMA GEMM ----------------
// Block 128x128, 8 warps of 64x32, K-chunk 32, 2-stage cp.async.
// smem tile: 128 rows x 32 fp16, row stride 80B (conflict-free ldmatrix).
#define ROW_B   80
#define TILE_B  (128 * ROW_B)          // 10240
#define STAGE_B (2 * TILE_B)           // A, B = 20480
#define MAIN_B  (2 * STAGE_B)          // 40960
#define EPI_B   (65536 + 2 * 2048)     // smf + segc + Pseg
#define GSMEM   (MAIN_B > EPI_B ? MAIN_B : EPI_B)

__device__ __forceinline__ void load_tile(uint32_t sm, const __half* __restrict__ g,
                                          size_t row0, int ld, int kb, int tid) {
    #pragma unroll
    for (int t = 0; t < 2; t++) {
        int idx = tid + t * 256;       // 512 x 16B
        int r = idx >> 2, c = idx & 3;
        cp16(sm + r * ROW_B + c * 16, g + (row0 + r) * (size_t)ld + kb + c * 8);
    }
}

__global__ void __launch_bounds__(256, 1) gemm_kernel(
    const __half* __restrict__ A0, int lda0, int nk0,
    const __half* __restrict__ A1, int lda1,
    const __half* __restrict__ B, int ldb,
    float* __restrict__ out, int ldo, int nk, int do_scan)
{
    extern __shared__ char smem[];
    uint32_t sb = smem_u32(smem);
    int tid = threadIdx.x, lane = tid & 31, wid = tid >> 5;
    int wm = wid & 1, wn = wid >> 1;
    int m = blockIdx.x, nt = blockIdx.y;
    size_t m0 = (size_t)m * 128;
    int n0 = nt * 128;

    float acc[4][4][4];
    #pragma unroll
    for (int a = 0; a < 4; a++)
        #pragma unroll
        for (int b = 0; b < 4; b++)
            #pragma unroll
            for (int c = 0; c < 4; c++) acc[a][b][c] = 0.f;

    auto load_chunk = [&](int i, int s) {
        uint32_t st = sb + s * STAGE_B;
        const __half* a;
        int lda, kb;
        if (i < nk0) { a = A0; lda = lda0; kb = i * 32; }
        else         { a = A1; lda = lda1; kb = (i - nk0) * 32; }
        load_tile(st,          a, m0, lda, kb, tid);
        load_tile(st + TILE_B, B, (size_t)n0, ldb, i * 32, tid);
    };

    load_chunk(0, 0);
    CP_COMMIT();

    for (int i = 0; i < nk; i++) {
        if (i + 1 < nk) { load_chunk(i + 1, (i + 1) & 1); CP_COMMIT(); cp_wait<1>(); }
        else            { cp_wait<0>(); }
        __syncthreads();

        uint32_t st = sb + (i & 1) * STAGE_B;
        #pragma unroll
        for (int kk = 0; kk < 32; kk += 16) {
            uint32_t af[4][4], bf[2][4];
            int arow = wm * 64 + (lane & 15);
            int acol = kk + ((lane >> 4) << 3);
            #pragma unroll
            for (int mi = 0; mi < 4; mi++)
                ldsm4(af[mi], st + (arow + mi * 16) * ROW_B + acol * 2);
            int brow = wn * 32 + ((lane >> 4) << 3) + (lane & 7);
            int bcol = kk + (((lane >> 3) & 1) << 3);
            #pragma unroll
            for (int g = 0; g < 2; g++)
                ldsm4(bf[g], st + TILE_B + (brow + g * 16) * ROW_B + bcol * 2);
            #pragma unroll
            for (int mi = 0; mi < 4; mi++)
                #pragma unroll
                for (int ni = 0; ni < 4; ni++)
                    mma_f16(acc[mi][ni], af[mi], &bf[ni >> 1][(ni & 1) * 2]);
        }
        __syncthreads();
    }

    int r0 = wm * 64 + (lane >> 2);
    int c0 = wn * 32 + (lane & 3) * 2;

    if (!do_scan) {
        #pragma unroll
        for (int mi = 0; mi < 4; mi++)
            #pragma unroll
            for (int ni = 0; ni < 4; ni++) {
                int rl = r0 + mi * 16, cl = c0 + ni * 8;
                *(float2*)(out + (m0 + rl) * (size_t)ldo + n0 + cl) =
                    make_float2(acc[mi][ni][0], acc[mi][ni][1]);
                *(float2*)(out + (m0 + rl + 8) * (size_t)ldo + n0 + cl) =
                    make_float2(acc[mi][ni][2], acc[mi][ni][3]);
            }
        return;
    }

    // ---- fused tile-local scan epilogue (GEMM1): write fp16 prescan + carries ----
    float2* smf  = (float2*)smem;                  // [128 rows][64 states]
    float2* segc = (float2*)(smem + 65536);        // [4][64]
    float2* Pseg = (float2*)(smem + 65536 + 2048); // [4][64]
    int sbase = nt * 64;

    #pragma unroll
    for (int mi = 0; mi < 4; mi++)
        #pragma unroll
        for (int ni = 0; ni < 4; ni++) {
            int rl = r0 + mi * 16, cl = c0 + ni * 8;
            smf[rl * 64 + (cl >> 1)]       = make_float2(acc[mi][ni][0], acc[mi][ni][1]);
            smf[(rl + 8) * 64 + (cl >> 1)] = make_float2(acc[mi][ni][2], acc[mi][ni][3]);
        }
    __syncthreads();

    int seg = tid >> 6, s = tid & 63;
    {   // step1: 4 segments x 32 rows, local scans in place
        float2 lam = g_lam[sbase + s];
        float2 p = make_float2(0.f, 0.f);
        #pragma unroll 4
        for (int t = 0; t < 32; t++) {
            int row = seg * 32 + t;
            p = cfma(lam, p, smf[row * 64 + s]);
            smf[row * 64 + s] = p;
        }
        segc[seg * 64 + s] = p;
    }
    __syncthreads();

    // step2: exclusive prefix of segment carries + tile carry out
    if (tid < 64) {
        float2 l32 = g_lam32[sbase + s];
        float2 e = make_float2(0.f, 0.f);
        #pragma unroll
        for (int g = 0; g < 4; g++) {
            Pseg[g * 64 + s] = e;
            e = cfma(l32, e, segc[g * 64 + s]);
        }
        g_carry[(size_t)m * NSTATE + sbase + s] = e;   // m == b*NC + chunk
    }
    __syncthreads();

    // step3: apply segment prefix, emit fp16 prescan states
    {
        float2 lam = g_lam[sbase + s];
        float2 mm = cmul(lam, Pseg[seg * 64 + s]);
        #pragma unroll 4
        for (int t = 0; t < 32; t++) {
            int row = seg * 32 + t;
            float2 p = smf[row * 64 + s];
            float2 v = make_float2(p.x + mm.x, p.y + mm.y);
            mm = cmul(lam, mm);
            ((__half2*)(g_Ssc + (m0 + row) * SCOLS))[sbase + s] =
                __half2(__float2half_rn(v.x), __float2half_rn(v.y));
        }
    }
}

// ---------------- cross-chunk combine (fp64, batched loads) ----------------
__global__ void combine_kernel() {
    int b = blockIdx.x;
    int n = threadIdx.x;
    double2 lL = g_lam128[n];
    double pre = 0.0, pim = 0.0;
    for (int c0 = 0; c0 < NC; c0 += 16) {
        float2 v[16];
        #pragma unroll
        for (int k = 0; k < 16; k++)
            v[k] = g_carry[((size_t)b * NC + c0 + k) * NSTATE + n];
        #pragma unroll
        for (int k = 0; k < 16; k++) {
            double nre = lL.x * pre - lL.y * pim + (double)v[k].x;
            double nim = lL.x * pim + lL.y * pre + (double)v[k].y;
            pre = nre; pim = nim;
            v[k] = make_float2((float)pre, (float)pim);
        }
        #pragma unroll
        for (int k = 0; k < 16; k++)
            g_carry[((size_t)b * NC + c0 + k) * NSTATE + n] = v[k];
    }
}

// ---------------- fixup (in place on fp16 states) ----------------
__global__ void fixup_kernel() {
    int b = blockIdx.x >> 6;
    int c = blockIdx.x & 63;
    int s = threadIdx.x;       // state 0..255
    if (c == 0) return;        // chunk 0 already final
    float2 ci = g_carry[((size_t)b * NC + c - 1) * NSTATE + s];
    float2 lam = g_lam[s];
    float2 mm = cmul(lam, ci);
    size_t rbase = (size_t)(b * T + c * CHUNK);
    __half2* p = (__half2*)(g_Ssc + rbase * SCOLS) + s;
    #pragma unroll 2
    for (int j = 0; j < CHUNK; j++) {
        __half2 hv = p[(size_t)j * (SCOLS / 2)];
        float2 v = make_float2(__half2float(hv.x) + mm.x, __half2float(hv.y) + mm.y);
        mm = cmul(lam, mm);
        p[(size_t)j * (SCOLS / 2)] = __half2(__float2half_rn(v.x), __float2half_rn(v.y));
    }
}

// ---------------- launch ----------------
extern "C" void kernel_launch(void* const* d_in, const int* in_sizes, int n_in,
                              void* d_out, int out_size) {
    const float* x         = (const float*)d_in[0];
    const float* nu_log    = (const float*)d_in[1];
    const float* theta_log = (const float*)d_in[2];
    const float* gamma_log = (const float*)d_in[3];
    const float* B_re      = (const float*)d_in[4];
    const float* B_im      = (const float*)d_in[5];
    const float* C_re      = (const float*)d_in[6];
    const float* C_im      = (const float*)d_in[7];
    const float* D         = (const float*)d_in[8];
    float* out = (float*)d_out;

    __half *xp, *sp, *w1, *wo;
    cudaGetSymbolAddress((void**)&xp, g_x);
    cudaGetSymbolAddress((void**)&sp, g_Ssc);
    cudaGetSymbolAddress((void**)&w1, g_W1);
    cudaGetSymbolAddress((void**)&wo, g_Wo);

    cudaFuncSetAttribute(gemm_kernel, cudaFuncAttributeMaxDynamicSharedMemorySize, GSMEM);

    prep_lambda_kernel<<<1, 256>>>(nu_log, theta_log);
    prep_w1_kernel<<<(SCOLS * IN_F + 255) / 256, 256>>>(gamma_log, B_re, B_im);
    prep_wout_kernel<<<(OUT_F * KOUT + 255) / 256, 256>>>(C_re, C_im, D);
    convert_x_kernel<<<(MROWS * IN_F / 4) / 256, 256>>>(x);

    // GEMM1 + fused tile-local scan: g_Ssc = chunkscan(x @ W1^T) (fp16), K=128
    gemm_kernel<<<dim3(MROWS / 128, 4), 256, GSMEM>>>(
        xp, IN_F, 4, xp, IN_F, w1, IN_F, nullptr, 0, 4, 1);

    combine_kernel<<<BATCH, NSTATE>>>();
    fixup_kernel<<<BATCH * NC, NSTATE>>>();

    // GEMM2: out = S @ Wout^T (K 0..511 states fp16, 512..639 x)
    gemm_kernel<<<dim3(MROWS / 128, 1), 256, GSMEM>>>(
        sp, SCOLS, 16, xp, IN_F, wo, KOUT, out, OUT_F, 20, 0);
}

// round 10
// speedup vs baseline: 2.5517x; 1.0870x over previous
#include <cuda_runtime.h>
#include <cuda_fp16.h>
#include <math.h>
#include <stdint.h>

// ---------------- problem constants ----------------
#define BATCH   8
#define T       8192
#define IN_F    128
#define OUT_F   128
#define NSTATE  256
#define NC      64
#define CHUNK   128
#define MROWS   (BATCH * T)     // 65536
#define SCOLS   512             // 2*NSTATE interleaved: col 2n=re, 2n+1=im
#define KOUT    640             // 512 states + 128 x

// ---------------- scratch ----------------
__device__ __align__(256) __half g_x[(size_t)MROWS * IN_F];     // x fp16
__device__ __align__(256) __half g_Ssc[(size_t)MROWS * SCOLS];  // prescan -> final states fp16
__device__ __align__(256) __half g_W1[SCOLS * IN_F];
__device__ __align__(256) __half g_Wo[OUT_F * KOUT];
__device__ float2  g_carry[BATCH * NC * NSTATE];
__device__ float2  g_lam[NSTATE];
__device__ float2  g_lam32[NSTATE];
__device__ double2 g_lam128[NSTATE];

// ---------------- PTX helpers ----------------
__device__ __forceinline__ uint32_t smem_u32(const void* p) {
    uint32_t a;
    asm("{ .reg .u64 t; cvta.to.shared.u64 t, %1; cvt.u32.u64 %0, t; }" : "=r"(a) : "l"(p));
    return a;
}
__device__ __forceinline__ void cp16(uint32_t smem, const void* g) {
    asm volatile("cp.async.cg.shared.global [%0], [%1], 16;" :: "r"(smem), "l"(g));
}
#define CP_COMMIT() asm volatile("cp.async.commit_group;" ::: "memory")
template <int N>
__device__ __forceinline__ void cp_wait() {
    asm volatile("cp.async.wait_group %0;" :: "n"(N) : "memory");
}
__device__ __forceinline__ void ldsm4(uint32_t* r, uint32_t addr) {
    asm volatile("ldmatrix.sync.aligned.m8n8.x4.shared.b16 {%0,%1,%2,%3}, [%4];"
                 : "=r"(r[0]), "=r"(r[1]), "=r"(r[2]), "=r"(r[3]) : "r"(addr));
}
__device__ __forceinline__ void mma_f16(float* c, const uint32_t* a, const uint32_t* b) {
    asm volatile("mma.sync.aligned.m16n8k16.row.col.f32.f16.f16.f32 "
                 "{%0,%1,%2,%3}, {%4,%5,%6,%7}, {%8,%9}, {%0,%1,%2,%3};"
                 : "+f"(c[0]), "+f"(c[1]), "+f"(c[2]), "+f"(c[3])
                 : "r"(a[0]), "r"(a[1]), "r"(a[2]), "r"(a[3]), "r"(b[0]), "r"(b[1]));
}
__device__ __forceinline__ float2 cmul(float2 a, float2 b) {
    return make_float2(a.x * b.x - a.y * b.y, a.x * b.y + a.y * b.x);
}
__device__ __forceinline__ float2 cfma(float2 l, float2 s, float2 u) {  // l*s + u
    return make_float2(fmaf(l.x, s.x, fmaf(-l.y, s.y, u.x)),
                       fmaf(l.x, s.y, fmaf( l.y, s.x, u.y)));
}

// ---------------- prep ----------------
__global__ void prep_lambda_kernel(const float* __restrict__ nu_log,
                                   const float* __restrict__ theta_log) {
    int n = threadIdx.x;
    double nu  = exp((double)nu_log[n]);
    double th  = exp((double)theta_log[n]);
    double mod = exp(-nu);
    g_lam[n] = make_float2((float)(mod * cos(th)), (float)(mod * sin(th)));
    double m32 = exp(-32.0 * nu);
    g_lam32[n] = make_float2((float)(m32 * cos(32.0 * th)), (float)(m32 * sin(32.0 * th)));
    double m128 = exp(-128.0 * nu);
    g_lam128[n] = make_double2(m128 * cos(128.0 * th), m128 * sin(128.0 * th));
}

__global__ void prep_w1_kernel(const float* __restrict__ gamma_log,
                               const float* __restrict__ B_re,
                               const float* __restrict__ B_im) {
    int idx = blockIdx.x * blockDim.x + threadIdx.x;
    if (idx >= SCOLS * IN_F) return;
    int r = idx / IN_F, i = idx % IN_F;
    int s = r >> 1;
    float gam = expf(gamma_log[s]);
    float v = gam * ((r & 1) ? B_im[s * IN_F + i] : B_re[s * IN_F + i]);
    g_W1[idx] = __float2half_rn(v);
}

__global__ void prep_wout_kernel(const float* __restrict__ C_re,
                                 const float* __restrict__ C_im,
                                 const float* __restrict__ D) {
    int idx = blockIdx.x * blockDim.x + threadIdx.x;
    if (idx >= OUT_F * KOUT) return;
    int o = idx / KOUT, k = idx % KOUT;
    float v;
    if (k < 512) {
        int s = k >> 1;
        v = (k & 1) ? -C_im[o * NSTATE + s] : C_re[o * NSTATE + s];
    } else {
        v = D[o * IN_F + (k - 512)];
    }
    g_Wo[idx] = __float2half_rn(v);
}

__global__ void convert_x_kernel(const float* __restrict__ x) {
    size_t i = ((size_t)blockIdx.x * blockDim.x + threadIdx.x) * 4;
    float4 v = *(const float4*)(x + i);
    __half2* p = (__half2*)(g_x + i);
    p[0] = __half2(__float2half_rn(v.x), __float2half_rn(v.y));
    p[1] = __half2(__float2half_rn(v.z), __float2half_rn(v.w));
}

// ---------------- MMA GEMM ----------------
// 8 warps of 64x64. GEMM1: block 128x256; GEMM2: block 256x128.
// Stage = (bm + bn) rows x 32 fp16 @ ROW_B stride = 384*80 = 30720 both ways.
#define ROW_B   80
#define STAGE_B (384 * ROW_B)          // 30720
#define MAIN_B  (2 * STAGE_B)          // 61440
#define EPI_B   (128 * 128 * 8 + 2 * 4096)  // smf(128KB) + segc + Pseg
#define GSMEM   (MAIN_B > EPI_B ? MAIN_B : EPI_B)

__device__ __forceinline__ void load_tile(uint32_t sm, const __half* __restrict__ g,
                                          size_t row0, int ld, int kb, int tid, int rows) {
    int nchunk = rows * 4;             // 16B chunks (32 cols fp16 per row)
    for (int idx = tid; idx < nchunk; idx += 256) {
        int r = idx >> 2, c = idx & 3;
        cp16(sm + r * ROW_B + c * 16, g + (row0 + r) * (size_t)ld + kb + c * 8);
    }
}

__global__ void __launch_bounds__(256, 1) gemm_kernel(
    const __half* __restrict__ A0, int lda0, int nk0,
    const __half* __restrict__ A1, int lda1,
    const __half* __restrict__ B, int ldb,
    float* __restrict__ out, int ldo, int nk, int do_scan,
    int bm, int bn)
{
    extern __shared__ char smem[];
    uint32_t sb = smem_u32(smem);
    int tid = threadIdx.x, lane = tid & 31, wid = tid >> 5;
    int wmN = bm >> 6;
    int wm = wid % wmN, wn = wid / wmN;
    int m = blockIdx.x, nt = blockIdx.y;
    size_t m0 = (size_t)m * bm;
    int n0 = nt * bn;
    uint32_t bOff = (uint32_t)bm * ROW_B;

    float acc[4][8][4];
    #pragma unroll
    for (int a = 0; a < 4; a++)
        #pragma unroll
        for (int b2 = 0; b2 < 8; b2++)
            #pragma unroll
            for (int c = 0; c < 4; c++) acc[a][b2][c] = 0.f;

    auto load_chunk = [&](int i, int s) {
        uint32_t st = sb + s * STAGE_B;
        const __half* a;
        int lda, kb;
        if (i < nk0) { a = A0; lda = lda0; kb = i * 32; }
        else         { a = A1; lda = lda1; kb = (i - nk0) * 32; }
        load_tile(st,        a, m0, lda, kb, tid, bm);
        load_tile(st + bOff, B, (size_t)n0, ldb, i * 32, tid, bn);
    };

    load_chunk(0, 0);
    CP_COMMIT();

    for (int i = 0; i < nk; i++) {
        if (i + 1 < nk) { load_chunk(i + 1, (i + 1) & 1); CP_COMMIT(); cp_wait<1>(); }
        else            { cp_wait<0>(); }
        __syncthreads();

        uint32_t st = sb + (i & 1) * STAGE_B;
        #pragma unroll
        for (int kk = 0; kk < 32; kk += 16) {
            uint32_t af[4][4], bf[4][4];
            int arow = wm * 64 + (lane & 15);
            int acol = kk + ((lane >> 4) << 3);
            #pragma unroll
            for (int mi = 0; mi < 4; mi++)
                ldsm4(af[mi], st + (arow + mi * 16) * ROW_B + acol * 2);
            int brow = wn * 64 + ((lane >> 4) << 3) + (lane & 7);
            int bcol = kk + (((lane >> 3) & 1) << 3);
            #pragma unroll
            for (int g = 0; g < 4; g++)
                ldsm4(bf[g], st + bOff + (brow + g * 16) * ROW_B + bcol * 2);
            #pragma unroll
            for (int mi = 0; mi < 4; mi++)
                #pragma unroll
                for (int ni = 0; ni < 8; ni++)
                    mma_f16(acc[mi][ni], af[mi], &bf[ni >> 1][(ni & 1) * 2]);
        }
        __syncthreads();
    }

    int r0 = wm * 64 + (lane >> 2);
    int cloc0 = wn * 64 + (lane & 3) * 2;

    if (!do_scan) {
        #pragma unroll
        for (int mi = 0; mi < 4; mi++)
            #pragma unroll
            for (int ni = 0; ni < 8; ni++) {
                int rl = r0 + mi * 16, cl = n0 + cloc0 + ni * 8;
                *(float2*)(out + (m0 + rl) * (size_t)ldo + cl) =
                    make_float2(acc[mi][ni][0], acc[mi][ni][1]);
                *(float2*)(out + (m0 + rl + 8) * (size_t)ldo + cl) =
                    make_float2(acc[mi][ni][2], acc[mi][ni][3]);
            }
        return;
    }

    // ---- fused tile-local scan epilogue (GEMM1: bm=128, bn=256 -> 128 states) ----
    float2* smf  = (float2*)smem;                   // [128 rows][128 states]
    float2* segc = (float2*)(smem + 131072);        // [4][128]
    float2* Pseg = (float2*)(smem + 131072 + 4096); // [4][128]
    int sbase = nt * 128;

    #pragma unroll
    for (int mi = 0; mi < 4; mi++)
        #pragma unroll
        for (int ni = 0; ni < 8; ni++) {
            int rl = r0 + mi * 16;
            int sl = (cloc0 + ni * 8) >> 1;
            smf[rl * 128 + sl]       = make_float2(acc[mi][ni][0], acc[mi][ni][1]);
            smf[(rl + 8) * 128 + sl] = make_float2(acc[mi][ni][2], acc[mi][ni][3]);
        }
    __syncthreads();

    int seg = tid >> 6, s0 = tid & 63;
    // step1: 4 segments x 32 rows, 2 states per thread, local scans in place
    #pragma unroll
    for (int h = 0; h < 2; h++) {
        int s = s0 + h * 64;
        float2 lam = g_lam[sbase + s];
        float2 p = make_float2(0.f, 0.f);
        #pragma unroll 4
        for (int t = 0; t < 32; t++) {
            int row = seg * 32 + t;
            p = cfma(lam, p, smf[row * 128 + s]);
            smf[row * 128 + s] = p;
        }
        segc[seg * 128 + s] = p;
    }
    __syncthreads();

    // step2: exclusive prefix of segment carries + tile carry out
    if (tid < 128) {
        int s = tid;
        float2 l32 = g_lam32[sbase + s];
        float2 e = make_float2(0.f, 0.f);
        #pragma unroll
        for (int g = 0; g < 4; g++) {
            Pseg[g * 128 + s] = e;
            e = cfma(l32, e, segc[g * 128 + s]);
        }
        g_carry[(size_t)m * NSTATE + sbase + s] = e;   // m == b*NC + chunk
    }
    __syncthreads();

    // step3: apply segment prefix, emit fp16 prescan states
    #pragma unroll
    for (int h = 0; h < 2; h++) {
        int s = s0 + h * 64;
        float2 lam = g_lam[sbase + s];
        float2 mm = cmul(lam, Pseg[seg * 128 + s]);
        #pragma unroll 4
        for (int t = 0; t < 32; t++) {
            int row = seg * 32 + t;
            float2 p = smf[row * 128 + s];
            float2 v = make_float2(p.x + mm.x, p.y + mm.y);
            mm = cmul(lam, mm);
            ((__half2*)(g_Ssc + (m0 + row) * SCOLS))[sbase + s] =
                __half2(__float2half_rn(v.x), __float2half_rn(v.y));
        }
    }
}

// ---------------- cross-chunk combine (fp64, batched loads) ----------------
__global__ void combine_kernel() {
    int b = blockIdx.x;
    int n = threadIdx.x;
    double2 lL = g_lam128[n];
    double pre = 0.0, pim = 0.0;
    for (int c0 = 0; c0 < NC; c0 += 16) {
        float2 v[16];
        #pragma unroll
        for (int k = 0; k < 16; k++)
            v[k] = g_carry[((size_t)b * NC + c0 + k) * NSTATE + n];
        #pragma unroll
        for (int k = 0; k < 16; k++) {
            double nre = lL.x * pre - lL.y * pim + (double)v[k].x;
            double nim = lL.x * pim + lL.y * pre + (double)v[k].y;
            pre = nre; pim = nim;
            v[k] = make_float2((float)pre, (float)pim);
        }
        #pragma unroll
        for (int k = 0; k < 16; k++)
            g_carry[((size_t)b * NC + c0 + k) * NSTATE + n] = v[k];
    }
}

// ---------------- fixup (in place on fp16 states) ----------------
__global__ void fixup_kernel() {
    int b = blockIdx.x >> 6;
    int c = blockIdx.x & 63;
    int s = threadIdx.x;       // state 0..255
    if (c == 0) return;        // chunk 0 already final
    float2 ci = g_carry[((size_t)b * NC + c - 1) * NSTATE + s];
    float2 lam = g_lam[s];
    float2 mm = cmul(lam, ci);
    size_t rbase = (size_t)(b * T + c * CHUNK);
    __half2* p = (__half2*)(g_Ssc + rbase * SCOLS) + s;
    #pragma unroll 2
    for (int j = 0; j < CHUNK; j++) {
        __half2 hv = p[(size_t)j * (SCOLS / 2)];
        float2 v = make_float2(__half2float(hv.x) + mm.x, __half2float(hv.y) + mm.y);
        mm = cmul(lam, mm);
        p[(size_t)j * (SCOLS / 2)] = __half2(__float2half_rn(v.x), __float2half_rn(v.y));
    }
}

// ---------------- launch ----------------
extern "C" void kernel_launch(void* const* d_in, const int* in_sizes, int n_in,
                              void* d_out, int out_size) {
    const float* x         = (const float*)d_in[0];
    const float* nu_log    = (const float*)d_in[1];
    const float* theta_log = (const float*)d_in[2];
    const float* gamma_log = (const float*)d_in[3];
    const float* B_re      = (const float*)d_in[4];
    const float* B_im      = (const float*)d_in[5];
    const float* C_re      = (const float*)d_in[6];
    const float* C_im      = (const float*)d_in[7];
    const float* D         = (const float*)d_in[8];
    float* out = (float*)d_out;

    __half *xp, *sp, *w1, *wo;
    cudaGetSymbolAddress((void**)&xp, g_x);
    cudaGetSymbolAddress((void**)&sp, g_Ssc);
    cudaGetSymbolAddress((void**)&w1, g_W1);
    cudaGetSymbolAddress((void**)&wo, g_Wo);

    cudaFuncSetAttribute(gemm_kernel, cudaFuncAttributeMaxDynamicSharedMemorySize, GSMEM);

    prep_lambda_kernel<<<1, 256>>>(nu_log, theta_log);
    prep_w1_kernel<<<(SCOLS * IN_F + 255) / 256, 256>>>(gamma_log, B_re, B_im);
    prep_wout_kernel<<<(OUT_F * KOUT + 255) / 256, 256>>>(C_re, C_im, D);
    convert_x_kernel<<<(MROWS * IN_F / 4) / 256, 256>>>(x);

    // GEMM1 + fused tile-local scan: g_Ssc = chunkscan(x @ W1^T), block 128x256
    gemm_kernel<<<dim3(MROWS / 128, 2), 256, GSMEM>>>(
        xp, IN_F, 4, xp, IN_F, w1, IN_F, nullptr, 0, 4, 1, 128, 256);

    combine_kernel<<<BATCH, NSTATE>>>();
    fixup_kernel<<<BATCH * NC, NSTATE>>>();

    // GEMM2: out = S @ Wout^T, block 256x128 (K 0..511 states, 512..639 x)
    gemm_kernel<<<dim3(MROWS / 256, 1), 256, GSMEM>>>(
        sp, SCOLS, 16, xp, IN_F, wo, KOUT, out, OUT_F, 20, 0, 256, 128);
}

// round 11
// speedup vs baseline: 2.9903x; 1.1719x over previous
#include <cuda_runtime.h>
#include <cuda.h>
#include <cuda_fp16.h>
#include <math.h>
#include <stdint.h>

// ---------------- problem constants ----------------
#define BATCH   8
#define T       8192
#define IN_F    128
#define OUT_F   128
#define NSTATE  256
#define NC      64
#define CHUNK   128
#define MROWS   (BATCH * T)     // 65536
#define SCOLS   512             // 2*NSTATE interleaved: col 2n=re, 2n+1=im
#define KOUT    640             // 512 states + 128 x

// ---------------- scratch ----------------
__device__ __align__(256) __half g_x[(size_t)MROWS * IN_F];     // x fp16
__device__ __align__(256) __half g_Ssc[(size_t)MROWS * SCOLS];  // prescan -> final states fp16
__device__ __align__(256) __half g_W1[SCOLS * IN_F];
__device__ __align__(256) __half g_Wo[OUT_F * KOUT];
__device__ float2  g_carry[BATCH * NC * NSTATE];
__device__ float2  g_lam[NSTATE];
__device__ float2  g_lam32[NSTATE];
__device__ double2 g_lam128[NSTATE];

// ---------------- PTX helpers ----------------
__device__ __forceinline__ uint32_t smem_u32(const void* p) {
    uint32_t a;
    asm("{ .reg .u64 t; cvta.to.shared.u64 t, %1; cvt.u32.u64 %0, t; }" : "=r"(a) : "l"(p));
    return a;
}
__device__ __forceinline__ void ldsm4(uint32_t* r, uint32_t addr) {
    asm volatile("ldmatrix.sync.aligned.m8n8.x4.shared.b16 {%0,%1,%2,%3}, [%4];"
                 : "=r"(r[0]), "=r"(r[1]), "=r"(r[2]), "=r"(r[3]) : "r"(addr));
}
__device__ __forceinline__ void mma_f16(float* c, const uint32_t* a, const uint32_t* b) {
    asm volatile("mma.sync.aligned.m16n8k16.row.col.f32.f16.f16.f32 "
                 "{%0,%1,%2,%3}, {%4,%5,%6,%7}, {%8,%9}, {%0,%1,%2,%3};"
                 : "+f"(c[0]), "+f"(c[1]), "+f"(c[2]), "+f"(c[3])
                 : "r"(a[0]), "r"(a[1]), "r"(a[2]), "r"(a[3]), "r"(b[0]), "r"(b[1]));
}
__device__ __forceinline__ float2 cmul(float2 a, float2 b) {
    return make_float2(a.x * b.x - a.y * b.y, a.x * b.y + a.y * b.x);
}
__device__ __forceinline__ float2 cfma(float2 l, float2 s, float2 u) {  // l*s + u
    return make_float2(fmaf(l.x, s.x, fmaf(-l.y, s.y, u.x)),
                       fmaf(l.x, s.y, fmaf( l.y, s.x, u.y)));
}
#define MBARRIER_INIT(mbar, cnt) \
    asm volatile("mbarrier.init.shared.b64 [%0], %1;" :: "r"((uint32_t)(mbar)), "r"((uint32_t)(cnt)) : "memory")
#define MBARRIER_EXPECT_TX(mbar, bytes) \
    asm volatile("mbarrier.arrive.expect_tx.shared.b64 _, [%0], %1;" :: "r"((uint32_t)(mbar)), "r"((uint32_t)(bytes)) : "memory")
__device__ __forceinline__ void mbar_wait(uint32_t mbar, uint32_t parity) {
    uint32_t done;
    asm volatile("{\n\t.reg .pred p;\n\t"
                 "mbarrier.try_wait.parity.acquire.cta.shared::cta.b64 p, [%1], %2;\n\t"
                 "selp.b32 %0, 1, 0, p;\n\t}"
                 : "=r"(done) : "r"(mbar), "r"(parity) : "memory");
    if (!done) {
        asm volatile("{\n\t.reg .pred P1;\n\t"
                     "WL_%=:\n\t"
                     "mbarrier.try_wait.parity.acquire.cta.shared::cta.b64 P1, [%0], %1, 0x989680;\n\t"
                     "@P1 bra.uni WD_%=;\n\t"
                     "bra.uni WL_%=;\n\t"
                     "WD_%=:\n\t}"
                     :: "r"(mbar), "r"(parity) : "memory");
    }
}
__device__ __forceinline__ void tma2d(uint32_t smem, const CUtensorMap* tm, int x, int y, uint32_t mbar) {
    asm volatile("cp.async.bulk.tensor.2d.shared::cta.global.tile.mbarrier::complete_tx::bytes "
                 "[%0], [%1, {%2, %3}], [%4];"
                 :: "r"(smem), "l"(tm), "r"(x), "r"(y), "r"(mbar) : "memory");
}
__device__ __forceinline__ uint32_t sw128(uint32_t off) { return off ^ ((off >> 3) & 0x70); }

// ---------------- prep ----------------
__global__ void prep_lambda_kernel(const float* __restrict__ nu_log,
                                   const float* __restrict__ theta_log) {
    int n = threadIdx.x;
    double nu  = exp((double)nu_log[n]);
    double th  = exp((double)theta_log[n]);
    double mod = exp(-nu);
    g_lam[n] = make_float2((float)(mod * cos(th)), (float)(mod * sin(th)));
    double m32 = exp(-32.0 * nu);
    g_lam32[n] = make_float2((float)(m32 * cos(32.0 * th)), (float)(m32 * sin(32.0 * th)));
    double m128 = exp(-128.0 * nu);
    g_lam128[n] = make_double2(m128 * cos(128.0 * th), m128 * sin(128.0 * th));
}

__global__ void prep_w1_kernel(const float* __restrict__ gamma_log,
                               const float* __restrict__ B_re,
                               const float* __restrict__ B_im) {
    int idx = blockIdx.x * blockDim.x + threadIdx.x;
    if (idx >= SCOLS * IN_F) return;
    int r = idx / IN_F, i = idx % IN_F;
    int s = r >> 1;
    float gam = expf(gamma_log[s]);
    float v = gam * ((r & 1) ? B_im[s * IN_F + i] : B_re[s * IN_F + i]);
    g_W1[idx] = __float2half_rn(v);
}

__global__ void prep_wout_kernel(const float* __restrict__ C_re,
                                 const float* __restrict__ C_im,
                                 const float* __restrict__ D) {
    int idx = blockIdx.x * blockDim.x + threadIdx.x;
    if (idx >= OUT_F * KOUT) return;
    int o = idx / KOUT, k = idx % KOUT;
    float v;
    if (k < 512) {
        int s = k >> 1;
        v = (k & 1) ? -C_im[o * NSTATE + s] : C_re[o * NSTATE + s];
    } else {
        v = D[o * IN_F + (k - 512)];
    }
    g_Wo[idx] = __float2half_rn(v);
}

__global__ void convert_x_kernel(const float* __restrict__ x) {
    size_t i = ((size_t)blockIdx.x * blockDim.x + threadIdx.x) * 4;
    float4 v = *(const float4*)(x + i);
    __half2* p = (__half2*)(g_x + i);
    p[0] = __half2(__float2half_rn(v.x), __float2half_rn(v.y));
    p[1] = __half2(__float2half_rn(v.z), __float2half_rn(v.w));
}

// ---------------- TMA MMA GEMM ----------------
// 8 warps of 64x64. GEMM1: block 128x256; GEMM2: block 256x128.
// K-chunk = 64 cols (128B rows, SW128). Stage = (bm+bn)*128 = 49152 B.
#define STAGE_SZ 49152
#define GSMEM    (1024 + 3 * STAGE_SZ)    // 148480; epilogue needs 139264

__global__ void __launch_bounds__(256, 1) gemm_kernel(
    const __grid_constant__ CUtensorMap tA0,
    const __grid_constant__ CUtensorMap tA1,
    const __grid_constant__ CUtensorMap tB,
    float* __restrict__ out, int ldo, int nk, int nk0, int do_scan,
    int bm, int bn, int ns)
{
    extern __shared__ char smem[];
    uint32_t sb = smem_u32(smem);
    int tid = threadIdx.x, lane = tid & 31, wid = tid >> 5;
    int wmN = bm >> 6;
    int wm = wid % wmN, wn = wid / wmN;
    int m = blockIdx.x, nt = blockIdx.y;
    size_t m0 = (size_t)m * bm;
    int n0 = nt * bn;
    uint32_t aOff = sb + 1024;
    uint32_t bOff2 = (uint32_t)bm * 128;

    float acc[4][8][4];
    #pragma unroll
    for (int a = 0; a < 4; a++)
        #pragma unroll
        for (int b2 = 0; b2 < 8; b2++)
            #pragma unroll
            for (int c = 0; c < 4; c++) acc[a][b2][c] = 0.f;

    if (tid == 0) {
        for (int s = 0; s < ns; s++) MBARRIER_INIT(sb + 8 * s, 1);
    }
    __syncthreads();

    auto issue = [&](int i) {
        int s = i % ns;
        uint32_t bar = sb + 8 * s;
        uint32_t stg = aOff + s * STAGE_SZ;
        MBARRIER_EXPECT_TX(bar, STAGE_SZ);
        const CUtensorMap* ta = (i < nk0) ? &tA0 : &tA1;
        int kx = (i < nk0) ? i * 64 : (i - nk0) * 64;
        tma2d(stg, ta, kx, (int)m0, bar);
        tma2d(stg + bOff2, &tB, i * 64, n0, bar);
    };

    if (tid == 0) {
        int np = nk < ns ? nk : ns;
        for (int i = 0; i < np; i++) issue(i);
    }

    for (int i = 0; i < nk; i++) {
        int s = i % ns;
        mbar_wait(sb + 8 * s, (i / ns) & 1);

        uint32_t stA = aOff + s * STAGE_SZ;
        uint32_t stB = stA + bOff2;
        #pragma unroll
        for (int kk = 0; kk < 64; kk += 16) {
            uint32_t af[4][4], bf[4][4];
            int arow = wm * 64 + (lane & 15);
            int acol = kk + ((lane >> 4) << 3);
            #pragma unroll
            for (int mi = 0; mi < 4; mi++)
                ldsm4(af[mi], stA + sw128((arow + mi * 16) * 128 + acol * 2));
            int brow = wn * 64 + ((lane >> 4) << 3) + (lane & 7);
            int bcol = kk + (((lane >> 3) & 1) << 3);
            #pragma unroll
            for (int g = 0; g < 4; g++)
                ldsm4(bf[g], stB + sw128((brow + g * 16) * 128 + bcol * 2));
            #pragma unroll
            for (int mi = 0; mi < 4; mi++)
                #pragma unroll
                for (int ni = 0; ni < 8; ni++)
                    mma_f16(acc[mi][ni], af[mi], &bf[ni >> 1][(ni & 1) * 2]);
        }
        __syncthreads();
        if (tid == 0 && i + ns < nk) issue(i + ns);
    }

    int r0 = wm * 64 + (lane >> 2);
    int cloc0 = wn * 64 + (lane & 3) * 2;

    if (!do_scan) {
        #pragma unroll
        for (int mi = 0; mi < 4; mi++)
            #pragma unroll
            for (int ni = 0; ni < 8; ni++) {
                int rl = r0 + mi * 16, cl = n0 + cloc0 + ni * 8;
                *(float2*)(out + (m0 + rl) * (size_t)ldo + cl) =
                    make_float2(acc[mi][ni][0], acc[mi][ni][1]);
                *(float2*)(out + (m0 + rl + 8) * (size_t)ldo + cl) =
                    make_float2(acc[mi][ni][2], acc[mi][ni][3]);
            }
        return;
    }

    // ---- fused tile-local scan epilogue (GEMM1: bm=128, bn=256 -> 128 states) ----
    __syncthreads();
    float2* smf  = (float2*)smem;                   // [128 rows][128 states]
    float2* segc = (float2*)(smem + 131072);        // [4][128]
    float2* Pseg = (float2*)(smem + 131072 + 4096); // [4][128]
    int sbase = nt * 128;

    #pragma unroll
    for (int mi = 0; mi < 4; mi++)
        #pragma unroll
        for (int ni = 0; ni < 8; ni++) {
            int rl = r0 + mi * 16;
            int sl = (cloc0 + ni * 8) >> 1;
            smf[rl * 128 + sl]       = make_float2(acc[mi][ni][0], acc[mi][ni][1]);
            smf[(rl + 8) * 128 + sl] = make_float2(acc[mi][ni][2], acc[mi][ni][3]);
        }
    __syncthreads();

    int seg = tid >> 6, s0 = tid & 63;
    // step1: 4 segments x 32 rows, 2 states per thread, local scans in place
    #pragma unroll
    for (int h = 0; h < 2; h++) {
        int s = s0 + h * 64;
        float2 lam = g_lam[sbase + s];
        float2 p = make_float2(0.f, 0.f);
        #pragma unroll 4
        for (int t = 0; t < 32; t++) {
            int row = seg * 32 + t;
            p = cfma(lam, p, smf[row * 128 + s]);
            smf[row * 128 + s] = p;
        }
        segc[seg * 128 + s] = p;
    }
    __syncthreads();

    // step2: exclusive prefix of segment carries + tile carry out
    if (tid < 128) {
        int s = tid;
        float2 l32 = g_lam32[sbase + s];
        float2 e = make_float2(0.f, 0.f);
        #pragma unroll
        for (int g = 0; g < 4; g++) {
            Pseg[g * 128 + s] = e;
            e = cfma(l32, e, segc[g * 128 + s]);
        }
        g_carry[(size_t)m * NSTATE + sbase + s] = e;   // m == b*NC + chunk
    }
    __syncthreads();

    // step3: apply segment prefix, emit fp16 prescan states
    #pragma unroll
    for (int h = 0; h < 2; h++) {
        int s = s0 + h * 64;
        float2 lam = g_lam[sbase + s];
        float2 mm = cmul(lam, Pseg[seg * 128 + s]);
        #pragma unroll 4
        for (int t = 0; t < 32; t++) {
            int row = seg * 32 + t;
            float2 p = smf[row * 128 + s];
            float2 v = make_float2(p.x + mm.x, p.y + mm.y);
            mm = cmul(lam, mm);
            ((__half2*)(g_Ssc + (m0 + row) * SCOLS))[sbase + s] =
                __half2(__float2half_rn(v.x), __float2half_rn(v.y));
        }
    }
}

// ---------------- cross-chunk combine (fp64, batched loads) ----------------
__global__ void combine_kernel() {
    int b = blockIdx.x;
    int n = threadIdx.x;
    double2 lL = g_lam128[n];
    double pre = 0.0, pim = 0.0;
    for (int c0 = 0; c0 < NC; c0 += 16) {
        float2 v[16];
        #pragma unroll
        for (int k = 0; k < 16; k++)
            v[k] = g_carry[((size_t)b * NC + c0 + k) * NSTATE + n];
        #pragma unroll
        for (int k = 0; k < 16; k++) {
            double nre = lL.x * pre - lL.y * pim + (double)v[k].x;
            double nim = lL.x * pim + lL.y * pre + (double)v[k].y;
            pre = nre; pim = nim;
            v[k] = make_float2((float)pre, (float)pim);
        }
        #pragma unroll
        for (int k = 0; k < 16; k++)
            g_carry[((size_t)b * NC + c0 + k) * NSTATE + n] = v[k];
    }
}

// ---------------- fixup (in place on fp16 states) ----------------
__global__ void fixup_kernel() {
    int b = blockIdx.x >> 6;
    int c = blockIdx.x & 63;
    int s = threadIdx.x;       // state 0..255
    if (c == 0) return;        // chunk 0 already final
    float2 ci = g_carry[((size_t)b * NC + c - 1) * NSTATE + s];
    float2 lam = g_lam[s];
    float2 mm = cmul(lam, ci);
    size_t rbase = (size_t)(b * T + c * CHUNK);
    __half2* p = (__half2*)(g_Ssc + rbase * SCOLS) + s;
    #pragma unroll 2
    for (int j = 0; j < CHUNK; j++) {
        __half2 hv = p[(size_t)j * (SCOLS / 2)];
        float2 v = make_float2(__half2float(hv.x) + mm.x, __half2float(hv.y) + mm.y);
        mm = cmul(lam, mm);
        p[(size_t)j * (SCOLS / 2)] = __half2(__float2half_rn(v.x), __float2half_rn(v.y));
    }
}

// ---------------- host: tensormap encode ----------------
typedef CUresult (*PFN_encodeTiled)(
    CUtensorMap*, CUtensorMapDataType, cuuint32_t, void*,
    const cuuint64_t*, const cuuint64_t*, const cuuint32_t*, const cuuint32_t*,
    CUtensorMapInterleave, CUtensorMapSwizzle, CUtensorMapL2promotion, CUtensorMapFloatOOBfill);

static void encode2d(PFN_encodeTiled enc, CUtensorMap* tm, void* ptr,
                     uint64_t cols, uint64_t rows, uint32_t box_rows) {
    cuuint64_t dims[2] = {cols, rows};
    cuuint64_t strides[1] = {cols * 2};
    cuuint32_t box[2] = {64, box_rows};
    cuuint32_t es[2] = {1, 1};
    enc(tm, CU_TENSOR_MAP_DATA_TYPE_FLOAT16, 2, ptr, dims, strides, box, es,
        CU_TENSOR_MAP_INTERLEAVE_NONE, CU_TENSOR_MAP_SWIZZLE_128B,
        CU_TENSOR_MAP_L2_PROMOTION_L2_128B, CU_TENSOR_MAP_FLOAT_OOB_FILL_NONE);
}

// ---------------- launch ----------------
extern "C" void kernel_launch(void* const* d_in, const int* in_sizes, int n_in,
                              void* d_out, int out_size) {
    const float* x         = (const float*)d_in[0];
    const float* nu_log    = (const float*)d_in[1];
    const float* theta_log = (const float*)d_in[2];
    const float* gamma_log = (const float*)d_in[3];
    const float* B_re      = (const float*)d_in[4];
    const float* B_im      = (const float*)d_in[5];
    const float* C_re      = (const float*)d_in[6];
    const float* C_im      = (const float*)d_in[7];
    const float* D         = (const float*)d_in[8];
    float* out = (float*)d_out;

    __half *xp, *sp, *w1, *wo;
    cudaGetSymbolAddress((void**)&xp, g_x);
    cudaGetSymbolAddress((void**)&sp, g_Ssc);
    cudaGetSymbolAddress((void**)&w1, g_W1);
    cudaGetSymbolAddress((void**)&wo, g_Wo);

    // encode tensormaps (host-side, deterministic)
    static PFN_encodeTiled enc = nullptr;
    if (!enc) {
        void* fn = nullptr;
        cudaDriverEntryPointQueryResult qr;
        cudaGetDriverEntryPointByVersion("cuTensorMapEncodeTiled", &fn, 12000,
                                         cudaEnableDefault, &qr);
        enc = (PFN_encodeTiled)fn;
    }
    CUtensorMap tmX128, tmW1, tmS, tmX256, tmWo;
    encode2d(enc, &tmX128, xp, IN_F, MROWS, 128);
    encode2d(enc, &tmW1,  w1, IN_F, SCOLS, 256);
    encode2d(enc, &tmS,   sp, SCOLS, MROWS, 256);
    encode2d(enc, &tmX256, xp, IN_F, MROWS, 256);
    encode2d(enc, &tmWo,  wo, KOUT, OUT_F, 128);

    cudaFuncSetAttribute(gemm_kernel, cudaFuncAttributeMaxDynamicSharedMemorySize, GSMEM);

    prep_lambda_kernel<<<1, 256>>>(nu_log, theta_log);
    prep_w1_kernel<<<(SCOLS * IN_F + 255) / 256, 256>>>(gamma_log, B_re, B_im);
    prep_wout_kernel<<<(OUT_F * KOUT + 255) / 256, 256>>>(C_re, C_im, D);
    convert_x_kernel<<<(MROWS * IN_F / 4) / 256, 256>>>(x);

    // GEMM1 + fused tile-local scan: block 128x256, K=128 (2 chunks of 64)
    gemm_kernel<<<dim3(MROWS / 128, 2), 256, GSMEM>>>(
        tmX128, tmX128, tmW1, nullptr, 0, 2, 2, 1, 128, 256, 2);

    combine_kernel<<<BATCH, NSTATE>>>();
    fixup_kernel<<<BATCH * NC, NSTATE>>>();

    // GEMM2: block 256x128, K=640 (8 chunks from S, 2 from x), 3-stage pipeline
    gemm_kernel<<<dim3(MROWS / 256, 1), 256, GSMEM>>>(
        tmS, tmX256, tmWo, out, OUT_F, 10, 8, 0, 256, 128, 3);
}

// round 12
// speedup vs baseline: 3.1005x; 1.0368x over previous
#include <cuda_runtime.h>
#include <cuda.h>
#include <cuda_fp16.h>
#include <math.h>
#include <stdint.h>

// ---------------- problem constants ----------------
#define BATCH   8
#define T       8192
#define IN_F    128
#define OUT_F   128
#define NSTATE  256
#define NC      64
#define CHUNK   128
#define MROWS   (BATCH * T)     // 65536
#define SCOLS   512             // 2*NSTATE interleaved: col 2n=re, 2n+1=im
#define KOUT    640             // 512 states + 128 x

// ---------------- scratch ----------------
__device__ __align__(256) __half g_x[(size_t)MROWS * IN_F];     // x fp16
__device__ __align__(256) __half g_Ssc[(size_t)MROWS * SCOLS];  // prescan states fp16
__device__ __align__(256) __half g_W1[SCOLS * IN_F];
__device__ __align__(256) __half g_Wo[OUT_F * KOUT];
__device__ float2  g_carry[BATCH * NC * NSTATE];
__device__ float2  g_lam[NSTATE];
__device__ float2  g_lam32[NSTATE];
__device__ double2 g_lam128[NSTATE];

// ---------------- PTX helpers ----------------
__device__ __forceinline__ uint32_t smem_u32(const void* p) {
    uint32_t a;
    asm("{ .reg .u64 t; cvta.to.shared.u64 t, %1; cvt.u32.u64 %0, t; }" : "=r"(a) : "l"(p));
    return a;
}
__device__ __forceinline__ void ldsm4(uint32_t* r, uint32_t addr) {
    asm volatile("ldmatrix.sync.aligned.m8n8.x4.shared.b16 {%0,%1,%2,%3}, [%4];"
                 : "=r"(r[0]), "=r"(r[1]), "=r"(r[2]), "=r"(r[3]) : "r"(addr));
}
__device__ __forceinline__ void mma_f16(float* c, const uint32_t* a, const uint32_t* b) {
    asm volatile("mma.sync.aligned.m16n8k16.row.col.f32.f16.f16.f32 "
                 "{%0,%1,%2,%3}, {%4,%5,%6,%7}, {%8,%9}, {%0,%1,%2,%3};"
                 : "+f"(c[0]), "+f"(c[1]), "+f"(c[2]), "+f"(c[3])
                 : "r"(a[0]), "r"(a[1]), "r"(a[2]), "r"(a[3]), "r"(b[0]), "r"(b[1]));
}
__device__ __forceinline__ float2 cmul(float2 a, float2 b) {
    return make_float2(a.x * b.x - a.y * b.y, a.x * b.y + a.y * b.x);
}
__device__ __forceinline__ float2 cfma(float2 l, float2 s, float2 u) {  // l*s + u
    return make_float2(fmaf(l.x, s.x, fmaf(-l.y, s.y, u.x)),
                       fmaf(l.x, s.y, fmaf( l.y, s.x, u.y)));
}
#define MBARRIER_INIT(mbar, cnt) \
    asm volatile("mbarrier.init.shared.b64 [%0], %1;" :: "r"((uint32_t)(mbar)), "r"((uint32_t)(cnt)) : "memory")
#define MBARRIER_EXPECT_TX(mbar, bytes) \
    asm volatile("mbarrier.arrive.expect_tx.shared.b64 _, [%0], %1;" :: "r"((uint32_t)(mbar)), "r"((uint32_t)(bytes)) : "memory")
__device__ __forceinline__ void mbar_wait(uint32_t mbar, uint32_t parity) {
    uint32_t done;
    asm volatile("{\n\t.reg .pred p;\n\t"
                 "mbarrier.try_wait.parity.acquire.cta.shared::cta.b64 p, [%1], %2;\n\t"
                 "selp.b32 %0, 1, 0, p;\n\t}"
                 : "=r"(done) : "r"(mbar), "r"(parity) : "memory");
    if (!done) {
        asm volatile("{\n\t.reg .pred P1;\n\t"
                     "WL_%=:\n\t"
                     "mbarrier.try_wait.parity.acquire.cta.shared::cta.b64 P1, [%0], %1, 0x989680;\n\t"
                     "@P1 bra.uni WD_%=;\n\t"
                     "bra.uni WL_%=;\n\t"
                     "WD_%=:\n\t}"
                     :: "r"(mbar), "r"(parity) : "memory");
    }
}
__device__ __forceinline__ void tma2d(uint32_t smem, const CUtensorMap* tm, int x, int y, uint32_t mbar) {
    asm volatile("cp.async.bulk.tensor.2d.shared::cta.global.tile.mbarrier::complete_tx::bytes "
                 "[%0], [%1, {%2, %3}], [%4];"
                 :: "r"(smem), "l"(tm), "r"(x), "r"(y), "r"(mbar) : "memory");
}
__device__ __forceinline__ uint32_t sw128(uint32_t off) { return off ^ ((off >> 3) & 0x70); }

// ---------------- prep ----------------
__global__ void prep_lambda_kernel(const float* __restrict__ nu_log,
                                   const float* __restrict__ theta_log) {
    int n = threadIdx.x;
    double nu  = exp((double)nu_log[n]);
    double th  = exp((double)theta_log[n]);
    double mod = exp(-nu);
    g_lam[n] = make_float2((float)(mod * cos(th)), (float)(mod * sin(th)));
    double m32 = exp(-32.0 * nu);
    g_lam32[n] = make_float2((float)(m32 * cos(32.0 * th)), (float)(m32 * sin(32.0 * th)));
    double m128 = exp(-128.0 * nu);
    g_lam128[n] = make_double2(m128 * cos(128.0 * th), m128 * sin(128.0 * th));
}

__global__ void prep_w1_kernel(const float* __restrict__ gamma_log,
                               const float* __restrict__ B_re,
                               const float* __restrict__ B_im) {
    int idx = blockIdx.x * blockDim.x + threadIdx.x;
    if (idx >= SCOLS * IN_F) return;
    int r = idx / IN_F, i = idx % IN_F;
    int s = r >> 1;
    float gam = expf(gamma_log[s]);
    float v = gam * ((r & 1) ? B_im[s * IN_F + i] : B_re[s * IN_F + i]);
    g_W1[idx] = __float2half_rn(v);
}

__global__ void prep_wout_kernel(const float* __restrict__ C_re,
                                 const float* __restrict__ C_im,
                                 const float* __restrict__ D) {
    int idx = blockIdx.x * blockDim.x + threadIdx.x;
    if (idx >= OUT_F * KOUT) return;
    int o = idx / KOUT, k = idx % KOUT;
    float v;
    if (k < 512) {
        int s = k >> 1;
        v = (k & 1) ? -C_im[o * NSTATE + s] : C_re[o * NSTATE + s];
    } else {
        v = D[o * IN_F + (k - 512)];
    }
    g_Wo[idx] = __float2half_rn(v);
}

__global__ void convert_x_kernel(const float* __restrict__ x) {
    size_t i = ((size_t)blockIdx.x * blockDim.x + threadIdx.x) * 4;
    float4 v = *(const float4*)(x + i);
    __half2* p = (__half2*)(g_x + i);
    p[0] = __half2(__float2half_rn(v.x), __float2half_rn(v.y));
    p[1] = __half2(__float2half_rn(v.z), __float2half_rn(v.w));
}

// ---------------- TMA MMA GEMM ----------------
// 8 warps of 64x64. GEMM1: block 128x256 (+fused scan); GEMM2: block 256x128 (+fused fixup).
// K-chunk = 64 cols (128B rows, SW128). Stage = (bm+bn)*128 = 49152 B.
#define STAGE_SZ 49152
#define GSMEM    (1024 + 4 * STAGE_SZ)    // 197632; epilogue needs 139264

__global__ void __launch_bounds__(256, 1) gemm_kernel(
    const __grid_constant__ CUtensorMap tA0,
    const __grid_constant__ CUtensorMap tA1,
    const __grid_constant__ CUtensorMap tB,
    float* __restrict__ out, int ldo, int nk, int nk0, int do_scan, int do_fix,
    int bm, int bn, int ns)
{
    extern __shared__ char smem[];
    uint32_t sb = smem_u32(smem);
    int tid = threadIdx.x, lane = tid & 31, wid = tid >> 5;
    int wmN = bm >> 6;
    int wm = wid % wmN, wn = wid / wmN;
    int m = blockIdx.x, nt = blockIdx.y;
    size_t m0 = (size_t)m * bm;
    int n0 = nt * bn;
    uint32_t aOff = sb + 1024;
    uint32_t bOff2 = (uint32_t)bm * 128;
    // fixup context (GEMM2): batch + first chunk of this block's rows
    int fb = (int)(m0 >> 13);            // m0 / T
    int fch0 = ((int)(m0 & 8191)) >> 7;  // (m0 % T) / CHUNK

    float acc[4][8][4];
    #pragma unroll
    for (int a = 0; a < 4; a++)
        #pragma unroll
        for (int b2 = 0; b2 < 8; b2++)
            #pragma unroll
            for (int c = 0; c < 4; c++) acc[a][b2][c] = 0.f;

    if (tid == 0) {
        for (int s = 0; s < ns; s++) MBARRIER_INIT(sb + 8 * s, 1);
    }
    __syncthreads();

    auto issue = [&](int i) {
        int s = i % ns;
        uint32_t bar = sb + 8 * s;
        uint32_t stg = aOff + s * STAGE_SZ;
        MBARRIER_EXPECT_TX(bar, STAGE_SZ);
        const CUtensorMap* ta = (i < nk0) ? &tA0 : &tA1;
        int kx = (i < nk0) ? i * 64 : (i - nk0) * 64;
        tma2d(stg, ta, kx, (int)m0, bar);
        tma2d(stg + bOff2, &tB, i * 64, n0, bar);
    };

    if (tid == 0) {
        int np = nk < ns ? nk : ns;
        for (int i = 0; i < np; i++) issue(i);
    }

    for (int i = 0; i < nk; i++) {
        int s = i % ns;
        mbar_wait(sb + 8 * s, (i / ns) & 1);

        uint32_t stA = aOff + s * STAGE_SZ;
        uint32_t stB = stA + bOff2;

        // ---- fused fixup (GEMM2, state chunks only): A[r,s] += lam^(jr+1)*carry, in smem ----
        if (do_fix && i < nk0) {
            int sl = tid & 31;             // state lane in this chunk
            int rseg = tid >> 5;           // 0..7 -> rows rseg*32..+31
            int gs = i * 32 + sl;          // global state
            int gch = fch0 + (rseg >> 2);  // global chunk of these rows
            if (gch > 0) {
                float2 ci = g_carry[((size_t)fb * NC + gch - 1) * NSTATE + gs];
                float2 lam = g_lam[gs];
                float2 l32 = g_lam32[gs];
                float2 mm = cmul(lam, ci);
                int q = rseg & 3;
                for (int k = 0; k < q; k++) mm = cmul(l32, mm);
                char* base = smem + (stA - sb);
                int r0 = rseg * 32;
                #pragma unroll 4
                for (int t = 0; t < 32; t++) {
                    uint32_t off = sw128((uint32_t)(r0 + t) * 128 + sl * 4);
                    __half2* ph = (__half2*)(base + off);
                    __half2 hv = *ph;
                    float2 v = make_float2(__half2float(hv.x) + mm.x,
                                           __half2float(hv.y) + mm.y);
                    mm = cmul(lam, mm);
                    *ph = __half2(__float2half_rn(v.x), __float2half_rn(v.y));
                }
            }
            __syncthreads();
        }

        #pragma unroll
        for (int kk = 0; kk < 64; kk += 16) {
            uint32_t af[4][4], bf[4][4];
            int arow = wm * 64 + (lane & 15);
            int acol = kk + ((lane >> 4) << 3);
            #pragma unroll
            for (int mi = 0; mi < 4; mi++)
                ldsm4(af[mi], stA + sw128((arow + mi * 16) * 128 + acol * 2));
            int brow = wn * 64 + ((lane >> 4) << 3) + (lane & 7);
            int bcol = kk + (((lane >> 3) & 1) << 3);
            #pragma unroll
            for (int g = 0; g < 4; g++)
                ldsm4(bf[g], stB + sw128((brow + g * 16) * 128 + bcol * 2));
            #pragma unroll
            for (int mi = 0; mi < 4; mi++)
                #pragma unroll
                for (int ni = 0; ni < 8; ni++)
                    mma_f16(acc[mi][ni], af[mi], &bf[ni >> 1][(ni & 1) * 2]);
        }
        __syncthreads();
        if (tid == 0 && i + ns < nk) issue(i + ns);
    }

    int r0 = wm * 64 + (lane >> 2);
    int cloc0 = wn * 64 + (lane & 3) * 2;

    if (!do_scan) {
        #pragma unroll
        for (int mi = 0; mi < 4; mi++)
            #pragma unroll
            for (int ni = 0; ni < 8; ni++) {
                int rl = r0 + mi * 16, cl = n0 + cloc0 + ni * 8;
                *(float2*)(out + (m0 + rl) * (size_t)ldo + cl) =
                    make_float2(acc[mi][ni][0], acc[mi][ni][1]);
                *(float2*)(out + (m0 + rl + 8) * (size_t)ldo + cl) =
                    make_float2(acc[mi][ni][2], acc[mi][ni][3]);
            }
        return;
    }

    // ---- fused tile-local scan epilogue (GEMM1: bm=128, bn=256 -> 128 states) ----
    __syncthreads();
    float2* smf  = (float2*)smem;                   // [128 rows][128 states]
    float2* segc = (float2*)(smem + 131072);        // [4][128]
    float2* Pseg = (float2*)(smem + 131072 + 4096); // [4][128]
    int sbase = nt * 128;

    #pragma unroll
    for (int mi = 0; mi < 4; mi++)
        #pragma unroll
        for (int ni = 0; ni < 8; ni++) {
            int rl = r0 + mi * 16;
            int sl = (cloc0 + ni * 8) >> 1;
            smf[rl * 128 + sl]       = make_float2(acc[mi][ni][0], acc[mi][ni][1]);
            smf[(rl + 8) * 128 + sl] = make_float2(acc[mi][ni][2], acc[mi][ni][3]);
        }
    __syncthreads();

    int seg = tid >> 6, s0 = tid & 63;
    // step1: 4 segments x 32 rows, 2 states per thread, local scans in place
    #pragma unroll
    for (int h = 0; h < 2; h++) {
        int s = s0 + h * 64;
        float2 lam = g_lam[sbase + s];
        float2 p = make_float2(0.f, 0.f);
        #pragma unroll 4
        for (int t = 0; t < 32; t++) {
            int row = seg * 32 + t;
            p = cfma(lam, p, smf[row * 128 + s]);
            smf[row * 128 + s] = p;
        }
        segc[seg * 128 + s] = p;
    }
    __syncthreads();

    // step2: exclusive prefix of segment carries + tile carry out
    if (tid < 128) {
        int s = tid;
        float2 l32 = g_lam32[sbase + s];
        float2 e = make_float2(0.f, 0.f);
        #pragma unroll
        for (int g = 0; g < 4; g++) {
            Pseg[g * 128 + s] = e;
            e = cfma(l32, e, segc[g * 128 + s]);
        }
        g_carry[(size_t)m * NSTATE + sbase + s] = e;   // m == b*NC + chunk
    }
    __syncthreads();

    // step3: apply segment prefix, emit fp16 prescan states
    #pragma unroll
    for (int h = 0; h < 2; h++) {
        int s = s0 + h * 64;
        float2 lam = g_lam[sbase + s];
        float2 mm = cmul(lam, Pseg[seg * 128 + s]);
        #pragma unroll 4
        for (int t = 0; t < 32; t++) {
            int row = seg * 32 + t;
            float2 p = smf[row * 128 + s];
            float2 v = make_float2(p.x + mm.x, p.y + mm.y);
            mm = cmul(lam, mm);
            ((__half2*)(g_Ssc + (m0 + row) * SCOLS))[sbase + s] =
                __half2(__float2half_rn(v.x), __float2half_rn(v.y));
        }
    }
}

// ---------------- cross-chunk combine (fp64, batched loads) ----------------
__global__ void combine_kernel() {
    int b = blockIdx.x;
    int n = threadIdx.x;
    double2 lL = g_lam128[n];
    double pre = 0.0, pim = 0.0;
    for (int c0 = 0; c0 < NC; c0 += 16) {
        float2 v[16];
        #pragma unroll
        for (int k = 0; k < 16; k++)
            v[k] = g_carry[((size_t)b * NC + c0 + k) * NSTATE + n];
        #pragma unroll
        for (int k = 0; k < 16; k++) {
            double nre = lL.x * pre - lL.y * pim + (double)v[k].x;
            double nim = lL.x * pim + lL.y * pre + (double)v[k].y;
            pre = nre; pim = nim;
            v[k] = make_float2((float)pre, (float)pim);
        }
        #pragma unroll
        for (int k = 0; k < 16; k++)
            g_carry[((size_t)b * NC + c0 + k) * NSTATE + n] = v[k];
    }
}

// ---------------- host: tensormap encode ----------------
typedef CUresult (*PFN_encodeTiled)(
    CUtensorMap*, CUtensorMapDataType, cuuint32_t, void*,
    const cuuint64_t*, const cuuint64_t*, const cuuint32_t*, const cuuint32_t*,
    CUtensorMapInterleave, CUtensorMapSwizzle, CUtensorMapL2promotion, CUtensorMapFloatOOBfill);

static void encode2d(PFN_encodeTiled enc, CUtensorMap* tm, void* ptr,
                     uint64_t cols, uint64_t rows, uint32_t box_rows) {
    cuuint64_t dims[2] = {cols, rows};
    cuuint64_t strides[1] = {cols * 2};
    cuuint32_t box[2] = {64, box_rows};
    cuuint32_t es[2] = {1, 1};
    enc(tm, CU_TENSOR_MAP_DATA_TYPE_FLOAT16, 2, ptr, dims, strides, box, es,
        CU_TENSOR_MAP_INTERLEAVE_NONE, CU_TENSOR_MAP_SWIZZLE_128B,
        CU_TENSOR_MAP_L2_PROMOTION_L2_128B, CU_TENSOR_MAP_FLOAT_OOB_FILL_NONE);
}

// ---------------- launch ----------------
extern "C" void kernel_launch(void* const* d_in, const int* in_sizes, int n_in,
                              void* d_out, int out_size) {
    const float* x         = (const float*)d_in[0];
    const float* nu_log    = (const float*)d_in[1];
    const float* theta_log = (const float*)d_in[2];
    const float* gamma_log = (const float*)d_in[3];
    const float* B_re      = (const float*)d_in[4];
    const float* B_im      = (const float*)d_in[5];
    const float* C_re      = (const float*)d_in[6];
    const float* C_im      = (const float*)d_in[7];
    const float* D         = (const float*)d_in[8];
    float* out = (float*)d_out;

    __half *xp, *sp, *w1, *wo;
    cudaGetSymbolAddress((void**)&xp, g_x);
    cudaGetSymbolAddress((void**)&sp, g_Ssc);
    cudaGetSymbolAddress((void**)&w1, g_W1);
    cudaGetSymbolAddress((void**)&wo, g_Wo);

    // encode tensormaps (host-side, deterministic)
    static PFN_encodeTiled enc = nullptr;
    if (!enc) {
        void* fn = nullptr;
        cudaDriverEntryPointQueryResult qr;
        cudaGetDriverEntryPointByVersion("cuTensorMapEncodeTiled", &fn, 12000,
                                         cudaEnableDefault, &qr);
        enc = (PFN_encodeTiled)fn;
    }
    CUtensorMap tmX128, tmW1, tmS, tmX256, tmWo;
    encode2d(enc, &tmX128, xp, IN_F, MROWS, 128);
    encode2d(enc, &tmW1,  w1, IN_F, SCOLS, 256);
    encode2d(enc, &tmS,   sp, SCOLS, MROWS, 256);
    encode2d(enc, &tmX256, xp, IN_F, MROWS, 256);
    encode2d(enc, &tmWo,  wo, KOUT, OUT_F, 128);

    cudaFuncSetAttribute(gemm_kernel, cudaFuncAttributeMaxDynamicSharedMemorySize, GSMEM);

    prep_lambda_kernel<<<1, 256>>>(nu_log, theta_log);
    prep_w1_kernel<<<(SCOLS * IN_F + 255) / 256, 256>>>(gamma_log, B_re, B_im);
    prep_wout_kernel<<<(OUT_F * KOUT + 255) / 256, 256>>>(C_re, C_im, D);
    convert_x_kernel<<<(MROWS * IN_F / 4) / 256, 256>>>(x);

    // GEMM1 + fused tile-local scan: block 128x256, K=128 (2 chunks of 64)
    gemm_kernel<<<dim3(MROWS / 128, 2), 256, GSMEM>>>(
        tmX128, tmX128, tmW1, nullptr, 0, 2, 2, 1, 0, 128, 256, 2);

    combine_kernel<<<BATCH, NSTATE>>>();

    // GEMM2 + fused fixup: block 256x128, K=640 (8 state chunks + 2 x chunks), 4-stage
    gemm_kernel<<<dim3(MROWS / 256, 1), 256, GSMEM>>>(
        tmS, tmX256, tmWo, out, OUT_F, 10, 8, 0, 1, 256, 128, 4);
}

// round 13
// speedup vs baseline: 3.5877x; 1.1571x over previous
#include <cuda_runtime.h>
#include <cuda.h>
#include <cuda_fp16.h>
#include <math.h>
#include <stdint.h>

// ---------------- problem constants ----------------
#define BATCH   8
#define T       8192
#define IN_F    128
#define OUT_F   128
#define NSTATE  256
#define NC      64
#define CHUNK   128
#define MROWS   (BATCH * T)     // 65536
#define SCOLS   512             // 2*NSTATE interleaved: col 2n=re, 2n+1=im
#define KOUT    640             // 512 states + 128 x

// ---------------- scratch ----------------
__device__ __align__(256) __half g_x[(size_t)MROWS * IN_F];     // x fp16
__device__ __align__(256) __half g_Ssc[(size_t)MROWS * SCOLS];  // prescan states fp16
__device__ __align__(256) __half g_W1[SCOLS * IN_F];
__device__ __align__(256) __half g_Wo[OUT_F * KOUT];
__device__ float2  g_carry[BATCH * NC * NSTATE];
__device__ float2  g_lam[NSTATE];
__device__ float2  g_lam16[NSTATE];
__device__ float2  g_lam32[NSTATE];
__device__ double2 g_lam128[NSTATE];

// ---------------- PTX helpers ----------------
__device__ __forceinline__ uint32_t smem_u32(const void* p) {
    uint32_t a;
    asm("{ .reg .u64 t; cvta.to.shared.u64 t, %1; cvt.u32.u64 %0, t; }" : "=r"(a) : "l"(p));
    return a;
}
__device__ __forceinline__ void ldsm4(uint32_t* r, uint32_t addr) {
    asm volatile("ldmatrix.sync.aligned.m8n8.x4.shared.b16 {%0,%1,%2,%3}, [%4];"
                 : "=r"(r[0]), "=r"(r[1]), "=r"(r[2]), "=r"(r[3]) : "r"(addr));
}
__device__ __forceinline__ void mma_f16(float* c, const uint32_t* a, const uint32_t* b) {
    asm volatile("mma.sync.aligned.m16n8k16.row.col.f32.f16.f16.f32 "
                 "{%0,%1,%2,%3}, {%4,%5,%6,%7}, {%8,%9}, {%0,%1,%2,%3};"
                 : "+f"(c[0]), "+f"(c[1]), "+f"(c[2]), "+f"(c[3])
                 : "r"(a[0]), "r"(a[1]), "r"(a[2]), "r"(a[3]), "r"(b[0]), "r"(b[1]));
}
__device__ __forceinline__ float2 cmul(float2 a, float2 b) {
    return make_float2(a.x * b.x - a.y * b.y, a.x * b.y + a.y * b.x);
}
__device__ __forceinline__ float2 cfma(float2 l, float2 s, float2 u) {  // l*s + u
    return make_float2(fmaf(l.x, s.x, fmaf(-l.y, s.y, u.x)),
                       fmaf(l.x, s.y, fmaf( l.y, s.x, u.y)));
}
#define MBARRIER_INIT(mbar, cnt) \
    asm volatile("mbarrier.init.shared.b64 [%0], %1;" :: "r"((uint32_t)(mbar)), "r"((uint32_t)(cnt)) : "memory")
#define MBARRIER_EXPECT_TX(mbar, bytes) \
    asm volatile("mbarrier.arrive.expect_tx.shared.b64 _, [%0], %1;" :: "r"((uint32_t)(mbar)), "r"((uint32_t)(bytes)) : "memory")
__device__ __forceinline__ void mbar_wait(uint32_t mbar, uint32_t parity) {
    uint32_t done;
    asm volatile("{\n\t.reg .pred p;\n\t"
                 "mbarrier.try_wait.parity.acquire.cta.shared::cta.b64 p, [%1], %2;\n\t"
                 "selp.b32 %0, 1, 0, p;\n\t}"
                 : "=r"(done) : "r"(mbar), "r"(parity) : "memory");
    if (!done) {
        asm volatile("{\n\t.reg .pred P1;\n\t"
                     "WL_%=:\n\t"
                     "mbarrier.try_wait.parity.acquire.cta.shared::cta.b64 P1, [%0], %1, 0x989680;\n\t"
                     "@P1 bra.uni WD_%=;\n\t"
                     "bra.uni WL_%=;\n\t"
                     "WD_%=:\n\t}"
                     :: "r"(mbar), "r"(parity) : "memory");
    }
}
__device__ __forceinline__ void tma2d(uint32_t smem, const CUtensorMap* tm, int x, int y, uint32_t mbar) {
    asm volatile("cp.async.bulk.tensor.2d.shared::cta.global.tile.mbarrier::complete_tx::bytes "
                 "[%0], [%1, {%2, %3}], [%4];"
                 :: "r"(smem), "l"(tm), "r"(x), "r"(y), "r"(mbar) : "memory");
}
__device__ __forceinline__ uint32_t sw128(uint32_t off) { return off ^ ((off >> 3) & 0x70); }

// ---------------- prep ----------------
__global__ void prep_lambda_kernel(const float* __restrict__ nu_log,
                                   const float* __restrict__ theta_log) {
    int n = threadIdx.x;
    double nu  = exp((double)nu_log[n]);
    double th  = exp((double)theta_log[n]);
    double mod = exp(-nu);
    g_lam[n] = make_float2((float)(mod * cos(th)), (float)(mod * sin(th)));
    double m16 = exp(-16.0 * nu);
    g_lam16[n] = make_float2((float)(m16 * cos(16.0 * th)), (float)(m16 * sin(16.0 * th)));
    double m32 = exp(-32.0 * nu);
    g_lam32[n] = make_float2((float)(m32 * cos(32.0 * th)), (float)(m32 * sin(32.0 * th)));
    double m128 = exp(-128.0 * nu);
    g_lam128[n] = make_double2(m128 * cos(128.0 * th), m128 * sin(128.0 * th));
}

__global__ void prep_w1_kernel(const float* __restrict__ gamma_log,
                               const float* __restrict__ B_re,
                               const float* __restrict__ B_im) {
    int idx = blockIdx.x * blockDim.x + threadIdx.x;
    if (idx >= SCOLS * IN_F) return;
    int r = idx / IN_F, i = idx % IN_F;
    int s = r >> 1;
    float gam = expf(gamma_log[s]);
    float v = gam * ((r & 1) ? B_im[s * IN_F + i] : B_re[s * IN_F + i]);
    g_W1[idx] = __float2half_rn(v);
}

__global__ void prep_wout_kernel(const float* __restrict__ C_re,
                                 const float* __restrict__ C_im,
                                 const float* __restrict__ D) {
    int idx = blockIdx.x * blockDim.x + threadIdx.x;
    if (idx >= OUT_F * KOUT) return;
    int o = idx / KOUT, k = idx % KOUT;
    float v;
    if (k < 512) {
        int s = k >> 1;
        v = (k & 1) ? -C_im[o * NSTATE + s] : C_re[o * NSTATE + s];
    } else {
        v = D[o * IN_F + (k - 512)];
    }
    g_Wo[idx] = __float2half_rn(v);
}

__global__ void convert_x_kernel(const float* __restrict__ x) {
    size_t i = ((size_t)blockIdx.x * blockDim.x + threadIdx.x) * 4;
    float4 v = *(const float4*)(x + i);
    __half2* p = (__half2*)(g_x + i);
    p[0] = __half2(__float2half_rn(v.x), __float2half_rn(v.y));
    p[1] = __half2(__float2half_rn(v.z), __float2half_rn(v.w));
}

// ---------------- TMA MMA GEMM ----------------
// Block 128x128, 8 warps of 64x32, K-chunk 64 (128B rows, SW128), ns=3, occ 2.
#define STAGE_SZ 32768
#define GSMEM    (1024 + 3 * STAGE_SZ)    // 99328 < 113664 -> 2 blocks/SM
#define BOFF2    16384                    // A tile = 128 rows * 128B

__global__ void __launch_bounds__(256, 2) gemm_kernel(
    const __grid_constant__ CUtensorMap tA0,
    const __grid_constant__ CUtensorMap tA1,
    const __grid_constant__ CUtensorMap tB,
    float* __restrict__ out, int ldo, int nk, int nk0, int do_scan, int do_fix,
    int ns)
{
    extern __shared__ char smem[];
    uint32_t sb = smem_u32(smem);
    int tid = threadIdx.x, lane = tid & 31, wid = tid >> 5;
    int wm = wid & 1, wn = wid >> 1;         // 2x4 warp grid, 64x32 tiles
    int m = blockIdx.x, nt = blockIdx.y;
    size_t m0 = (size_t)m * 128;
    int n0 = nt * 128;
    uint32_t aOff = sb + 1024;
    // fixup context (GEMM2): each block's 128 rows = exactly one scan chunk
    int fb = m >> 6;                          // m0 / T
    int fch = m & 63;                         // chunk index within batch

    float acc[4][4][4];
    #pragma unroll
    for (int a = 0; a < 4; a++)
        #pragma unroll
        for (int b2 = 0; b2 < 4; b2++)
            #pragma unroll
            for (int c = 0; c < 4; c++) acc[a][b2][c] = 0.f;

    if (tid == 0) {
        for (int s = 0; s < ns; s++) MBARRIER_INIT(sb + 8 * s, 1);
    }
    __syncthreads();

    auto issue = [&](int i) {
        int s = i % ns;
        uint32_t bar = sb + 8 * s;
        uint32_t stg = aOff + s * STAGE_SZ;
        MBARRIER_EXPECT_TX(bar, STAGE_SZ);
        const CUtensorMap* ta = (i < nk0) ? &tA0 : &tA1;
        int kx = (i < nk0) ? i * 64 : (i - nk0) * 64;
        tma2d(stg, ta, kx, (int)m0, bar);
        tma2d(stg + BOFF2, &tB, i * 64, n0, bar);
    };

    if (tid == 0) {
        int np = nk < ns ? nk : ns;
        for (int i = 0; i < np; i++) issue(i);
    }

    for (int i = 0; i < nk; i++) {
        int s = i % ns;
        mbar_wait(sb + 8 * s, (i / ns) & 1);

        uint32_t stA = aOff + s * STAGE_SZ;
        uint32_t stB = stA + BOFF2;

        // ---- fused fixup (GEMM2, state chunks): A[r,s] += lam^(r+1)*carry, in smem ----
        if (do_fix && i < nk0 && fch > 0) {
            int sl = tid & 31;                 // state lane in this 32-state chunk
            int rseg = tid >> 5;               // 0..7 -> rows rseg*16..+15
            int gs = i * 32 + sl;              // global state
            float2 ci = g_carry[((size_t)fb * NC + fch - 1) * NSTATE + gs];
            float2 lam = g_lam[gs];
            float2 l16 = g_lam16[gs];
            float2 mm = cmul(lam, ci);
            for (int k = 0; k < rseg; k++) mm = cmul(l16, mm);
            char* base = smem + (stA - sb);
            int rr0 = rseg * 16;
            #pragma unroll 4
            for (int t = 0; t < 16; t++) {
                uint32_t off = sw128((uint32_t)(rr0 + t) * 128 + sl * 4);
                __half2* ph = (__half2*)(base + off);
                __half2 hv = *ph;
                float2 v = make_float2(__half2float(hv.x) + mm.x,
                                       __half2float(hv.y) + mm.y);
                mm = cmul(lam, mm);
                *ph = __half2(__float2half_rn(v.x), __float2half_rn(v.y));
            }
            __syncthreads();
        }

        #pragma unroll
        for (int kk = 0; kk < 64; kk += 16) {
            uint32_t af[4][4], bf[2][4];
            int arow = wm * 64 + (lane & 15);
            int acol = kk + ((lane >> 4) << 3);
            #pragma unroll
            for (int mi = 0; mi < 4; mi++)
                ldsm4(af[mi], stA + sw128((arow + mi * 16) * 128 + acol * 2));
            int brow = wn * 32 + ((lane >> 4) << 3) + (lane & 7);
            int bcol = kk + (((lane >> 3) & 1) << 3);
            #pragma unroll
            for (int g = 0; g < 2; g++)
                ldsm4(bf[g], stB + sw128((brow + g * 16) * 128 + bcol * 2));
            #pragma unroll
            for (int mi = 0; mi < 4; mi++)
                #pragma unroll
                for (int ni = 0; ni < 4; ni++)
                    mma_f16(acc[mi][ni], af[mi], &bf[ni >> 1][(ni & 1) * 2]);
        }
        __syncthreads();
        if (tid == 0 && i + ns < nk) issue(i + ns);
    }

    int r0 = wm * 64 + (lane >> 2);
    int cloc0 = wn * 32 + (lane & 3) * 2;

    if (!do_scan) {
        #pragma unroll
        for (int mi = 0; mi < 4; mi++)
            #pragma unroll
            for (int ni = 0; ni < 4; ni++) {
                int rl = r0 + mi * 16, cl = n0 + cloc0 + ni * 8;
                *(float2*)(out + (m0 + rl) * (size_t)ldo + cl) =
                    make_float2(acc[mi][ni][0], acc[mi][ni][1]);
                *(float2*)(out + (m0 + rl + 8) * (size_t)ldo + cl) =
                    make_float2(acc[mi][ni][2], acc[mi][ni][3]);
            }
        return;
    }

    // ---- fused tile-local scan epilogue (GEMM1: 64 states per block) ----
    __syncthreads();
    float2* smf  = (float2*)smem;                  // [128 rows][64 states]
    float2* segc = (float2*)(smem + 65536);        // [4][64]
    float2* Pseg = (float2*)(smem + 65536 + 2048); // [4][64]
    int sbase = nt * 64;

    #pragma unroll
    for (int mi = 0; mi < 4; mi++)
        #pragma unroll
        for (int ni = 0; ni < 4; ni++) {
            int rl = r0 + mi * 16;
            int sl = (cloc0 + ni * 8) >> 1;
            smf[rl * 64 + sl]       = make_float2(acc[mi][ni][0], acc[mi][ni][1]);
            smf[(rl + 8) * 64 + sl] = make_float2(acc[mi][ni][2], acc[mi][ni][3]);
        }
    __syncthreads();

    int seg = tid >> 6, s0 = tid & 63;
    {   // step1: 4 segments x 32 rows, local scans in place
        float2 lam = g_lam[sbase + s0];
        float2 p = make_float2(0.f, 0.f);
        #pragma unroll 4
        for (int t = 0; t < 32; t++) {
            int row = seg * 32 + t;
            p = cfma(lam, p, smf[row * 64 + s0]);
            smf[row * 64 + s0] = p;
        }
        segc[seg * 64 + s0] = p;
    }
    __syncthreads();

    // step2: exclusive prefix of segment carries + tile carry out
    if (tid < 64) {
        float2 l32 = g_lam32[sbase + s0];
        float2 e = make_float2(0.f, 0.f);
        #pragma unroll
        for (int g = 0; g < 4; g++) {
            Pseg[g * 64 + s0] = e;
            e = cfma(l32, e, segc[g * 64 + s0]);
        }
        g_carry[(size_t)m * NSTATE + sbase + s0] = e;   // m == b*NC + chunk
    }
    __syncthreads();

    // step3: apply segment prefix, emit fp16 prescan states
    {
        float2 lam = g_lam[sbase + s0];
        float2 mm = cmul(lam, Pseg[seg * 64 + s0]);
        #pragma unroll 4
        for (int t = 0; t < 32; t++) {
            int row = seg * 32 + t;
            float2 p = smf[row * 64 + s0];
            float2 v = make_float2(p.x + mm.x, p.y + mm.y);
            mm = cmul(lam, mm);
            ((__half2*)(g_Ssc + (m0 + row) * SCOLS))[sbase + s0] =
                __half2(__float2half_rn(v.x), __float2half_rn(v.y));
        }
    }
}

// ---------------- cross-chunk combine (fp64, batched loads) ----------------
__global__ void combine_kernel() {
    int b = blockIdx.x;
    int n = threadIdx.x;
    double2 lL = g_lam128[n];
    double pre = 0.0, pim = 0.0;
    for (int c0 = 0; c0 < NC; c0 += 16) {
        float2 v[16];
        #pragma unroll
        for (int k = 0; k < 16; k++)
            v[k] = g_carry[((size_t)b * NC + c0 + k) * NSTATE + n];
        #pragma unroll
        for (int k = 0; k < 16; k++) {
            double nre = lL.x * pre - lL.y * pim + (double)v[k].x;
            double nim = lL.x * pim + lL.y * pre + (double)v[k].y;
            pre = nre; pim = nim;
            v[k] = make_float2((float)pre, (float)pim);
        }
        #pragma unroll
        for (int k = 0; k < 16; k++)
            g_carry[((size_t)b * NC + c0 + k) * NSTATE + n] = v[k];
    }
}

// ---------------- host: tensormap encode ----------------
typedef CUresult (*PFN_encodeTiled)(
    CUtensorMap*, CUtensorMapDataType, cuuint32_t, void*,
    const cuuint64_t*, const cuuint64_t*, const cuuint32_t*, const cuuint32_t*,
    CUtensorMapInterleave, CUtensorMapSwizzle, CUtensorMapL2promotion, CUtensorMapFloatOOBfill);

static void encode2d(PFN_encodeTiled enc, CUtensorMap* tm, void* ptr,
                     uint64_t cols, uint64_t rows, uint32_t box_rows) {
    cuuint64_t dims[2] = {cols, rows};
    cuuint64_t strides[1] = {cols * 2};
    cuuint32_t box[2] = {64, box_rows};
    cuuint32_t es[2] = {1, 1};
    enc(tm, CU_TENSOR_MAP_DATA_TYPE_FLOAT16, 2, ptr, dims, strides, box, es,
        CU_TENSOR_MAP_INTERLEAVE_NONE, CU_TENSOR_MAP_SWIZZLE_128B,
        CU_TENSOR_MAP_L2_PROMOTION_L2_128B, CU_TENSOR_MAP_FLOAT_OOB_FILL_NONE);
}

// ---------------- launch ----------------
extern "C" void kernel_launch(void* const* d_in, const int* in_sizes, int n_in,
                              void* d_out, int out_size) {
    const float* x         = (const float*)d_in[0];
    const float* nu_log    = (const float*)d_in[1];
    const float* theta_log = (const float*)d_in[2];
    const float* gamma_log = (const float*)d_in[3];
    const float* B_re      = (const float*)d_in[4];
    const float* B_im      = (const float*)d_in[5];
    const float* C_re      = (const float*)d_in[6];
    const float* C_im      = (const float*)d_in[7];
    const float* D         = (const float*)d_in[8];
    float* out = (float*)d_out;

    __half *xp, *sp, *w1, *wo;
    cudaGetSymbolAddress((void**)&xp, g_x);
    cudaGetSymbolAddress((void**)&sp, g_Ssc);
    cudaGetSymbolAddress((void**)&w1, g_W1);
    cudaGetSymbolAddress((void**)&wo, g_Wo);

    static PFN_encodeTiled enc = nullptr;
    if (!enc) {
        void* fn = nullptr;
        cudaDriverEntryPointQueryResult qr;
        cudaGetDriverEntryPointByVersion("cuTensorMapEncodeTiled", &fn, 12000,
                                         cudaEnableDefault, &qr);
        enc = (PFN_encodeTiled)fn;
    }
    CUtensorMap tmX, tmW1, tmS, tmWo;
    encode2d(enc, &tmX,  xp, IN_F, MROWS, 128);
    encode2d(enc, &tmW1, w1, IN_F, SCOLS, 128);
    encode2d(enc, &tmS,  sp, SCOLS, MROWS, 128);
    encode2d(enc, &tmWo, wo, KOUT, OUT_F, 128);

    cudaFuncSetAttribute(gemm_kernel, cudaFuncAttributeMaxDynamicSharedMemorySize, GSMEM);

    prep_lambda_kernel<<<1, 256>>>(nu_log, theta_log);
    prep_w1_kernel<<<(SCOLS * IN_F + 255) / 256, 256>>>(gamma_log, B_re, B_im);
    prep_wout_kernel<<<(OUT_F * KOUT + 255) / 256, 256>>>(C_re, C_im, D);
    convert_x_kernel<<<(MROWS * IN_F / 4) / 256, 256>>>(x);

    // GEMM1 + fused tile-local scan: block 128x128, grid (512,4), K=128 (2 chunks)
    gemm_kernel<<<dim3(MROWS / 128, 4), 256, GSMEM>>>(
        tmX, tmX, tmW1, nullptr, 0, 2, 2, 1, 0, 3);

    combine_kernel<<<BATCH, NSTATE>>>();

    // GEMM2 + fused fixup: block 128x128, grid (512,1), K=640 (8 state + 2 x chunks)
    gemm_kernel<<<dim3(MROWS / 128, 1), 256, GSMEM>>>(
        tmS, tmX, tmWo, out, OUT_F, 10, 8, 0, 1, 3);
}

// round 14
// speedup vs baseline: 3.6372x; 1.0138x over previous
#include <cuda_runtime.h>
#include <cuda.h>
#include <cuda_fp16.h>
#include <math.h>
#include <stdint.h>

// ---------------- problem constants ----------------
#define BATCH   8
#define T       8192
#define IN_F    128
#define OUT_F   128
#define NSTATE  256
#define NC      64
#define CHUNK   128
#define MROWS   (BATCH * T)     // 65536
#define SCOLS   512             // 2*NSTATE interleaved: col 2n=re, 2n+1=im
#define KOUT    640             // 512 states + 128 x

// ---------------- scratch ----------------
__device__ __align__(256) __half g_x[(size_t)MROWS * IN_F];     // x fp16
__device__ __align__(256) __half g_Ssc[(size_t)MROWS * SCOLS];  // prescan states fp16
__device__ __align__(256) __half g_W1[SCOLS * IN_F];
__device__ __align__(256) __half g_Wo[OUT_F * KOUT];
__device__ float2  g_carry[BATCH * NC * NSTATE];
__device__ float2  g_lam[NSTATE];
__device__ float2  g_lam16[NSTATE];
__device__ double2 g_lam128[NSTATE];

// ---------------- PTX helpers ----------------
__device__ __forceinline__ uint32_t smem_u32(const void* p) {
    uint32_t a;
    asm("{ .reg .u64 t; cvta.to.shared.u64 t, %1; cvt.u32.u64 %0, t; }" : "=r"(a) : "l"(p));
    return a;
}
__device__ __forceinline__ void ldsm4(uint32_t* r, uint32_t addr) {
    asm volatile("ldmatrix.sync.aligned.m8n8.x4.shared.b16 {%0,%1,%2,%3}, [%4];"
                 : "=r"(r[0]), "=r"(r[1]), "=r"(r[2]), "=r"(r[3]) : "r"(addr));
}
__device__ __forceinline__ void mma_f16(float* c, const uint32_t* a, const uint32_t* b) {
    asm volatile("mma.sync.aligned.m16n8k16.row.col.f32.f16.f16.f32 "
                 "{%0,%1,%2,%3}, {%4,%5,%6,%7}, {%8,%9}, {%0,%1,%2,%3};"
                 : "+f"(c[0]), "+f"(c[1]), "+f"(c[2]), "+f"(c[3])
                 : "r"(a[0]), "r"(a[1]), "r"(a[2]), "r"(a[3]), "r"(b[0]), "r"(b[1]));
}
__device__ __forceinline__ float2 cmul(float2 a, float2 b) {
    return make_float2(a.x * b.x - a.y * b.y, a.x * b.y + a.y * b.x);
}
__device__ __forceinline__ float2 cfma(float2 l, float2 s, float2 u) {  // l*s + u
    return make_float2(fmaf(l.x, s.x, fmaf(-l.y, s.y, u.x)),
                       fmaf(l.x, s.y, fmaf( l.y, s.x, u.y)));
}
#define MBARRIER_INIT(mbar, cnt) \
    asm volatile("mbarrier.init.shared.b64 [%0], %1;" :: "r"((uint32_t)(mbar)), "r"((uint32_t)(cnt)) : "memory")
#define MBARRIER_EXPECT_TX(mbar, bytes) \
    asm volatile("mbarrier.arrive.expect_tx.shared.b64 _, [%0], %1;" :: "r"((uint32_t)(mbar)), "r"((uint32_t)(bytes)) : "memory")
__device__ __forceinline__ void mbar_wait(uint32_t mbar, uint32_t parity) {
    uint32_t done;
    asm volatile("{\n\t.reg .pred p;\n\t"
                 "mbarrier.try_wait.parity.acquire.cta.shared::cta.b64 p, [%1], %2;\n\t"
                 "selp.b32 %0, 1, 0, p;\n\t}"
                 : "=r"(done) : "r"(mbar), "r"(parity) : "memory");
    if (!done) {
        asm volatile("{\n\t.reg .pred P1;\n\t"
                     "WL_%=:\n\t"
                     "mbarrier.try_wait.parity.acquire.cta.shared::cta.b64 P1, [%0], %1, 0x989680;\n\t"
                     "@P1 bra.uni WD_%=;\n\t"
                     "bra.uni WL_%=;\n\t"
                     "WD_%=:\n\t}"
                     :: "r"(mbar), "r"(parity) : "memory");
    }
}
__device__ __forceinline__ void tma2d(uint32_t smem, const CUtensorMap* tm, int x, int y, uint32_t mbar) {
    asm volatile("cp.async.bulk.tensor.2d.shared::cta.global.tile.mbarrier::complete_tx::bytes "
                 "[%0], [%1, {%2, %3}], [%4];"
                 :: "r"(smem), "l"(tm), "r"(x), "r"(y), "r"(mbar) : "memory");
}
__device__ __forceinline__ uint32_t sw128(uint32_t off) { return off ^ ((off >> 3) & 0x70); }

// ---------------- merged prep: lambda tables + W1 + Wo ----------------
__global__ void prep_all_kernel(const float* __restrict__ nu_log,
                                const float* __restrict__ theta_log,
                                const float* __restrict__ gamma_log,
                                const float* __restrict__ B_re,
                                const float* __restrict__ B_im,
                                const float* __restrict__ C_re,
                                const float* __restrict__ C_im,
                                const float* __restrict__ D) {
    int b = blockIdx.x, tid = threadIdx.x;
    if (b == 0) {   // lambda tables (fp64)
        int n = tid;
        double nu  = exp((double)nu_log[n]);
        double th  = exp((double)theta_log[n]);
        double mod = exp(-nu);
        g_lam[n] = make_float2((float)(mod * cos(th)), (float)(mod * sin(th)));
        double m16 = exp(-16.0 * nu);
        g_lam16[n] = make_float2((float)(m16 * cos(16.0 * th)), (float)(m16 * sin(16.0 * th)));
        double m128 = exp(-128.0 * nu);
        g_lam128[n] = make_double2(m128 * cos(128.0 * th), m128 * sin(128.0 * th));
    }
    if (b < 256) {  // W1: 256 blocks x 256 = 65536 elems
        int idx = b * 256 + tid;
        int r = idx / IN_F, i = idx % IN_F;
        int s = r >> 1;
        float gam = expf(gamma_log[s]);
        float v = gam * ((r & 1) ? B_im[s * IN_F + i] : B_re[s * IN_F + i]);
        g_W1[idx] = __float2half_rn(v);
    } else {        // Wo: 320 blocks x 256 = 81920 elems
        int idx = (b - 256) * 256 + tid;
        int o = idx / KOUT, k = idx % KOUT;
        float v;
        if (k < 512) {
            int s = k >> 1;
            v = (k & 1) ? -C_im[o * NSTATE + s] : C_re[o * NSTATE + s];
        } else {
            v = D[o * IN_F + (k - 512)];
        }
        g_Wo[idx] = __float2half_rn(v);
    }
}

__global__ void convert_x_kernel(const float* __restrict__ x) {
    size_t i = ((size_t)blockIdx.x * blockDim.x + threadIdx.x) * 8;
    float4 v0 = *(const float4*)(x + i);
    float4 v1 = *(const float4*)(x + i + 4);
    __half2 h0(__float2half_rn(v0.x), __float2half_rn(v0.y));
    __half2 h1(__float2half_rn(v0.z), __float2half_rn(v0.w));
    __half2 h2(__float2half_rn(v1.x), __float2half_rn(v1.y));
    __half2 h3(__float2half_rn(v1.z), __float2half_rn(v1.w));
    uint4 pk;
    pk.x = *(uint32_t*)&h0; pk.y = *(uint32_t*)&h1;
    pk.z = *(uint32_t*)&h2; pk.w = *(uint32_t*)&h3;
    *(uint4*)(g_x + i) = pk;
}

// ================= GEMM1: A-resident, B ring, fused scan =================
// Block 128 rows; A (128x128 fp16, 2 chunks) resident; loop nt=0..3 over
// 128-col W1 tiles with 2-stage B ring. 8 warps of 64x32.
#define G1_A    1024
#define G1_B    (1024 + 32768)
#define G1_SMF  (1024 + 65536)         // float2[128][32] = 32 KB
#define G1_SEGC (G1_SMF + 32768)       // float2[8][32] = 2 KB
#define G1_PSEG (G1_SEGC + 2048)       // float2[8][32] = 2 KB
#define G1_SMEM (G1_PSEG + 2048)       // 103424 -> occ 2

__global__ void __launch_bounds__(256, 2) gemm1_kernel(
    const __grid_constant__ CUtensorMap tA,
    const __grid_constant__ CUtensorMap tB)
{
    extern __shared__ char smem[];
    uint32_t sb = smem_u32(smem);
    int tid = threadIdx.x, lane = tid & 31, wid = tid >> 5;
    int wm = wid & 1, wn = wid >> 1;          // 2x4 warp grid, 64x32 tiles
    int m = blockIdx.x;
    size_t m0 = (size_t)m * 128;

    if (tid == 0) {
        MBARRIER_INIT(sb, 1);          // barA
        MBARRIER_INIT(sb + 8, 1);      // barB stage 0
        MBARRIER_INIT(sb + 16, 1);     // barB stage 1
    }
    __syncthreads();

    if (tid == 0) {
        MBARRIER_EXPECT_TX(sb, 32768);
        tma2d(sb + G1_A,         &tA, 0,  (int)m0, sb);
        tma2d(sb + G1_A + 16384, &tA, 64, (int)m0, sb);
        // first two B tiles: j=0 -> (nt0,k0), j=1 -> (nt0,k1)
        MBARRIER_EXPECT_TX(sb + 8, 16384);
        tma2d(sb + G1_B,         &tB, 0,  0, sb + 8);
        MBARRIER_EXPECT_TX(sb + 16, 16384);
        tma2d(sb + G1_B + 16384, &tB, 64, 0, sb + 16);
    }
    mbar_wait(sb, 0);   // A resident

    float2* smf  = (float2*)(smem + (G1_SMF - 0));
    float2* segc = (float2*)(smem + G1_SEGC);
    float2* Pseg = (float2*)(smem + G1_PSEG);

    for (int nt = 0; nt < 4; nt++) {
        float acc[4][4][4];
        #pragma unroll
        for (int a = 0; a < 4; a++)
            #pragma unroll
            for (int b2 = 0; b2 < 4; b2++)
                #pragma unroll
                for (int c = 0; c < 4; c++) acc[a][b2][c] = 0.f;

        #pragma unroll
        for (int k = 0; k < 2; k++) {
            int j = nt * 2 + k;
            int s = j & 1;
            mbar_wait(sb + 8 + 8 * s, (j >> 1) & 1);
            uint32_t stA = sb + G1_A + k * 16384;
            uint32_t stB = sb + G1_B + s * 16384;
            #pragma unroll
            for (int kk = 0; kk < 64; kk += 16) {
                uint32_t af[4][4], bf[2][4];
                int arow = wm * 64 + (lane & 15);
                int acol = kk + ((lane >> 4) << 3);
                #pragma unroll
                for (int mi = 0; mi < 4; mi++)
                    ldsm4(af[mi], stA + sw128((arow + mi * 16) * 128 + acol * 2));
                int brow = wn * 32 + ((lane >> 4) << 3) + (lane & 7);
                int bcol = kk + (((lane >> 3) & 1) << 3);
                #pragma unroll
                for (int g = 0; g < 2; g++)
                    ldsm4(bf[g], stB + sw128((brow + g * 16) * 128 + bcol * 2));
                #pragma unroll
                for (int mi = 0; mi < 4; mi++)
                    #pragma unroll
                    for (int ni = 0; ni < 4; ni++)
                        mma_f16(acc[mi][ni], af[mi], &bf[ni >> 1][(ni & 1) * 2]);
            }
            __syncthreads();
            // reissue this stage for tile j+2
            if (tid == 0 && j + 2 < 8) {
                int jn = j + 2;
                int ntn = jn >> 1, kn = jn & 1;
                MBARRIER_EXPECT_TX(sb + 8 + 8 * s, 16384);
                tma2d(sb + G1_B + s * 16384, &tB, kn * 64, ntn * 128, sb + 8 + 8 * s);
            }
        }

        // ---- fused scan epilogue for this nt (64 states, two 32-state halves) ----
        int r0 = wm * 64 + (lane >> 2);
        int cloc0 = wn * 32 + (lane & 3) * 2;
        #pragma unroll
        for (int h = 0; h < 2; h++) {
            if ((wn >> 1) == h) {   // warps owning cols [h*64, h*64+64)
                #pragma unroll
                for (int mi = 0; mi < 4; mi++)
                    #pragma unroll
                    for (int ni = 0; ni < 4; ni++) {
                        int rl = r0 + mi * 16;
                        int sl = ((cloc0 + ni * 8) >> 1) - h * 32;
                        smf[rl * 32 + sl]       = make_float2(acc[mi][ni][0], acc[mi][ni][1]);
                        smf[(rl + 8) * 32 + sl] = make_float2(acc[mi][ni][2], acc[mi][ni][3]);
                    }
            }
            __syncthreads();
            int sbase = nt * 64 + h * 32;
            int seg = tid >> 5, s0 = tid & 31;
            {   // step1: 8 segments x 16 rows
                float2 lam = g_lam[sbase + s0];
                float2 p = make_float2(0.f, 0.f);
                #pragma unroll 4
                for (int t = 0; t < 16; t++) {
                    int row = seg * 16 + t;
                    p = cfma(lam, p, smf[row * 32 + s0]);
                    smf[row * 32 + s0] = p;
                }
                segc[seg * 32 + s0] = p;
            }
            __syncthreads();
            if (tid < 32) {   // step2: exclusive prefix with Lambda^16 + carry out
                float2 l16 = g_lam16[sbase + s0];
                float2 e = make_float2(0.f, 0.f);
                #pragma unroll
                for (int g = 0; g < 8; g++) {
                    Pseg[g * 32 + s0] = e;
                    e = cfma(l16, e, segc[g * 32 + s0]);
                }
                g_carry[(size_t)m * NSTATE + sbase + s0] = e;   // m == b*NC + chunk
            }
            __syncthreads();
            {   // step3: apply prefix, emit fp16 prescan states
                float2 lam = g_lam[sbase + s0];
                float2 mm = cmul(lam, Pseg[seg * 32 + s0]);
                #pragma unroll 4
                for (int t = 0; t < 16; t++) {
                    int row = seg * 16 + t;
                    float2 p = smf[row * 32 + s0];
                    float2 v = make_float2(p.x + mm.x, p.y + mm.y);
                    mm = cmul(lam, mm);
                    ((__half2*)(g_Ssc + (m0 + row) * SCOLS))[sbase + s0] =
                        __half2(__float2half_rn(v.x), __float2half_rn(v.y));
                }
            }
            __syncthreads();
        }
    }
}

// ================= GEMM2: TMA + fused fixup (R13, unchanged) =================
#define STAGE_SZ 32768
#define GSMEM    (1024 + 3 * STAGE_SZ)    // 99328 -> 2 blocks/SM
#define BOFF2    16384

__global__ void __launch_bounds__(256, 2) gemm2_kernel(
    const __grid_constant__ CUtensorMap tA0,
    const __grid_constant__ CUtensorMap tA1,
    const __grid_constant__ CUtensorMap tB,
    float* __restrict__ out, int ldo, int nk, int nk0, int ns)
{
    extern __shared__ char smem[];
    uint32_t sb = smem_u32(smem);
    int tid = threadIdx.x, lane = tid & 31, wid = tid >> 5;
    int wm = wid & 1, wn = wid >> 1;
    int m = blockIdx.x;
    size_t m0 = (size_t)m * 128;
    uint32_t aOff = sb + 1024;
    int fb = m >> 6;
    int fch = m & 63;

    float acc[4][4][4];
    #pragma unroll
    for (int a = 0; a < 4; a++)
        #pragma unroll
        for (int b2 = 0; b2 < 4; b2++)
            #pragma unroll
            for (int c = 0; c < 4; c++) acc[a][b2][c] = 0.f;

    if (tid == 0) {
        for (int s = 0; s < ns; s++) MBARRIER_INIT(sb + 8 * s, 1);
    }
    __syncthreads();

    auto issue = [&](int i) {
        int s = i % ns;
        uint32_t bar = sb + 8 * s;
        uint32_t stg = aOff + s * STAGE_SZ;
        MBARRIER_EXPECT_TX(bar, STAGE_SZ);
        const CUtensorMap* ta = (i < nk0) ? &tA0 : &tA1;
        int kx = (i < nk0) ? i * 64 : (i - nk0) * 64;
        tma2d(stg, ta, kx, (int)m0, bar);
        tma2d(stg + BOFF2, &tB, i * 64, 0, bar);
    };

    if (tid == 0) {
        int np = nk < ns ? nk : ns;
        for (int i = 0; i < np; i++) issue(i);
    }

    for (int i = 0; i < nk; i++) {
        int s = i % ns;
        mbar_wait(sb + 8 * s, (i / ns) & 1);

        uint32_t stA = aOff + s * STAGE_SZ;
        uint32_t stB = stA + BOFF2;

        if (i < nk0 && fch > 0) {
            int sl = tid & 31;
            int rseg = tid >> 5;
            int gs = i * 32 + sl;
            float2 ci = g_carry[((size_t)fb * NC + fch - 1) * NSTATE + gs];
            float2 lam = g_lam[gs];
            float2 l16 = g_lam16[gs];
            float2 mm = cmul(lam, ci);
            for (int k = 0; k < rseg; k++) mm = cmul(l16, mm);
            char* base = smem + (stA - sb);
            int rr0 = rseg * 16;
            #pragma unroll 4
            for (int t = 0; t < 16; t++) {
                uint32_t off = sw128((uint32_t)(rr0 + t) * 128 + sl * 4);
                __half2* ph = (__half2*)(base + off);
                __half2 hv = *ph;
                float2 v = make_float2(__half2float(hv.x) + mm.x,
                                       __half2float(hv.y) + mm.y);
                mm = cmul(lam, mm);
                *ph = __half2(__float2half_rn(v.x), __float2half_rn(v.y));
            }
            __syncthreads();
        }

        #pragma unroll
        for (int kk = 0; kk < 64; kk += 16) {
            uint32_t af[4][4], bf[2][4];
            int arow = wm * 64 + (lane & 15);
            int acol = kk + ((lane >> 4) << 3);
            #pragma unroll
            for (int mi = 0; mi < 4; mi++)
                ldsm4(af[mi], stA + sw128((arow + mi * 16) * 128 + acol * 2));
            int brow = wn * 32 + ((lane >> 4) << 3) + (lane & 7);
            int bcol = kk + (((lane >> 3) & 1) << 3);
            #pragma unroll
            for (int g = 0; g < 2; g++)
                ldsm4(bf[g], stB + sw128((brow + g * 16) * 128 + bcol * 2));
            #pragma unroll
            for (int mi = 0; mi < 4; mi++)
                #pragma unroll
                for (int ni = 0; ni < 4; ni++)
                    mma_f16(acc[mi][ni], af[mi], &bf[ni >> 1][(ni & 1) * 2]);
        }
        __syncthreads();
        if (tid == 0 && i + ns < nk) issue(i + ns);
    }

    int r0 = wm * 64 + (lane >> 2);
    int cloc0 = wn * 32 + (lane & 3) * 2;
    #pragma unroll
    for (int mi = 0; mi < 4; mi++)
        #pragma unroll
        for (int ni = 0; ni < 4; ni++) {
            int rl = r0 + mi * 16, cl = cloc0 + ni * 8;
            *(float2*)(out + (m0 + rl) * (size_t)ldo + cl) =
                make_float2(acc[mi][ni][0], acc[mi][ni][1]);
            *(float2*)(out + (m0 + rl + 8) * (size_t)ldo + cl) =
                make_float2(acc[mi][ni][2], acc[mi][ni][3]);
        }
}

// ---------------- cross-chunk combine (fp64, batched loads) ----------------
__global__ void combine_kernel() {
    int b = blockIdx.x;
    int n = threadIdx.x;
    double2 lL = g_lam128[n];
    double pre = 0.0, pim = 0.0;
    for (int c0 = 0; c0 < NC; c0 += 16) {
        float2 v[16];
        #pragma unroll
        for (int k = 0; k < 16; k++)
            v[k] = g_carry[((size_t)b * NC + c0 + k) * NSTATE + n];
        #pragma unroll
        for (int k = 0; k < 16; k++) {
            double nre = lL.x * pre - lL.y * pim + (double)v[k].x;
            double nim = lL.x * pim + lL.y * pre + (double)v[k].y;
            pre = nre; pim = nim;
            v[k] = make_float2((float)pre, (float)pim);
        }
        #pragma unroll
        for (int k = 0; k < 16; k++)
            g_carry[((size_t)b * NC + c0 + k) * NSTATE + n] = v[k];
    }
}

// ---------------- host: tensormap encode ----------------
typedef CUresult (*PFN_encodeTiled)(
    CUtensorMap*, CUtensorMapDataType, cuuint32_t, void*,
    const cuuint64_t*, const cuuint64_t*, const cuuint32_t*, const cuuint32_t*,
    CUtensorMapInterleave, CUtensorMapSwizzle, CUtensorMapL2promotion, CUtensorMapFloatOOBfill);

static void encode2d(PFN_encodeTiled enc, CUtensorMap* tm, void* ptr,
                     uint64_t cols, uint64_t rows, uint32_t box_rows) {
    cuuint64_t dims[2] = {cols, rows};
    cuuint64_t strides[1] = {cols * 2};
    cuuint32_t box[2] = {64, box_rows};
    cuuint32_t es[2] = {1, 1};
    enc(tm, CU_TENSOR_MAP_DATA_TYPE_FLOAT16, 2, ptr, dims, strides, box, es,
        CU_TENSOR_MAP_INTERLEAVE_NONE, CU_TENSOR_MAP_SWIZZLE_128B,
        CU_TENSOR_MAP_L2_PROMOTION_L2_128B, CU_TENSOR_MAP_FLOAT_OOB_FILL_NONE);
}

// ---------------- launch ----------------
extern "C" void kernel_launch(void* const* d_in, const int* in_sizes, int n_in,
                              void* d_out, int out_size) {
    const float* x         = (const float*)d_in[0];
    const float* nu_log    = (const float*)d_in[1];
    const float* theta_log = (const float*)d_in[2];
    const float* gamma_log = (const float*)d_in[3];
    const float* B_re      = (const float*)d_in[4];
    const float* B_im      = (const float*)d_in[5];
    const float* C_re      = (const float*)d_in[6];
    const float* C_im      = (const float*)d_in[7];
    const float* D         = (const float*)d_in[8];
    float* out = (float*)d_out;

    __half *xp, *sp, *w1, *wo;
    cudaGetSymbolAddress((void**)&xp, g_x);
    cudaGetSymbolAddress((void**)&sp, g_Ssc);
    cudaGetSymbolAddress((void**)&w1, g_W1);
    cudaGetSymbolAddress((void**)&wo, g_Wo);

    static PFN_encodeTiled enc = nullptr;
    if (!enc) {
        void* fn = nullptr;
        cudaDriverEntryPointQueryResult qr;
        cudaGetDriverEntryPointByVersion("cuTensorMapEncodeTiled", &fn, 12000,
                                         cudaEnableDefault, &qr);
        enc = (PFN_encodeTiled)fn;
    }
    CUtensorMap tmX, tmW1, tmS, tmWo;
    encode2d(enc, &tmX,  xp, IN_F, MROWS, 128);
    encode2d(enc, &tmW1, w1, IN_F, SCOLS, 128);
    encode2d(enc, &tmS,  sp, SCOLS, MROWS, 128);
    encode2d(enc, &tmWo, wo, KOUT, OUT_F, 128);

    cudaFuncSetAttribute(gemm1_kernel, cudaFuncAttributeMaxDynamicSharedMemorySize, G1_SMEM);
    cudaFuncSetAttribute(gemm2_kernel, cudaFuncAttributeMaxDynamicSharedMemorySize, GSMEM);

    prep_all_kernel<<<576, 256>>>(nu_log, theta_log, gamma_log, B_re, B_im, C_re, C_im, D);
    convert_x_kernel<<<(MROWS * IN_F / 8) / 256, 256>>>(x);

    // GEMM1 (A-resident) + fused tile-local scan: grid 512
    gemm1_kernel<<<MROWS / 128, 256, G1_SMEM>>>(tmX, tmW1);

    combine_kernel<<<BATCH, NSTATE>>>();

    // GEMM2 + fused fixup: grid 512, K=640 (8 state + 2 x chunks), 3-stage
    gemm2_kernel<<<MROWS / 128, 256, GSMEM>>>(tmS, tmX, tmWo, out, OUT_F, 10, 8, 3);
}

// round 15
// speedup vs baseline: 3.7457x; 1.0298x over previous
#include <cuda_runtime.h>
#include <cuda.h>
#include <cuda_fp16.h>
#include <math.h>
#include <stdint.h>

// ---------------- problem constants ----------------
#define BATCH   8
#define T       8192
#define IN_F    128
#define OUT_F   128
#define NSTATE  256
#define NC      64
#define CHUNK   128
#define MROWS   (BATCH * T)     // 65536
#define SCOLS   512             // 2*NSTATE interleaved: col 2n=re, 2n+1=im
#define KOUT    640             // 512 states + 128 x

// ---------------- scratch ----------------
__device__ __align__(256) __half g_x[(size_t)MROWS * IN_F];     // x fp16
__device__ __align__(256) __half g_Ssc[(size_t)MROWS * SCOLS];  // prescan states fp16
__device__ __align__(256) __half g_W1[SCOLS * IN_F];
__device__ __align__(256) __half g_Wo[OUT_F * KOUT];
__device__ float2  g_carry[BATCH * NC * NSTATE];
__device__ float2  g_lam[NSTATE];
__device__ float2  g_lam16[NSTATE];
__device__ double2 g_lam128[NSTATE];

// ---------------- PTX helpers ----------------
__device__ __forceinline__ uint32_t smem_u32(const void* p) {
    uint32_t a;
    asm("{ .reg .u64 t; cvta.to.shared.u64 t, %1; cvt.u32.u64 %0, t; }" : "=r"(a) : "l"(p));
    return a;
}
__device__ __forceinline__ void ldsm4(uint32_t* r, uint32_t addr) {
    asm volatile("ldmatrix.sync.aligned.m8n8.x4.shared.b16 {%0,%1,%2,%3}, [%4];"
                 : "=r"(r[0]), "=r"(r[1]), "=r"(r[2]), "=r"(r[3]) : "r"(addr));
}
__device__ __forceinline__ void mma_f16(float* c, const uint32_t* a, const uint32_t* b) {
    asm volatile("mma.sync.aligned.m16n8k16.row.col.f32.f16.f16.f32 "
                 "{%0,%1,%2,%3}, {%4,%5,%6,%7}, {%8,%9}, {%0,%1,%2,%3};"
                 : "+f"(c[0]), "+f"(c[1]), "+f"(c[2]), "+f"(c[3])
                 : "r"(a[0]), "r"(a[1]), "r"(a[2]), "r"(a[3]), "r"(b[0]), "r"(b[1]));
}
__device__ __forceinline__ float2 cmul(float2 a, float2 b) {
    return make_float2(a.x * b.x - a.y * b.y, a.x * b.y + a.y * b.x);
}
__device__ __forceinline__ float2 cfma(float2 l, float2 s, float2 u) {  // l*s + u
    return make_float2(fmaf(l.x, s.x, fmaf(-l.y, s.y, u.x)),
                       fmaf(l.x, s.y, fmaf( l.y, s.x, u.y)));
}
#define MBARRIER_INIT(mbar, cnt) \
    asm volatile("mbarrier.init.shared.b64 [%0], %1;" :: "r"((uint32_t)(mbar)), "r"((uint32_t)(cnt)) : "memory")
#define MBARRIER_EXPECT_TX(mbar, bytes) \
    asm volatile("mbarrier.arrive.expect_tx.shared.b64 _, [%0], %1;" :: "r"((uint32_t)(mbar)), "r"((uint32_t)(bytes)) : "memory")
__device__ __forceinline__ void mbar_wait(uint32_t mbar, uint32_t parity) {
    uint32_t done;
    asm volatile("{\n\t.reg .pred p;\n\t"
                 "mbarrier.try_wait.parity.acquire.cta.shared::cta.b64 p, [%1], %2;\n\t"
                 "selp.b32 %0, 1, 0, p;\n\t}"
                 : "=r"(done) : "r"(mbar), "r"(parity) : "memory");
    if (!done) {
        asm volatile("{\n\t.reg .pred P1;\n\t"
                     "WL_%=:\n\t"
                     "mbarrier.try_wait.parity.acquire.cta.shared::cta.b64 P1, [%0], %1, 0x989680;\n\t"
                     "@P1 bra.uni WD_%=;\n\t"
                     "bra.uni WL_%=;\n\t"
                     "WD_%=:\n\t}"
                     :: "r"(mbar), "r"(parity) : "memory");
    }
}
__device__ __forceinline__ void tma2d(uint32_t smem, const CUtensorMap* tm, int x, int y, uint32_t mbar) {
    asm volatile("cp.async.bulk.tensor.2d.shared::cta.global.tile.mbarrier::complete_tx::bytes "
                 "[%0], [%1, {%2, %3}], [%4];"
                 :: "r"(smem), "l"(tm), "r"(x), "r"(y), "r"(mbar) : "memory");
}
__device__ __forceinline__ uint32_t sw128(uint32_t off) { return off ^ ((off >> 3) & 0x70); }

// ---------------- merged prep: lambda tables + W1 + Wo ----------------
__global__ void prep_all_kernel(const float* __restrict__ nu_log,
                                const float* __restrict__ theta_log,
                                const float* __restrict__ gamma_log,
                                const float* __restrict__ B_re,
                                const float* __restrict__ B_im,
                                const float* __restrict__ C_re,
                                const float* __restrict__ C_im,
                                const float* __restrict__ D) {
    int b = blockIdx.x, tid = threadIdx.x;
    if (b == 0) {   // lambda tables (fp64)
        int n = tid;
        double nu  = exp((double)nu_log[n]);
        double th  = exp((double)theta_log[n]);
        double mod = exp(-nu);
        g_lam[n] = make_float2((float)(mod * cos(th)), (float)(mod * sin(th)));
        double m16 = exp(-16.0 * nu);
        g_lam16[n] = make_float2((float)(m16 * cos(16.0 * th)), (float)(m16 * sin(16.0 * th)));
        double m128 = exp(-128.0 * nu);
        g_lam128[n] = make_double2(m128 * cos(128.0 * th), m128 * sin(128.0 * th));
    }
    if (b < 256) {  // W1: 256 blocks x 256 = 65536 elems
        int idx = b * 256 + tid;
        int r = idx / IN_F, i = idx % IN_F;
        int s = r >> 1;
        float gam = expf(gamma_log[s]);
        float v = gam * ((r & 1) ? B_im[s * IN_F + i] : B_re[s * IN_F + i]);
        g_W1[idx] = __float2half_rn(v);
    } else {        // Wo: 320 blocks x 256 = 81920 elems
        int idx = (b - 256) * 256 + tid;
        int o = idx / KOUT, k = idx % KOUT;
        float v;
        if (k < 512) {
            int s = k >> 1;
            v = (k & 1) ? -C_im[o * NSTATE + s] : C_re[o * NSTATE + s];
        } else {
            v = D[o * IN_F + (k - 512)];
        }
        g_Wo[idx] = __float2half_rn(v);
    }
}

__global__ void convert_x_kernel(const float* __restrict__ x) {
    size_t i = ((size_t)blockIdx.x * blockDim.x + threadIdx.x) * 8;
    float4 v0 = *(const float4*)(x + i);
    float4 v1 = *(const float4*)(x + i + 4);
    __half2 h0(__float2half_rn(v0.x), __float2half_rn(v0.y));
    __half2 h1(__float2half_rn(v0.z), __float2half_rn(v0.w));
    __half2 h2(__float2half_rn(v1.x), __float2half_rn(v1.y));
    __half2 h3(__float2half_rn(v1.z), __float2half_rn(v1.w));
    uint4 pk;
    pk.x = *(uint32_t*)&h0; pk.y = *(uint32_t*)&h1;
    pk.z = *(uint32_t*)&h2; pk.w = *(uint32_t*)&h3;
    *(uint4*)(g_x + i) = pk;
}

// ================= GEMM1: A-resident, B ring, fused scan =================
#define G1_A    1024
#define G1_B    (1024 + 32768)
#define G1_SMF  (1024 + 65536)         // float2[128][32] = 32 KB
#define G1_SEGC (G1_SMF + 32768)       // float2[8][32] = 2 KB
#define G1_PSEG (G1_SEGC + 2048)       // float2[8][32] = 2 KB
#define G1_SMEM (G1_PSEG + 2048)       // 103424 -> occ 2

__global__ void __launch_bounds__(256, 2) gemm1_kernel(
    const __grid_constant__ CUtensorMap tA,
    const __grid_constant__ CUtensorMap tB)
{
    extern __shared__ char smem[];
    uint32_t sb = smem_u32(smem);
    int tid = threadIdx.x, lane = tid & 31, wid = tid >> 5;
    int wm = wid & 1, wn = wid >> 1;          // 2x4 warp grid, 64x32 tiles
    int m = blockIdx.x;
    size_t m0 = (size_t)m * 128;

    if (tid == 0) {
        MBARRIER_INIT(sb, 1);          // barA
        MBARRIER_INIT(sb + 8, 1);      // barB stage 0
        MBARRIER_INIT(sb + 16, 1);     // barB stage 1
    }
    __syncthreads();

    if (tid == 0) {
        MBARRIER_EXPECT_TX(sb, 32768);
        tma2d(sb + G1_A,         &tA, 0,  (int)m0, sb);
        tma2d(sb + G1_A + 16384, &tA, 64, (int)m0, sb);
        MBARRIER_EXPECT_TX(sb + 8, 16384);
        tma2d(sb + G1_B,         &tB, 0,  0, sb + 8);
        MBARRIER_EXPECT_TX(sb + 16, 16384);
        tma2d(sb + G1_B + 16384, &tB, 64, 0, sb + 16);
    }
    mbar_wait(sb, 0);   // A resident

    float2* smf  = (float2*)(smem + G1_SMF);
    float2* segc = (float2*)(smem + G1_SEGC);
    float2* Pseg = (float2*)(smem + G1_PSEG);

    for (int nt = 0; nt < 4; nt++) {
        float acc[4][4][4];
        #pragma unroll
        for (int a = 0; a < 4; a++)
            #pragma unroll
            for (int b2 = 0; b2 < 4; b2++)
                #pragma unroll
                for (int c = 0; c < 4; c++) acc[a][b2][c] = 0.f;

        #pragma unroll
        for (int k = 0; k < 2; k++) {
            int j = nt * 2 + k;
            int s = j & 1;
            mbar_wait(sb + 8 + 8 * s, (j >> 1) & 1);
            uint32_t stA = sb + G1_A + k * 16384;
            uint32_t stB = sb + G1_B + s * 16384;
            #pragma unroll
            for (int kk = 0; kk < 64; kk += 16) {
                uint32_t af[4][4], bf[2][4];
                int arow = wm * 64 + (lane & 15);
                int acol = kk + ((lane >> 4) << 3);
                #pragma unroll
                for (int mi = 0; mi < 4; mi++)
                    ldsm4(af[mi], stA + sw128((arow + mi * 16) * 128 + acol * 2));
                int brow = wn * 32 + ((lane >> 4) << 3) + (lane & 7);
                int bcol = kk + (((lane >> 3) & 1) << 3);
                #pragma unroll
                for (int g = 0; g < 2; g++)
                    ldsm4(bf[g], stB + sw128((brow + g * 16) * 128 + bcol * 2));
                #pragma unroll
                for (int mi = 0; mi < 4; mi++)
                    #pragma unroll
                    for (int ni = 0; ni < 4; ni++)
                        mma_f16(acc[mi][ni], af[mi], &bf[ni >> 1][(ni & 1) * 2]);
            }
            __syncthreads();
            if (tid == 0 && j + 2 < 8) {
                int jn = j + 2;
                int ntn = jn >> 1, kn = jn & 1;
                MBARRIER_EXPECT_TX(sb + 8 + 8 * s, 16384);
                tma2d(sb + G1_B + s * 16384, &tB, kn * 64, ntn * 128, sb + 8 + 8 * s);
            }
        }

        // ---- fused scan epilogue for this nt (64 states, two 32-state halves) ----
        int r0 = wm * 64 + (lane >> 2);
        int cloc0 = wn * 32 + (lane & 3) * 2;
        #pragma unroll
        for (int h = 0; h < 2; h++) {
            if ((wn >> 1) == h) {
                #pragma unroll
                for (int mi = 0; mi < 4; mi++)
                    #pragma unroll
                    for (int ni = 0; ni < 4; ni++) {
                        int rl = r0 + mi * 16;
                        int sl = ((cloc0 + ni * 8) >> 1) - h * 32;
                        smf[rl * 32 + sl]       = make_float2(acc[mi][ni][0], acc[mi][ni][1]);
                        smf[(rl + 8) * 32 + sl] = make_float2(acc[mi][ni][2], acc[mi][ni][3]);
                    }
            }
            __syncthreads();
            int sbase = nt * 64 + h * 32;
            int seg = tid >> 5, s0 = tid & 31;
            {
                float2 lam = g_lam[sbase + s0];
                float2 p = make_float2(0.f, 0.f);
                #pragma unroll 4
                for (int t = 0; t < 16; t++) {
                    int row = seg * 16 + t;
                    p = cfma(lam, p, smf[row * 32 + s0]);
                    smf[row * 32 + s0] = p;
                }
                segc[seg * 32 + s0] = p;
            }
            __syncthreads();
            if (tid < 32) {
                float2 l16 = g_lam16[sbase + s0];
                float2 e = make_float2(0.f, 0.f);
                #pragma unroll
                for (int g = 0; g < 8; g++) {
                    Pseg[g * 32 + s0] = e;
                    e = cfma(l16, e, segc[g * 32 + s0]);
                }
                g_carry[(size_t)m * NSTATE + sbase + s0] = e;   // m == b*NC + chunk
            }
            __syncthreads();
            {
                float2 lam = g_lam[sbase + s0];
                float2 mm = cmul(lam, Pseg[seg * 32 + s0]);
                #pragma unroll 4
                for (int t = 0; t < 16; t++) {
                    int row = seg * 16 + t;
                    float2 p = smf[row * 32 + s0];
                    float2 v = make_float2(p.x + mm.x, p.y + mm.y);
                    mm = cmul(lam, mm);
                    ((__half2*)(g_Ssc + (m0 + row) * SCOLS))[sbase + s0] =
                        __half2(__float2half_rn(v.x), __float2half_rn(v.y));
                }
            }
            __syncthreads();
        }
    }
}

// ================= GEMM2: TMA + fused fixup =================
#define STAGE_SZ 32768
#define GSMEM    (1024 + 3 * STAGE_SZ)    // 99328 -> 2 blocks/SM
#define BOFF2    16384

__global__ void __launch_bounds__(256, 2) gemm2_kernel(
    const __grid_constant__ CUtensorMap tA0,
    const __grid_constant__ CUtensorMap tA1,
    const __grid_constant__ CUtensorMap tB,
    float* __restrict__ out, int ldo, int nk, int nk0, int ns)
{
    extern __shared__ char smem[];
    uint32_t sb = smem_u32(smem);
    int tid = threadIdx.x, lane = tid & 31, wid = tid >> 5;
    int wm = wid & 1, wn = wid >> 1;
    int m = blockIdx.x;
    size_t m0 = (size_t)m * 128;
    uint32_t aOff = sb + 1024;
    int fb = m >> 6;
    int fch = m & 63;

    float acc[4][4][4];
    #pragma unroll
    for (int a = 0; a < 4; a++)
        #pragma unroll
        for (int b2 = 0; b2 < 4; b2++)
            #pragma unroll
            for (int c = 0; c < 4; c++) acc[a][b2][c] = 0.f;

    if (tid == 0) {
        for (int s = 0; s < ns; s++) MBARRIER_INIT(sb + 8 * s, 1);
    }
    __syncthreads();

    auto issue = [&](int i) {
        int s = i % ns;
        uint32_t bar = sb + 8 * s;
        uint32_t stg = aOff + s * STAGE_SZ;
        MBARRIER_EXPECT_TX(bar, STAGE_SZ);
        const CUtensorMap* ta = (i < nk0) ? &tA0 : &tA1;
        int kx = (i < nk0) ? i * 64 : (i - nk0) * 64;
        tma2d(stg, ta, kx, (int)m0, bar);
        tma2d(stg + BOFF2, &tB, i * 64, 0, bar);
    };

    if (tid == 0) {
        int np = nk < ns ? nk : ns;
        for (int i = 0; i < np; i++) issue(i);
    }

    for (int i = 0; i < nk; i++) {
        int s = i % ns;
        mbar_wait(sb + 8 * s, (i / ns) & 1);

        uint32_t stA = aOff + s * STAGE_SZ;
        uint32_t stB = stA + BOFF2;

        if (i < nk0 && fch > 0) {
            int sl = tid & 31;
            int rseg = tid >> 5;
            int gs = i * 32 + sl;
            float2 ci = g_carry[((size_t)fb * NC + fch - 1) * NSTATE + gs];
            float2 lam = g_lam[gs];
            float2 l16 = g_lam16[gs];
            float2 mm = cmul(lam, ci);
            for (int k = 0; k < rseg; k++) mm = cmul(l16, mm);
            char* base = smem + (stA - sb);
            int rr0 = rseg * 16;
            #pragma unroll 4
            for (int t = 0; t < 16; t++) {
                uint32_t off = sw128((uint32_t)(rr0 + t) * 128 + sl * 4);
                __half2* ph = (__half2*)(base + off);
                __half2 hv = *ph;
                float2 v = make_float2(__half2float(hv.x) + mm.x,
                                       __half2float(hv.y) + mm.y);
                mm = cmul(lam, mm);
                *ph = __half2(__float2half_rn(v.x), __float2half_rn(v.y));
            }
            __syncthreads();
        }

        #pragma unroll
        for (int kk = 0; kk < 64; kk += 16) {
            uint32_t af[4][4], bf[2][4];
            int arow = wm * 64 + (lane & 15);
            int acol = kk + ((lane >> 4) << 3);
            #pragma unroll
            for (int mi = 0; mi < 4; mi++)
                ldsm4(af[mi], stA + sw128((arow + mi * 16) * 128 + acol * 2));
            int brow = wn * 32 + ((lane >> 4) << 3) + (lane & 7);
            int bcol = kk + (((lane >> 3) & 1) << 3);
            #pragma unroll
            for (int g = 0; g < 2; g++)
                ldsm4(bf[g], stB + sw128((brow + g * 16) * 128 + bcol * 2));
            #pragma unroll
            for (int mi = 0; mi < 4; mi++)
                #pragma unroll
                for (int ni = 0; ni < 4; ni++)
                    mma_f16(acc[mi][ni], af[mi], &bf[ni >> 1][(ni & 1) * 2]);
        }
        __syncthreads();
        if (tid == 0 && i + ns < nk) issue(i + ns);
    }

    int r0 = wm * 64 + (lane >> 2);
    int cloc0 = wn * 32 + (lane & 3) * 2;
    #pragma unroll
    for (int mi = 0; mi < 4; mi++)
        #pragma unroll
        for (int ni = 0; ni < 4; ni++) {
            int rl = r0 + mi * 16, cl = cloc0 + ni * 8;
            *(float2*)(out + (m0 + rl) * (size_t)ldo + cl) =
                make_float2(acc[mi][ni][0], acc[mi][ni][1]);
            *(float2*)(out + (m0 + rl + 8) * (size_t)ldo + cl) =
                make_float2(acc[mi][ni][2], acc[mi][ni][3]);
        }
}

// ---------------- cross-chunk combine: warp Kogge-Stone scan (fp64) ----------------
// One warp per (b,n) pair; lane t owns chunks {2t, 2t+1}.
__global__ void combine_ks_kernel() {
    int w = blockIdx.x * 8 + (threadIdx.x >> 5);   // 0..2047
    int t = threadIdx.x & 31;
    int b = w >> 8, n = w & 255;
    size_t base = ((size_t)b * NC) * NSTATE + n;
    double2 lam = g_lam128[n];

    float2 c0 = g_carry[base + (size_t)(2 * t) * NSTATE];
    float2 c1 = g_carry[base + (size_t)(2 * t + 1) * NSTATE];

    // local pair prefix: p1 = lam*c0 + c1
    double sr = lam.x * (double)c0.x - lam.y * (double)c0.y + (double)c1.x;
    double si = lam.x * (double)c0.y + lam.y * (double)c0.x + (double)c1.y;

    // Kogge-Stone over 32 super-chunks, multiplier a = lam^2 (squared each step)
    double ar = lam.x * lam.x - lam.y * lam.y;
    double ai = 2.0 * lam.x * lam.y;
    #pragma unroll
    for (int k = 1; k < 32; k <<= 1) {
        double ur = __shfl_up_sync(0xFFFFFFFF, sr, k);
        double ui = __shfl_up_sync(0xFFFFFFFF, si, k);
        if (t >= k) {
            sr = ar * ur - ai * ui + sr;
            si = ar * ui + ai * ur + si;
        }
        double nar = ar * ar - ai * ai;
        ai = 2.0 * ar * ai;
        ar = nar;
    }
    // sr,si = inclusive prefix through chunk 2t+1
    double er = __shfl_up_sync(0xFFFFFFFF, sr, 1);
    double ei = __shfl_up_sync(0xFFFFFFFF, si, 1);
    double q0r = (double)c0.x, q0i = (double)c0.y;
    if (t > 0) {
        q0r += lam.x * er - lam.y * ei;
        q0i += lam.x * ei + lam.y * er;
    }
    g_carry[base + (size_t)(2 * t) * NSTATE]     = make_float2((float)q0r, (float)q0i);
    g_carry[base + (size_t)(2 * t + 1) * NSTATE] = make_float2((float)sr, (float)si);
}

// ---------------- host: tensormap encode ----------------
typedef CUresult (*PFN_encodeTiled)(
    CUtensorMap*, CUtensorMapDataType, cuuint32_t, void*,
    const cuuint64_t*, const cuuint64_t*, const cuuint32_t*, const cuuint32_t*,
    CUtensorMapInterleave, CUtensorMapSwizzle, CUtensorMapL2promotion, CUtensorMapFloatOOBfill);

static void encode2d(PFN_encodeTiled enc, CUtensorMap* tm, void* ptr,
                     uint64_t cols, uint64_t rows, uint32_t box_rows) {
    cuuint64_t dims[2] = {cols, rows};
    cuuint64_t strides[1] = {cols * 2};
    cuuint32_t box[2] = {64, box_rows};
    cuuint32_t es[2] = {1, 1};
    enc(tm, CU_TENSOR_MAP_DATA_TYPE_FLOAT16, 2, ptr, dims, strides, box, es,
        CU_TENSOR_MAP_INTERLEAVE_NONE, CU_TENSOR_MAP_SWIZZLE_128B,
        CU_TENSOR_MAP_L2_PROMOTION_L2_128B, CU_TENSOR_MAP_FLOAT_OOB_FILL_NONE);
}

// ---------------- launch ----------------
extern "C" void kernel_launch(void* const* d_in, const int* in_sizes, int n_in,
                              void* d_out, int out_size) {
    const float* x         = (const float*)d_in[0];
    const float* nu_log    = (const float*)d_in[1];
    const float* theta_log = (const float*)d_in[2];
    const float* gamma_log = (const float*)d_in[3];
    const float* B_re      = (const float*)d_in[4];
    const float* B_im      = (const float*)d_in[5];
    const float* C_re      = (const float*)d_in[6];
    const float* C_im      = (const float*)d_in[7];
    const float* D         = (const float*)d_in[8];
    float* out = (float*)d_out;

    __half *xp, *sp, *w1, *wo;
    cudaGetSymbolAddress((void**)&xp, g_x);
    cudaGetSymbolAddress((void**)&sp, g_Ssc);
    cudaGetSymbolAddress((void**)&w1, g_W1);
    cudaGetSymbolAddress((void**)&wo, g_Wo);

    static PFN_encodeTiled enc = nullptr;
    if (!enc) {
        void* fn = nullptr;
        cudaDriverEntryPointQueryResult qr;
        cudaGetDriverEntryPointByVersion("cuTensorMapEncodeTiled", &fn, 12000,
                                         cudaEnableDefault, &qr);
        enc = (PFN_encodeTiled)fn;
    }
    CUtensorMap tmX, tmW1, tmS, tmWo;
    encode2d(enc, &tmX,  xp, IN_F, MROWS, 128);
    encode2d(enc, &tmW1, w1, IN_F, SCOLS, 128);
    encode2d(enc, &tmS,  sp, SCOLS, MROWS, 128);
    encode2d(enc, &tmWo, wo, KOUT, OUT_F, 128);

    cudaFuncSetAttribute(gemm1_kernel, cudaFuncAttributeMaxDynamicSharedMemorySize, G1_SMEM);
    cudaFuncSetAttribute(gemm2_kernel, cudaFuncAttributeMaxDynamicSharedMemorySize, GSMEM);

    prep_all_kernel<<<576, 256>>>(nu_log, theta_log, gamma_log, B_re, B_im, C_re, C_im, D);
    convert_x_kernel<<<(MROWS * IN_F / 8) / 256, 256>>>(x);

    // GEMM1 (A-resident) + fused tile-local scan: grid 512
    gemm1_kernel<<<MROWS / 128, 256, G1_SMEM>>>(tmX, tmW1);

    // cross-chunk combine: warp-parallel Kogge-Stone (2048 warps)
    combine_ks_kernel<<<256, 256>>>();

    // GEMM2 + fused fixup: grid 512, K=640 (8 state + 2 x chunks), 3-stage
    gemm2_kernel<<<MROWS / 128, 256, GSMEM>>>(tmS, tmX, tmWo, out, OUT_F, 10, 8, 3);
}

// round 16
// speedup vs baseline: 3.7484x; 1.0007x over previous
#include <cuda_runtime.h>
#include <cuda.h>
#include <cuda_fp16.h>
#include <math.h>
#include <stdint.h>

// ---------------- problem constants ----------------
#define BATCH   8
#define T       8192
#define IN_F    128
#define OUT_F   128
#define NSTATE  256
#define NC      64
#define CHUNK   128
#define MROWS   (BATCH * T)     // 65536
#define SCOLS   512             // 2*NSTATE interleaved: col 2n=re, 2n+1=im
#define KOUT    640             // 512 states + 128 x

// ---------------- scratch ----------------
__device__ __align__(256) __half g_x[(size_t)MROWS * IN_F];     // x fp16
__device__ __align__(256) __half g_Ssc[(size_t)MROWS * SCOLS];  // prescan states fp16
__device__ __align__(256) __half g_W1[SCOLS * IN_F];
__device__ __align__(256) __half g_Wo[OUT_F * KOUT];
__device__ float2  g_carry[BATCH * NC * NSTATE];    // chunk-major (fixup reads)
__device__ float2  g_carryT[BATCH * NSTATE * NC];   // state-major (combine reads)
__device__ float2  g_lam[NSTATE];
__device__ float2  g_lam16[NSTATE];
__device__ double2 g_lam128[NSTATE];

// ---------------- PTX helpers ----------------
__device__ __forceinline__ uint32_t smem_u32(const void* p) {
    uint32_t a;
    asm("{ .reg .u64 t; cvta.to.shared.u64 t, %1; cvt.u32.u64 %0, t; }" : "=r"(a) : "l"(p));
    return a;
}
__device__ __forceinline__ void ldsm4(uint32_t* r, uint32_t addr) {
    asm volatile("ldmatrix.sync.aligned.m8n8.x4.shared.b16 {%0,%1,%2,%3}, [%4];"
                 : "=r"(r[0]), "=r"(r[1]), "=r"(r[2]), "=r"(r[3]) : "r"(addr));
}
__device__ __forceinline__ void mma_f16(float* c, const uint32_t* a, const uint32_t* b) {
    asm volatile("mma.sync.aligned.m16n8k16.row.col.f32.f16.f16.f32 "
                 "{%0,%1,%2,%3}, {%4,%5,%6,%7}, {%8,%9}, {%0,%1,%2,%3};"
                 : "+f"(c[0]), "+f"(c[1]), "+f"(c[2]), "+f"(c[3])
                 : "r"(a[0]), "r"(a[1]), "r"(a[2]), "r"(a[3]), "r"(b[0]), "r"(b[1]));
}
__device__ __forceinline__ float2 cmul(float2 a, float2 b) {
    return make_float2(a.x * b.x - a.y * b.y, a.x * b.y + a.y * b.x);
}
__device__ __forceinline__ float2 cfma(float2 l, float2 s, float2 u) {  // l*s + u
    return make_float2(fmaf(l.x, s.x, fmaf(-l.y, s.y, u.x)),
                       fmaf(l.x, s.y, fmaf( l.y, s.x, u.y)));
}
#define MBARRIER_INIT(mbar, cnt) \
    asm volatile("mbarrier.init.shared.b64 [%0], %1;" :: "r"((uint32_t)(mbar)), "r"((uint32_t)(cnt)) : "memory")
#define MBARRIER_EXPECT_TX(mbar, bytes) \
    asm volatile("mbarrier.arrive.expect_tx.shared.b64 _, [%0], %1;" :: "r"((uint32_t)(mbar)), "r"((uint32_t)(bytes)) : "memory")
__device__ __forceinline__ void mbar_wait(uint32_t mbar, uint32_t parity) {
    uint32_t done;
    asm volatile("{\n\t.reg .pred p;\n\t"
                 "mbarrier.try_wait.parity.acquire.cta.shared::cta.b64 p, [%1], %2;\n\t"
                 "selp.b32 %0, 1, 0, p;\n\t}"
                 : "=r"(done) : "r"(mbar), "r"(parity) : "memory");
    if (!done) {
        asm volatile("{\n\t.reg .pred P1;\n\t"
                     "WL_%=:\n\t"
                     "mbarrier.try_wait.parity.acquire.cta.shared::cta.b64 P1, [%0], %1, 0x989680;\n\t"
                     "@P1 bra.uni WD_%=;\n\t"
                     "bra.uni WL_%=;\n\t"
                     "WD_%=:\n\t}"
                     :: "r"(mbar), "r"(parity) : "memory");
    }
}
__device__ __forceinline__ void tma2d(uint32_t smem, const CUtensorMap* tm, int x, int y, uint32_t mbar) {
    asm volatile("cp.async.bulk.tensor.2d.shared::cta.global.tile.mbarrier::complete_tx::bytes "
                 "[%0], [%1, {%2, %3}], [%4];"
                 :: "r"(smem), "l"(tm), "r"(x), "r"(y), "r"(mbar) : "memory");
}
__device__ __forceinline__ uint32_t sw128(uint32_t off) { return off ^ ((off >> 3) & 0x70); }

// ---------------- merged prep: lambda tables + W1 + Wo ----------------
__global__ void prep_all_kernel(const float* __restrict__ nu_log,
                                const float* __restrict__ theta_log,
                                const float* __restrict__ gamma_log,
                                const float* __restrict__ B_re,
                                const float* __restrict__ B_im,
                                const float* __restrict__ C_re,
                                const float* __restrict__ C_im,
                                const float* __restrict__ D) {
    int b = blockIdx.x, tid = threadIdx.x;
    if (b == 0) {   // lambda tables (fp64)
        int n = tid;
        double nu  = exp((double)nu_log[n]);
        double th  = exp((double)theta_log[n]);
        double mod = exp(-nu);
        g_lam[n] = make_float2((float)(mod * cos(th)), (float)(mod * sin(th)));
        double m16 = exp(-16.0 * nu);
        g_lam16[n] = make_float2((float)(m16 * cos(16.0 * th)), (float)(m16 * sin(16.0 * th)));
        double m128 = exp(-128.0 * nu);
        g_lam128[n] = make_double2(m128 * cos(128.0 * th), m128 * sin(128.0 * th));
    }
    if (b < 256) {  // W1
        int idx = b * 256 + tid;
        int r = idx / IN_F, i = idx % IN_F;
        int s = r >> 1;
        float gam = expf(gamma_log[s]);
        float v = gam * ((r & 1) ? B_im[s * IN_F + i] : B_re[s * IN_F + i]);
        g_W1[idx] = __float2half_rn(v);
    } else {        // Wo
        int idx = (b - 256) * 256 + tid;
        int o = idx / KOUT, k = idx % KOUT;
        float v;
        if (k < 512) {
            int s = k >> 1;
            v = (k & 1) ? -C_im[o * NSTATE + s] : C_re[o * NSTATE + s];
        } else {
            v = D[o * IN_F + (k - 512)];
        }
        g_Wo[idx] = __float2half_rn(v);
    }
}

__global__ void convert_x_kernel(const float* __restrict__ x) {
    size_t i = ((size_t)blockIdx.x * blockDim.x + threadIdx.x) * 8;
    float4 v0 = *(const float4*)(x + i);
    float4 v1 = *(const float4*)(x + i + 4);
    __half2 h0(__float2half_rn(v0.x), __float2half_rn(v0.y));
    __half2 h1(__float2half_rn(v0.z), __float2half_rn(v0.w));
    __half2 h2(__float2half_rn(v1.x), __float2half_rn(v1.y));
    __half2 h3(__float2half_rn(v1.z), __float2half_rn(v1.w));
    uint4 pk;
    pk.x = *(uint32_t*)&h0; pk.y = *(uint32_t*)&h1;
    pk.z = *(uint32_t*)&h2; pk.w = *(uint32_t*)&h3;
    *(uint4*)(g_x + i) = pk;
}

// ================= GEMM1: A-resident, B ring, fused scan =================
#define G1_A    1024
#define G1_B    (1024 + 32768)
#define G1_SMF  (1024 + 65536)         // float2[128][32] = 32 KB
#define G1_SEGC (G1_SMF + 32768)       // float2[8][32] = 2 KB
#define G1_PSEG (G1_SEGC + 2048)       // float2[8][32] = 2 KB
#define G1_SMEM (G1_PSEG + 2048)       // 103424 -> occ 2

__global__ void __launch_bounds__(256, 2) gemm1_kernel(
    const __grid_constant__ CUtensorMap tA,
    const __grid_constant__ CUtensorMap tB)
{
    extern __shared__ char smem[];
    uint32_t sb = smem_u32(smem);
    int tid = threadIdx.x, lane = tid & 31, wid = tid >> 5;
    int wm = wid & 1, wn = wid >> 1;          // 2x4 warp grid, 64x32 tiles
    int m = blockIdx.x;
    size_t m0 = (size_t)m * 128;

    if (tid == 0) {
        MBARRIER_INIT(sb, 1);
        MBARRIER_INIT(sb + 8, 1);
        MBARRIER_INIT(sb + 16, 1);
    }
    __syncthreads();

    if (tid == 0) {
        MBARRIER_EXPECT_TX(sb, 32768);
        tma2d(sb + G1_A,         &tA, 0,  (int)m0, sb);
        tma2d(sb + G1_A + 16384, &tA, 64, (int)m0, sb);
        MBARRIER_EXPECT_TX(sb + 8, 16384);
        tma2d(sb + G1_B,         &tB, 0,  0, sb + 8);
        MBARRIER_EXPECT_TX(sb + 16, 16384);
        tma2d(sb + G1_B + 16384, &tB, 64, 0, sb + 16);
    }
    mbar_wait(sb, 0);   // A resident

    float2* smf  = (float2*)(smem + G1_SMF);
    float2* segc = (float2*)(smem + G1_SEGC);
    float2* Pseg = (float2*)(smem + G1_PSEG);

    for (int nt = 0; nt < 4; nt++) {
        float acc[4][4][4];
        #pragma unroll
        for (int a = 0; a < 4; a++)
            #pragma unroll
            for (int b2 = 0; b2 < 4; b2++)
                #pragma unroll
                for (int c = 0; c < 4; c++) acc[a][b2][c] = 0.f;

        #pragma unroll
        for (int k = 0; k < 2; k++) {
            int j = nt * 2 + k;
            int s = j & 1;
            mbar_wait(sb + 8 + 8 * s, (j >> 1) & 1);
            uint32_t stA = sb + G1_A + k * 16384;
            uint32_t stB = sb + G1_B + s * 16384;
            #pragma unroll
            for (int kk = 0; kk < 64; kk += 16) {
                uint32_t af[4][4], bf[2][4];
                int arow = wm * 64 + (lane & 15);
                int acol = kk + ((lane >> 4) << 3);
                #pragma unroll
                for (int mi = 0; mi < 4; mi++)
                    ldsm4(af[mi], stA + sw128((arow + mi * 16) * 128 + acol * 2));
                int brow = wn * 32 + ((lane >> 4) << 3) + (lane & 7);
                int bcol = kk + (((lane >> 3) & 1) << 3);
                #pragma unroll
                for (int g = 0; g < 2; g++)
                    ldsm4(bf[g], stB + sw128((brow + g * 16) * 128 + bcol * 2));
                #pragma unroll
                for (int mi = 0; mi < 4; mi++)
                    #pragma unroll
                    for (int ni = 0; ni < 4; ni++)
                        mma_f16(acc[mi][ni], af[mi], &bf[ni >> 1][(ni & 1) * 2]);
            }
            __syncthreads();
            if (tid == 0 && j + 2 < 8) {
                int jn = j + 2;
                int ntn = jn >> 1, kn = jn & 1;
                MBARRIER_EXPECT_TX(sb + 8 + 8 * s, 16384);
                tma2d(sb + G1_B + s * 16384, &tB, kn * 64, ntn * 128, sb + 8 + 8 * s);
            }
        }

        // ---- fused scan epilogue for this nt (64 states, two 32-state halves) ----
        int r0 = wm * 64 + (lane >> 2);
        int cloc0 = wn * 32 + (lane & 3) * 2;
        #pragma unroll
        for (int h = 0; h < 2; h++) {
            if ((wn >> 1) == h) {
                #pragma unroll
                for (int mi = 0; mi < 4; mi++)
                    #pragma unroll
                    for (int ni = 0; ni < 4; ni++) {
                        int rl = r0 + mi * 16;
                        int sl = ((cloc0 + ni * 8) >> 1) - h * 32;
                        smf[rl * 32 + sl]       = make_float2(acc[mi][ni][0], acc[mi][ni][1]);
                        smf[(rl + 8) * 32 + sl] = make_float2(acc[mi][ni][2], acc[mi][ni][3]);
                    }
            }
            __syncthreads();
            int sbase = nt * 64 + h * 32;
            int seg = tid >> 5, s0 = tid & 31;
            {   // step1: 8 segments x 16 rows (true scan, serial)
                float2 lam = g_lam[sbase + s0];
                float2 p = make_float2(0.f, 0.f);
                #pragma unroll 4
                for (int t = 0; t < 16; t++) {
                    int row = seg * 16 + t;
                    p = cfma(lam, p, smf[row * 32 + s0]);
                    smf[row * 32 + s0] = p;
                }
                segc[seg * 32 + s0] = p;
            }
            __syncthreads();
            if (tid < 32) {   // step2: exclusive prefix + carry out (state-major)
                float2 l16 = g_lam16[sbase + s0];
                float2 e = make_float2(0.f, 0.f);
                #pragma unroll
                for (int g = 0; g < 8; g++) {
                    Pseg[g * 32 + s0] = e;
                    e = cfma(l16, e, segc[g * 32 + s0]);
                }
                g_carryT[((size_t)(m >> 6) * NSTATE + sbase + s0) * NC + (m & 63)] = e;
            }
            __syncthreads();
            {   // step3: apply prefix, ILP-4 power chains
                float2 lam = g_lam[sbase + s0];
                float2 lam2 = cmul(lam, lam);
                float2 lam4 = cmul(lam2, lam2);
                float2 e = Pseg[seg * 32 + s0];
                float2 p0 = cmul(lam, e);
                float2 p1 = cmul(lam, p0);
                float2 p2 = cmul(lam, p1);
                float2 p3 = cmul(lam, p2);
                #pragma unroll
                for (int t4 = 0; t4 < 4; t4++) {
                    int row = seg * 16 + t4 * 4;
                    float2 q0 = smf[(row + 0) * 32 + s0];
                    float2 q1 = smf[(row + 1) * 32 + s0];
                    float2 q2 = smf[(row + 2) * 32 + s0];
                    float2 q3 = smf[(row + 3) * 32 + s0];
                    __half2* ob = (__half2*)(g_Ssc + (m0 + row) * SCOLS) + sbase + s0;
                    ob[0]             = __half2(__float2half_rn(q0.x + p0.x), __float2half_rn(q0.y + p0.y));
                    ob[SCOLS / 2]     = __half2(__float2half_rn(q1.x + p1.x), __float2half_rn(q1.y + p1.y));
                    ob[SCOLS]         = __half2(__float2half_rn(q2.x + p2.x), __float2half_rn(q2.y + p2.y));
                    ob[3 * SCOLS / 2] = __half2(__float2half_rn(q3.x + p3.x), __float2half_rn(q3.y + p3.y));
                    p0 = cmul(lam4, p0); p1 = cmul(lam4, p1);
                    p2 = cmul(lam4, p2); p3 = cmul(lam4, p3);
                }
            }
            __syncthreads();
        }
    }
}

// ================= GEMM2: TMA + fused fixup (ILP-4) =================
#define STAGE_SZ 32768
#define GSMEM    (1024 + 3 * STAGE_SZ)    // 99328 -> 2 blocks/SM
#define BOFF2    16384

__global__ void __launch_bounds__(256, 2) gemm2_kernel(
    const __grid_constant__ CUtensorMap tA0,
    const __grid_constant__ CUtensorMap tA1,
    const __grid_constant__ CUtensorMap tB,
    float* __restrict__ out, int ldo, int nk, int nk0, int ns)
{
    extern __shared__ char smem[];
    uint32_t sb = smem_u32(smem);
    int tid = threadIdx.x, lane = tid & 31, wid = tid >> 5;
    int wm = wid & 1, wn = wid >> 1;
    int m = blockIdx.x;
    size_t m0 = (size_t)m * 128;
    uint32_t aOff = sb + 1024;
    int fb = m >> 6;
    int fch = m & 63;

    float acc[4][4][4];
    #pragma unroll
    for (int a = 0; a < 4; a++)
        #pragma unroll
        for (int b2 = 0; b2 < 4; b2++)
            #pragma unroll
            for (int c = 0; c < 4; c++) acc[a][b2][c] = 0.f;

    if (tid == 0) {
        for (int s = 0; s < ns; s++) MBARRIER_INIT(sb + 8 * s, 1);
    }
    __syncthreads();

    auto issue = [&](int i) {
        int s = i % ns;
        uint32_t bar = sb + 8 * s;
        uint32_t stg = aOff + s * STAGE_SZ;
        MBARRIER_EXPECT_TX(bar, STAGE_SZ);
        const CUtensorMap* ta = (i < nk0) ? &tA0 : &tA1;
        int kx = (i < nk0) ? i * 64 : (i - nk0) * 64;
        tma2d(stg, ta, kx, (int)m0, bar);
        tma2d(stg + BOFF2, &tB, i * 64, 0, bar);
    };

    if (tid == 0) {
        int np = nk < ns ? nk : ns;
        for (int i = 0; i < np; i++) issue(i);
    }

    for (int i = 0; i < nk; i++) {
        int s = i % ns;
        mbar_wait(sb + 8 * s, (i / ns) & 1);

        uint32_t stA = aOff + s * STAGE_SZ;
        uint32_t stB = stA + BOFF2;

        // ---- fused fixup, 4 independent power chains ----
        if (i < nk0 && fch > 0) {
            int sl = tid & 31;
            int rseg = tid >> 5;
            int gs = i * 32 + sl;
            float2 ci = g_carry[((size_t)fb * NC + fch - 1) * NSTATE + gs];
            float2 lam = g_lam[gs];
            float2 l16 = g_lam16[gs];
            float2 mm = cmul(lam, ci);
            for (int k = 0; k < rseg; k++) mm = cmul(l16, mm);
            float2 lam2 = cmul(lam, lam);
            float2 lam4 = cmul(lam2, lam2);
            float2 p0 = mm;
            float2 p1 = cmul(lam, p0);
            float2 p2 = cmul(lam, p1);
            float2 p3 = cmul(lam, p2);
            char* base = smem + (stA - sb);
            int rr0 = rseg * 16;
            #pragma unroll
            for (int t4 = 0; t4 < 4; t4++) {
                int row = rr0 + t4 * 4;
                __half2* ph0 = (__half2*)(base + sw128((uint32_t)(row + 0) * 128 + sl * 4));
                __half2* ph1 = (__half2*)(base + sw128((uint32_t)(row + 1) * 128 + sl * 4));
                __half2* ph2 = (__half2*)(base + sw128((uint32_t)(row + 2) * 128 + sl * 4));
                __half2* ph3 = (__half2*)(base + sw128((uint32_t)(row + 3) * 128 + sl * 4));
                __half2 h0 = *ph0, h1 = *ph1, h2 = *ph2, h3 = *ph3;
                *ph0 = __half2(__float2half_rn(__half2float(h0.x) + p0.x), __float2half_rn(__half2float(h0.y) + p0.y));
                *ph1 = __half2(__float2half_rn(__half2float(h1.x) + p1.x), __float2half_rn(__half2float(h1.y) + p1.y));
                *ph2 = __half2(__float2half_rn(__half2float(h2.x) + p2.x), __float2half_rn(__half2float(h2.y) + p2.y));
                *ph3 = __half2(__float2half_rn(__half2float(h3.x) + p3.x), __float2half_rn(__half2float(h3.y) + p3.y));
                p0 = cmul(lam4, p0); p1 = cmul(lam4, p1);
                p2 = cmul(lam4, p2); p3 = cmul(lam4, p3);
            }
            __syncthreads();
        }

        #pragma unroll
        for (int kk = 0; kk < 64; kk += 16) {
            uint32_t af[4][4], bf[2][4];
            int arow = wm * 64 + (lane & 15);
            int acol = kk + ((lane >> 4) << 3);
            #pragma unroll
            for (int mi = 0; mi < 4; mi++)
                ldsm4(af[mi], stA + sw128((arow + mi * 16) * 128 + acol * 2));
            int brow = wn * 32 + ((lane >> 4) << 3) + (lane & 7);
            int bcol = kk + (((lane >> 3) & 1) << 3);
            #pragma unroll
            for (int g = 0; g < 2; g++)
                ldsm4(bf[g], stB + sw128((brow + g * 16) * 128 + bcol * 2));
            #pragma unroll
            for (int mi = 0; mi < 4; mi++)
                #pragma unroll
                for (int ni = 0; ni < 4; ni++)
                    mma_f16(acc[mi][ni], af[mi], &bf[ni >> 1][(ni & 1) * 2]);
        }
        __syncthreads();
        if (tid == 0 && i + ns < nk) issue(i + ns);
    }

    int r0 = wm * 64 + (lane >> 2);
    int cloc0 = wn * 32 + (lane & 3) * 2;
    #pragma unroll
    for (int mi = 0; mi < 4; mi++)
        #pragma unroll
        for (int ni = 0; ni < 4; ni++) {
            int rl = r0 + mi * 16, cl = cloc0 + ni * 8;
            *(float2*)(out + (m0 + rl) * (size_t)ldo + cl) =
                make_float2(acc[mi][ni][0], acc[mi][ni][1]);
            *(float2*)(out + (m0 + rl + 8) * (size_t)ldo + cl) =
                make_float2(acc[mi][ni][2], acc[mi][ni][3]);
        }
}

// ------ cross-chunk combine: warp Kogge-Stone, coalesced loads (fp64) ------
// Warp w handles (b,n); reads g_carryT[w*64..w*64+63] contiguous.
__global__ void combine_ks_kernel() {
    int w = blockIdx.x * 8 + (threadIdx.x >> 5);   // 0..2047
    int t = threadIdx.x & 31;
    int b = w >> 8, n = w & 255;
    const float2* src = g_carryT + (size_t)w * NC;
    double2 lam = g_lam128[n];

    float2 c0 = src[2 * t];
    float2 c1 = src[2 * t + 1];

    double sr = lam.x * (double)c0.x - lam.y * (double)c0.y + (double)c1.x;
    double si = lam.x * (double)c0.y + lam.y * (double)c0.x + (double)c1.y;

    double ar = lam.x * lam.x - lam.y * lam.y;
    double ai = 2.0 * lam.x * lam.y;
    #pragma unroll
    for (int k = 1; k < 32; k <<= 1) {
        double ur = __shfl_up_sync(0xFFFFFFFF, sr, k);
        double ui = __shfl_up_sync(0xFFFFFFFF, si, k);
        if (t >= k) {
            sr = ar * ur - ai * ui + sr;
            si = ar * ui + ai * ur + si;
        }
        double nar = ar * ar - ai * ai;
        ai = 2.0 * ar * ai;
        ar = nar;
    }
    double er = __shfl_up_sync(0xFFFFFFFF, sr, 1);
    double ei = __shfl_up_sync(0xFFFFFFFF, si, 1);
    double q0r = (double)c0.x, q0i = (double)c0.y;
    if (t > 0) {
        q0r += lam.x * er - lam.y * ei;
        q0i += lam.x * ei + lam.y * er;
    }
    size_t dbase = ((size_t)b * NC) * NSTATE + n;
    g_carry[dbase + (size_t)(2 * t) * NSTATE]     = make_float2((float)q0r, (float)q0i);
    g_carry[dbase + (size_t)(2 * t + 1) * NSTATE] = make_float2((float)sr, (float)si);
}

// ---------------- host: tensormap encode ----------------
typedef CUresult (*PFN_encodeTiled)(
    CUtensorMap*, CUtensorMapDataType, cuuint32_t, void*,
    const cuuint64_t*, const cuuint64_t*, const cuuint32_t*, const cuuint32_t*,
    CUtensorMapInterleave, CUtensorMapSwizzle, CUtensorMapL2promotion, CUtensorMapFloatOOBfill);

static void encode2d(PFN_encodeTiled enc, CUtensorMap* tm, void* ptr,
                     uint64_t cols, uint64_t rows, uint32_t box_rows) {
    cuuint64_t dims[2] = {cols, rows};
    cuuint64_t strides[1] = {cols * 2};
    cuuint32_t box[2] = {64, box_rows};
    cuuint32_t es[2] = {1, 1};
    enc(tm, CU_TENSOR_MAP_DATA_TYPE_FLOAT16, 2, ptr, dims, strides, box, es,
        CU_TENSOR_MAP_INTERLEAVE_NONE, CU_TENSOR_MAP_SWIZZLE_128B,
        CU_TENSOR_MAP_L2_PROMOTION_L2_128B, CU_TENSOR_MAP_FLOAT_OOB_FILL_NONE);
}

// ---------------- launch ----------------
extern "C" void kernel_launch(void* const* d_in, const int* in_sizes, int n_in,
                              void* d_out, int out_size) {
    const float* x         = (const float*)d_in[0];
    const float* nu_log    = (const float*)d_in[1];
    const float* theta_log = (const float*)d_in[2];
    const float* gamma_log = (const float*)d_in[3];
    const float* B_re      = (const float*)d_in[4];
    const float* B_im      = (const float*)d_in[5];
    const float* C_re      = (const float*)d_in[6];
    const float* C_im      = (const float*)d_in[7];
    const float* D         = (const float*)d_in[8];
    float* out = (float*)d_out;

    __half *xp, *sp, *w1, *wo;
    cudaGetSymbolAddress((void**)&xp, g_x);
    cudaGetSymbolAddress((void**)&sp, g_Ssc);
    cudaGetSymbolAddress((void**)&w1, g_W1);
    cudaGetSymbolAddress((void**)&wo, g_Wo);

    static PFN_encodeTiled enc = nullptr;
    if (!enc) {
        void* fn = nullptr;
        cudaDriverEntryPointQueryResult qr;
        cudaGetDriverEntryPointByVersion("cuTensorMapEncodeTiled", &fn, 12000,
                                         cudaEnableDefault, &qr);
        enc = (PFN_encodeTiled)fn;
    }
    CUtensorMap tmX, tmW1, tmS, tmWo;
    encode2d(enc, &tmX,  xp, IN_F, MROWS, 128);
    encode2d(enc, &tmW1, w1, IN_F, SCOLS, 128);
    encode2d(enc, &tmS,  sp, SCOLS, MROWS, 128);
    encode2d(enc, &tmWo, wo, KOUT, OUT_F, 128);

    cudaFuncSetAttribute(gemm1_kernel, cudaFuncAttributeMaxDynamicSharedMemorySize, G1_SMEM);
    cudaFuncSetAttribute(gemm2_kernel, cudaFuncAttributeMaxDynamicSharedMemorySize, GSMEM);

    prep_all_kernel<<<576, 256>>>(nu_log, theta_log, gamma_log, B_re, B_im, C_re, C_im, D);
    convert_x_kernel<<<(MROWS * IN_F / 8) / 256, 256>>>(x);

    // GEMM1 (A-resident) + fused tile-local scan: grid 512
    gemm1_kernel<<<MROWS / 128, 256, G1_SMEM>>>(tmX, tmW1);

    // cross-chunk combine: warp-parallel Kogge-Stone, coalesced
    combine_ks_kernel<<<256, 256>>>();

    // GEMM2 + fused fixup: grid 512, K=640 (8 state + 2 x chunks), 3-stage
    gemm2_kernel<<<MROWS / 128, 256, GSMEM>>>(tmS, tmX, tmWo, out, OUT_F, 10, 8, 3);
}

// round 17
// speedup vs baseline: 3.9298x; 1.0484x over previous
#include <cuda_runtime.h>
#include <cuda.h>
#include <cuda_fp16.h>
#include <math.h>
#include <stdint.h>

// ---------------- problem constants ----------------
#define BATCH   8
#define T       8192
#define IN_F    128
#define OUT_F   128
#define NSTATE  256
#define NC      64
#define CHUNK   128
#define MROWS   (BATCH * T)     // 65536
#define SCOLS   512             // 2*NSTATE interleaved: col 2n=re, 2n+1=im
#define KOUT    640             // 512 states + 128 x

// ---------------- scratch ----------------
__device__ __align__(256) __half g_x[(size_t)MROWS * IN_F];     // x fp16
__device__ __align__(256) __half g_Ssc[(size_t)MROWS * SCOLS];  // prescan states fp16
__device__ __align__(256) __half g_W1[SCOLS * IN_F];
__device__ __align__(256) __half g_Wo[OUT_F * KOUT];
__device__ float2  g_carry[BATCH * NC * NSTATE];    // chunk-major (fixup reads)
__device__ float2  g_carryT[BATCH * NSTATE * NC];   // state-major (combine reads)
__device__ float2  g_lam[NSTATE];
__device__ float2  g_lam16[NSTATE];
__device__ double2 g_lam128[NSTATE];

// ---------------- PTX helpers ----------------
__device__ __forceinline__ uint32_t smem_u32(const void* p) {
    uint32_t a;
    asm("{ .reg .u64 t; cvta.to.shared.u64 t, %1; cvt.u32.u64 %0, t; }" : "=r"(a) : "l"(p));
    return a;
}
__device__ __forceinline__ void ldsm4(uint32_t* r, uint32_t addr) {
    asm volatile("ldmatrix.sync.aligned.m8n8.x4.shared.b16 {%0,%1,%2,%3}, [%4];"
                 : "=r"(r[0]), "=r"(r[1]), "=r"(r[2]), "=r"(r[3]) : "r"(addr));
}
__device__ __forceinline__ void mma_f16(float* c, const uint32_t* a, const uint32_t* b) {
    asm volatile("mma.sync.aligned.m16n8k16.row.col.f32.f16.f16.f32 "
                 "{%0,%1,%2,%3}, {%4,%5,%6,%7}, {%8,%9}, {%0,%1,%2,%3};"
                 : "+f"(c[0]), "+f"(c[1]), "+f"(c[2]), "+f"(c[3])
                 : "r"(a[0]), "r"(a[1]), "r"(a[2]), "r"(a[3]), "r"(b[0]), "r"(b[1]));
}
__device__ __forceinline__ float2 cmul(float2 a, float2 b) {
    return make_float2(a.x * b.x - a.y * b.y, a.x * b.y + a.y * b.x);
}
__device__ __forceinline__ float2 cfma(float2 l, float2 s, float2 u) {  // l*s + u
    return make_float2(fmaf(l.x, s.x, fmaf(-l.y, s.y, u.x)),
                       fmaf(l.x, s.y, fmaf( l.y, s.x, u.y)));
}
#define MBARRIER_INIT(mbar, cnt) \
    asm volatile("mbarrier.init.shared.b64 [%0], %1;" :: "r"((uint32_t)(mbar)), "r"((uint32_t)(cnt)) : "memory")
#define MBARRIER_EXPECT_TX(mbar, bytes) \
    asm volatile("mbarrier.arrive.expect_tx.shared.b64 _, [%0], %1;" :: "r"((uint32_t)(mbar)), "r"((uint32_t)(bytes)) : "memory")
__device__ __forceinline__ void mbar_wait(uint32_t mbar, uint32_t parity) {
    uint32_t done;
    asm volatile("{\n\t.reg .pred p;\n\t"
                 "mbarrier.try_wait.parity.acquire.cta.shared::cta.b64 p, [%1], %2;\n\t"
                 "selp.b32 %0, 1, 0, p;\n\t}"
                 : "=r"(done) : "r"(mbar), "r"(parity) : "memory");
    if (!done) {
        asm volatile("{\n\t.reg .pred P1;\n\t"
                     "WL_%=:\n\t"
                     "mbarrier.try_wait.parity.acquire.cta.shared::cta.b64 P1, [%0], %1, 0x989680;\n\t"
                     "@P1 bra.uni WD_%=;\n\t"
                     "bra.uni WL_%=;\n\t"
                     "WD_%=:\n\t}"
                     :: "r"(mbar), "r"(parity) : "memory");
    }
}
__device__ __forceinline__ void tma2d(uint32_t smem, const CUtensorMap* tm, int x, int y, uint32_t mbar) {
    asm volatile("cp.async.bulk.tensor.2d.shared::cta.global.tile.mbarrier::complete_tx::bytes "
                 "[%0], [%1, {%2, %3}], [%4];"
                 :: "r"(smem), "l"(tm), "r"(x), "r"(y), "r"(mbar) : "memory");
}
__device__ __forceinline__ uint32_t sw128(uint32_t off) { return off ^ ((off >> 3) & 0x70); }

// -------- merged prep: lambda tables + W1 + Wo + x convert (one launch) --------
__global__ void prep_all_kernel(const float* __restrict__ nu_log,
                                const float* __restrict__ theta_log,
                                const float* __restrict__ gamma_log,
                                const float* __restrict__ B_re,
                                const float* __restrict__ B_im,
                                const float* __restrict__ C_re,
                                const float* __restrict__ C_im,
                                const float* __restrict__ D,
                                const float* __restrict__ x) {
    int b = blockIdx.x, tid = threadIdx.x;
    if (b == 0 && tid < NSTATE) {   // lambda tables (fp64)
        int n = tid;
        double nu  = exp((double)nu_log[n]);
        double th  = exp((double)theta_log[n]);
        double mod = exp(-nu);
        g_lam[n] = make_float2((float)(mod * cos(th)), (float)(mod * sin(th)));
        double m16 = exp(-16.0 * nu);
        g_lam16[n] = make_float2((float)(m16 * cos(16.0 * th)), (float)(m16 * sin(16.0 * th)));
        double m128 = exp(-128.0 * nu);
        g_lam128[n] = make_double2(m128 * cos(128.0 * th), m128 * sin(128.0 * th));
    }
    if (b < 256) {        // W1: 65536 elems
        int idx = b * 256 + tid;
        int r = idx / IN_F, i = idx % IN_F;
        int s = r >> 1;
        float gam = expf(gamma_log[s]);
        float v = gam * ((r & 1) ? B_im[s * IN_F + i] : B_re[s * IN_F + i]);
        g_W1[idx] = __float2half_rn(v);
    } else if (b < 576) { // Wo: 81920 elems
        int idx = (b - 256) * 256 + tid;
        int o = idx / KOUT, k = idx % KOUT;
        float v;
        if (k < 512) {
            int s = k >> 1;
            v = (k & 1) ? -C_im[o * NSTATE + s] : C_re[o * NSTATE + s];
        } else {
            v = D[o * IN_F + (k - 512)];
        }
        g_Wo[idx] = __float2half_rn(v);
    } else {              // x convert: 4096 blocks, 8 elems/thread
        size_t i = ((size_t)(b - 576) * 256 + tid) * 8;
        float4 v0 = *(const float4*)(x + i);
        float4 v1 = *(const float4*)(x + i + 4);
        __half2 h0(__float2half_rn(v0.x), __float2half_rn(v0.y));
        __half2 h1(__float2half_rn(v0.z), __float2half_rn(v0.w));
        __half2 h2(__float2half_rn(v1.x), __float2half_rn(v1.y));
        __half2 h3(__float2half_rn(v1.z), __float2half_rn(v1.w));
        uint4 pk;
        pk.x = *(uint32_t*)&h0; pk.y = *(uint32_t*)&h1;
        pk.z = *(uint32_t*)&h2; pk.w = *(uint32_t*)&h3;
        *(uint4*)(g_x + i) = pk;
    }
}

// ================= GEMM1: A-resident, B ring, fused scan =================
#define G1_A    1024
#define G1_B    (1024 + 32768)
#define G1_SMF  (1024 + 65536)         // float2[128][32] = 32 KB
#define G1_SEGC (G1_SMF + 32768)       // float2[8][32] = 2 KB
#define G1_PSEG (G1_SEGC + 2048)       // float2[8][32] = 2 KB
#define G1_SMEM (G1_PSEG + 2048)       // 103424 -> occ 2

__global__ void __launch_bounds__(256, 2) gemm1_kernel(
    const __grid_constant__ CUtensorMap tA,
    const __grid_constant__ CUtensorMap tB)
{
    extern __shared__ char smem[];
    uint32_t sb = smem_u32(smem);
    int tid = threadIdx.x, lane = tid & 31, wid = tid >> 5;
    int wm = wid & 1, wn = wid >> 1;          // 2x4 warp grid, 64x32 tiles
    int m = blockIdx.x;
    size_t m0 = (size_t)m * 128;

    if (tid == 0) {
        MBARRIER_INIT(sb, 1);
        MBARRIER_INIT(sb + 8, 1);
        MBARRIER_INIT(sb + 16, 1);
    }
    __syncthreads();

    if (tid == 0) {
        MBARRIER_EXPECT_TX(sb, 32768);
        tma2d(sb + G1_A,         &tA, 0,  (int)m0, sb);
        tma2d(sb + G1_A + 16384, &tA, 64, (int)m0, sb);
        MBARRIER_EXPECT_TX(sb + 8, 16384);
        tma2d(sb + G1_B,         &tB, 0,  0, sb + 8);
        MBARRIER_EXPECT_TX(sb + 16, 16384);
        tma2d(sb + G1_B + 16384, &tB, 64, 0, sb + 16);
    }
    mbar_wait(sb, 0);   // A resident

    float2* smf  = (float2*)(smem + G1_SMF);
    float2* segc = (float2*)(smem + G1_SEGC);
    float2* Pseg = (float2*)(smem + G1_PSEG);

    for (int nt = 0; nt < 4; nt++) {
        float acc[4][4][4];
        #pragma unroll
        for (int a = 0; a < 4; a++)
            #pragma unroll
            for (int b2 = 0; b2 < 4; b2++)
                #pragma unroll
                for (int c = 0; c < 4; c++) acc[a][b2][c] = 0.f;

        #pragma unroll
        for (int k = 0; k < 2; k++) {
            int j = nt * 2 + k;
            int s = j & 1;
            mbar_wait(sb + 8 + 8 * s, (j >> 1) & 1);
            uint32_t stA = sb + G1_A + k * 16384;
            uint32_t stB = sb + G1_B + s * 16384;
            #pragma unroll
            for (int kk = 0; kk < 64; kk += 16) {
                uint32_t af[4][4], bf[2][4];
                int arow = wm * 64 + (lane & 15);
                int acol = kk + ((lane >> 4) << 3);
                #pragma unroll
                for (int mi = 0; mi < 4; mi++)
                    ldsm4(af[mi], stA + sw128((arow + mi * 16) * 128 + acol * 2));
                int brow = wn * 32 + ((lane >> 4) << 3) + (lane & 7);
                int bcol = kk + (((lane >> 3) & 1) << 3);
                #pragma unroll
                for (int g = 0; g < 2; g++)
                    ldsm4(bf[g], stB + sw128((brow + g * 16) * 128 + bcol * 2));
                #pragma unroll
                for (int mi = 0; mi < 4; mi++)
                    #pragma unroll
                    for (int ni = 0; ni < 4; ni++)
                        mma_f16(acc[mi][ni], af[mi], &bf[ni >> 1][(ni & 1) * 2]);
            }
            __syncthreads();
            if (tid == 0 && j + 2 < 8) {
                int jn = j + 2;
                int ntn = jn >> 1, kn = jn & 1;
                MBARRIER_EXPECT_TX(sb + 8 + 8 * s, 16384);
                tma2d(sb + G1_B + s * 16384, &tB, kn * 64, ntn * 128, sb + 8 + 8 * s);
            }
        }

        // ---- fused scan epilogue for this nt (64 states, two 32-state halves) ----
        int r0 = wm * 64 + (lane >> 2);
        int cloc0 = wn * 32 + (lane & 3) * 2;
        #pragma unroll
        for (int h = 0; h < 2; h++) {
            if ((wn >> 1) == h) {
                #pragma unroll
                for (int mi = 0; mi < 4; mi++)
                    #pragma unroll
                    for (int ni = 0; ni < 4; ni++) {
                        int rl = r0 + mi * 16;
                        int sl = ((cloc0 + ni * 8) >> 1) - h * 32;
                        smf[rl * 32 + sl]       = make_float2(acc[mi][ni][0], acc[mi][ni][1]);
                        smf[(rl + 8) * 32 + sl] = make_float2(acc[mi][ni][2], acc[mi][ni][3]);
                    }
            }
            __syncthreads();
            int sbase = nt * 64 + h * 32;
            int seg = tid >> 5, s0 = tid & 31;
            {
                float2 lam = g_lam[sbase + s0];
                float2 p = make_float2(0.f, 0.f);
                #pragma unroll 4
                for (int t = 0; t < 16; t++) {
                    int row = seg * 16 + t;
                    p = cfma(lam, p, smf[row * 32 + s0]);
                    smf[row * 32 + s0] = p;
                }
                segc[seg * 32 + s0] = p;
            }
            __syncthreads();
            if (tid < 32) {
                float2 l16 = g_lam16[sbase + s0];
                float2 e = make_float2(0.f, 0.f);
                #pragma unroll
                for (int g = 0; g < 8; g++) {
                    Pseg[g * 32 + s0] = e;
                    e = cfma(l16, e, segc[g * 32 + s0]);
                }
                g_carryT[((size_t)(m >> 6) * NSTATE + sbase + s0) * NC + (m & 63)] = e;
            }
            __syncthreads();
            {
                float2 lam = g_lam[sbase + s0];
                float2 lam2 = cmul(lam, lam);
                float2 lam4 = cmul(lam2, lam2);
                float2 e = Pseg[seg * 32 + s0];
                float2 p0 = cmul(lam, e);
                float2 p1 = cmul(lam, p0);
                float2 p2 = cmul(lam, p1);
                float2 p3 = cmul(lam, p2);
                #pragma unroll
                for (int t4 = 0; t4 < 4; t4++) {
                    int row = seg * 16 + t4 * 4;
                    float2 q0 = smf[(row + 0) * 32 + s0];
                    float2 q1 = smf[(row + 1) * 32 + s0];
                    float2 q2 = smf[(row + 2) * 32 + s0];
                    float2 q3 = smf[(row + 3) * 32 + s0];
                    __half2* ob = (__half2*)(g_Ssc + (m0 + row) * SCOLS) + sbase + s0;
                    ob[0]             = __half2(__float2half_rn(q0.x + p0.x), __float2half_rn(q0.y + p0.y));
                    ob[SCOLS / 2]     = __half2(__float2half_rn(q1.x + p1.x), __float2half_rn(q1.y + p1.y));
                    ob[SCOLS]         = __half2(__float2half_rn(q2.x + p2.x), __float2half_rn(q2.y + p2.y));
                    ob[3 * SCOLS / 2] = __half2(__float2half_rn(q3.x + p3.x), __float2half_rn(q3.y + p3.y));
                    p0 = cmul(lam4, p0); p1 = cmul(lam4, p1);
                    p2 = cmul(lam4, p2); p3 = cmul(lam4, p3);
                }
            }
            __syncthreads();
        }
    }
}

// ============ GEMM2: persistent, TMA + fused fixup ============
#define STAGE_SZ 32768
#define GSMEM    (1024 + 3 * STAGE_SZ)    // 99328 -> 2 blocks/SM
#define BOFF2    16384
#define G2_GRID  296
#define G2_TILES 512
#define NK2      10
#define NK02     8

__global__ void __launch_bounds__(256, 2) gemm2_kernel(
    const __grid_constant__ CUtensorMap tA0,
    const __grid_constant__ CUtensorMap tA1,
    const __grid_constant__ CUtensorMap tB,
    float* __restrict__ out)
{
    extern __shared__ char smem[];
    uint32_t sb = smem_u32(smem);
    int tid = threadIdx.x, lane = tid & 31, wid = tid >> 5;
    int wm = wid & 1, wn = wid >> 1;
    int bid = blockIdx.x;
    uint32_t aOff = sb + 1024;

    int ntile = (G2_TILES - bid + G2_GRID - 1) / G2_GRID;   // tiles for this block
    int total = ntile * NK2;

    if (tid == 0) {
        for (int s = 0; s < 3; s++) MBARRIER_INIT(sb + 8 * s, 1);
    }
    __syncthreads();

    auto issue = [&](int g) {
        int t = g / NK2, i = g % NK2;
        int m = bid + t * G2_GRID;
        int s = g % 3;
        uint32_t bar = sb + 8 * s;
        uint32_t stg = aOff + s * STAGE_SZ;
        MBARRIER_EXPECT_TX(bar, STAGE_SZ);
        const CUtensorMap* ta = (i < NK02) ? &tA0 : &tA1;
        int kx = (i < NK02) ? i * 64 : (i - NK02) * 64;
        tma2d(stg, ta, kx, m * 128, bar);
        tma2d(stg + BOFF2, &tB, i * 64, 0, bar);
    };

    if (tid == 0) {
        int np = total < 3 ? total : 3;
        for (int g = 0; g < np; g++) issue(g);
    }

    float acc[4][4][4];
    for (int g = 0; g < total; g++) {
        int t = g / NK2, i = g % NK2;
        int m = bid + t * G2_GRID;
        size_t m0 = (size_t)m * 128;
        int fb = m >> 6, fch = m & 63;

        if (i == 0) {
            #pragma unroll
            for (int a = 0; a < 4; a++)
                #pragma unroll
                for (int b2 = 0; b2 < 4; b2++)
                    #pragma unroll
                    for (int c = 0; c < 4; c++) acc[a][b2][c] = 0.f;
        }

        int s = g % 3;
        mbar_wait(sb + 8 * s, (g / 3) & 1);

        uint32_t stA = aOff + s * STAGE_SZ;
        uint32_t stB = stA + BOFF2;

        // ---- fused fixup (state chunks) ----
        if (i < NK02 && fch > 0) {
            int sl = tid & 31;
            int rseg = tid >> 5;
            int gs = i * 32 + sl;
            float2 ci = g_carry[((size_t)fb * NC + fch - 1) * NSTATE + gs];
            float2 lam = g_lam[gs];
            float2 l16 = g_lam16[gs];
            float2 mm = cmul(lam, ci);
            for (int k = 0; k < rseg; k++) mm = cmul(l16, mm);
            float2 lam2 = cmul(lam, lam);
            float2 lam4 = cmul(lam2, lam2);
            float2 p0 = mm;
            float2 p1 = cmul(lam, p0);
            float2 p2 = cmul(lam, p1);
            float2 p3 = cmul(lam, p2);
            char* base = smem + (stA - sb);
            int rr0 = rseg * 16;
            #pragma unroll
            for (int t4 = 0; t4 < 4; t4++) {
                int row = rr0 + t4 * 4;
                __half2* ph0 = (__half2*)(base + sw128((uint32_t)(row + 0) * 128 + sl * 4));
                __half2* ph1 = (__half2*)(base + sw128((uint32_t)(row + 1) * 128 + sl * 4));
                __half2* ph2 = (__half2*)(base + sw128((uint32_t)(row + 2) * 128 + sl * 4));
                __half2* ph3 = (__half2*)(base + sw128((uint32_t)(row + 3) * 128 + sl * 4));
                __half2 h0 = *ph0, h1 = *ph1, h2 = *ph2, h3 = *ph3;
                *ph0 = __half2(__float2half_rn(__half2float(h0.x) + p0.x), __float2half_rn(__half2float(h0.y) + p0.y));
                *ph1 = __half2(__float2half_rn(__half2float(h1.x) + p1.x), __float2half_rn(__half2float(h1.y) + p1.y));
                *ph2 = __half2(__float2half_rn(__half2float(h2.x) + p2.x), __float2half_rn(__half2float(h2.y) + p2.y));
                *ph3 = __half2(__float2half_rn(__half2float(h3.x) + p3.x), __float2half_rn(__half2float(h3.y) + p3.y));
                p0 = cmul(lam4, p0); p1 = cmul(lam4, p1);
                p2 = cmul(lam4, p2); p3 = cmul(lam4, p3);
            }
            __syncthreads();
        }

        #pragma unroll
        for (int kk = 0; kk < 64; kk += 16) {
            uint32_t af[4][4], bf[2][4];
            int arow = wm * 64 + (lane & 15);
            int acol = kk + ((lane >> 4) << 3);
            #pragma unroll
            for (int mi = 0; mi < 4; mi++)
                ldsm4(af[mi], stA + sw128((arow + mi * 16) * 128 + acol * 2));
            int brow = wn * 32 + ((lane >> 4) << 3) + (lane & 7);
            int bcol = kk + (((lane >> 3) & 1) << 3);
            #pragma unroll
            for (int g2 = 0; g2 < 2; g2++)
                ldsm4(bf[g2], stB + sw128((brow + g2 * 16) * 128 + bcol * 2));
            #pragma unroll
            for (int mi = 0; mi < 4; mi++)
                #pragma unroll
                for (int ni = 0; ni < 4; ni++)
                    mma_f16(acc[mi][ni], af[mi], &bf[ni >> 1][(ni & 1) * 2]);
        }
        __syncthreads();
        if (tid == 0 && g + 3 < total) issue(g + 3);

        if (i == NK2 - 1) {
            // ---- epilogue for tile m ----
            int r0 = wm * 64 + (lane >> 2);
            int cloc0 = wn * 32 + (lane & 3) * 2;
            #pragma unroll
            for (int mi = 0; mi < 4; mi++)
                #pragma unroll
                for (int ni = 0; ni < 4; ni++) {
                    int rl = r0 + mi * 16, cl = cloc0 + ni * 8;
                    *(float2*)(out + (m0 + rl) * (size_t)OUT_F + cl) =
                        make_float2(acc[mi][ni][0], acc[mi][ni][1]);
                    *(float2*)(out + (m0 + rl + 8) * (size_t)OUT_F + cl) =
                        make_float2(acc[mi][ni][2], acc[mi][ni][3]);
                }
        }
    }
}

// ------ cross-chunk combine: warp Kogge-Stone, coalesced loads (fp64) ------
__global__ void combine_ks_kernel() {
    int w = blockIdx.x * 8 + (threadIdx.x >> 5);   // 0..2047
    int t = threadIdx.x & 31;
    int b = w >> 8, n = w & 255;
    const float2* src = g_carryT + (size_t)w * NC;
    double2 lam = g_lam128[n];

    float2 c0 = src[2 * t];
    float2 c1 = src[2 * t + 1];

    double sr = lam.x * (double)c0.x - lam.y * (double)c0.y + (double)c1.x;
    double si = lam.x * (double)c0.y + lam.y * (double)c0.x + (double)c1.y;

    double ar = lam.x * lam.x - lam.y * lam.y;
    double ai = 2.0 * lam.x * lam.y;
    #pragma unroll
    for (int k = 1; k < 32; k <<= 1) {
        double ur = __shfl_up_sync(0xFFFFFFFF, sr, k);
        double ui = __shfl_up_sync(0xFFFFFFFF, si, k);
        if (t >= k) {
            sr = ar * ur - ai * ui + sr;
            si = ar * ui + ai * ur + si;
        }
        double nar = ar * ar - ai * ai;
        ai = 2.0 * ar * ai;
        ar = nar;
    }
    double er = __shfl_up_sync(0xFFFFFFFF, sr, 1);
    double ei = __shfl_up_sync(0xFFFFFFFF, si, 1);
    double q0r = (double)c0.x, q0i = (double)c0.y;
    if (t > 0) {
        q0r += lam.x * er - lam.y * ei;
        q0i += lam.x * ei + lam.y * er;
    }
    size_t dbase = ((size_t)b * NC) * NSTATE + n;
    g_carry[dbase + (size_t)(2 * t) * NSTATE]     = make_float2((float)q0r, (float)q0i);
    g_carry[dbase + (size_t)(2 * t + 1) * NSTATE] = make_float2((float)sr, (float)si);
}

// ---------------- host: tensormap encode ----------------
typedef CUresult (*PFN_encodeTiled)(
    CUtensorMap*, CUtensorMapDataType, cuuint32_t, void*,
    const cuuint64_t*, const cuuint64_t*, const cuuint32_t*, const cuuint32_t*,
    CUtensorMapInterleave, CUtensorMapSwizzle, CUtensorMapL2promotion, CUtensorMapFloatOOBfill);

static void encode2d(PFN_encodeTiled enc, CUtensorMap* tm, void* ptr,
                     uint64_t cols, uint64_t rows, uint32_t box_rows) {
    cuuint64_t dims[2] = {cols, rows};
    cuuint64_t strides[1] = {cols * 2};
    cuuint32_t box[2] = {64, box_rows};
    cuuint32_t es[2] = {1, 1};
    enc(tm, CU_TENSOR_MAP_DATA_TYPE_FLOAT16, 2, ptr, dims, strides, box, es,
        CU_TENSOR_MAP_INTERLEAVE_NONE, CU_TENSOR_MAP_SWIZZLE_128B,
        CU_TENSOR_MAP_L2_PROMOTION_L2_128B, CU_TENSOR_MAP_FLOAT_OOB_FILL_NONE);
}

// ---------------- launch ----------------
extern "C" void kernel_launch(void* const* d_in, const int* in_sizes, int n_in,
                              void* d_out, int out_size) {
    const float* x         = (const float*)d_in[0];
    const float* nu_log    = (const float*)d_in[1];
    const float* theta_log = (const float*)d_in[2];
    const float* gamma_log = (const float*)d_in[3];
    const float* B_re      = (const float*)d_in[4];
    const float* B_im      = (const float*)d_in[5];
    const float* C_re      = (const float*)d_in[6];
    const float* C_im      = (const float*)d_in[7];
    const float* D         = (const float*)d_in[8];
    float* out = (float*)d_out;

    __half *xp, *sp, *w1, *wo;
    cudaGetSymbolAddress((void**)&xp, g_x);
    cudaGetSymbolAddress((void**)&sp, g_Ssc);
    cudaGetSymbolAddress((void**)&w1, g_W1);
    cudaGetSymbolAddress((void**)&wo, g_Wo);

    static PFN_encodeTiled enc = nullptr;
    if (!enc) {
        void* fn = nullptr;
        cudaDriverEntryPointQueryResult qr;
        cudaGetDriverEntryPointByVersion("cuTensorMapEncodeTiled", &fn, 12000,
                                         cudaEnableDefault, &qr);
        enc = (PFN_encodeTiled)fn;
    }
    CUtensorMap tmX, tmW1, tmS, tmWo;
    encode2d(enc, &tmX,  xp, IN_F, MROWS, 128);
    encode2d(enc, &tmW1, w1, IN_F, SCOLS, 128);
    encode2d(enc, &tmS,  sp, SCOLS, MROWS, 128);
    encode2d(enc, &tmWo, wo, KOUT, OUT_F, 128);

    cudaFuncSetAttribute(gemm1_kernel, cudaFuncAttributeMaxDynamicSharedMemorySize, G1_SMEM);
    cudaFuncSetAttribute(gemm2_kernel, cudaFuncAttributeMaxDynamicSharedMemorySize, GSMEM);

    // merged prep + x convert (576 prep blocks + 4096 convert blocks)
    prep_all_kernel<<<576 + 4096, 256>>>(nu_log, theta_log, gamma_log,
                                         B_re, B_im, C_re, C_im, D, x);

    // GEMM1 (A-resident) + fused tile-local scan: grid 512
    gemm1_kernel<<<MROWS / 128, 256, G1_SMEM>>>(tmX, tmW1);

    // cross-chunk combine: warp-parallel Kogge-Stone, coalesced
    combine_ks_kernel<<<256, 256>>>();

    // GEMM2 persistent + fused fixup: grid 296, 512 tiles, 3-stage ring
    gemm2_kernel<<<G2_GRID, 256, GSMEM>>>(tmS, tmX, tmWo, out);
}